// round 8
// baseline (speedup 1.0000x reference)
#include <cuda_runtime.h>
#include <cuda_bf16.h>

typedef unsigned long long ull;
typedef unsigned int u32;

// ===================== helpers =======================
__device__ __forceinline__ u32 f2tf32(float x) {
    u32 u; asm("cvt.rna.tf32.f32 %0, %1;" : "=r"(u) : "f"(x)); return u;
}
__device__ __forceinline__ float tf32f(float x) {
    return __uint_as_float(f2tf32(x));
}
#define MMA_TF32(acc, a0, a1, a2, a3, b0, b1) \
    asm volatile( \
        "mma.sync.aligned.m16n8k8.row.col.f32.tf32.tf32.f32 " \
        "{%0,%1,%2,%3}, {%4,%5,%6,%7}, {%8,%9}, {%0,%1,%2,%3};" \
        : "+f"((acc)[0]), "+f"((acc)[1]), "+f"((acc)[2]), "+f"((acc)[3]) \
        : "r"(a0), "r"(a1), "r"(a2), "r"(a3), "r"(b0), "r"(b1))

#define MMA_BF16(acc, a, b0, b1) \
    asm volatile( \
        "mma.sync.aligned.m16n8k16.row.col.f32.bf16.bf16.f32 " \
        "{%0,%1,%2,%3}, {%4,%5,%6,%7}, {%8,%9}, {%0,%1,%2,%3};" \
        : "+f"((acc)[0]), "+f"((acc)[1]), "+f"((acc)[2]), "+f"((acc)[3]) \
        : "r"((a)[0]), "r"((a)[1]), "r"((a)[2]), "r"((a)[3]), "r"(b0), "r"(b1))

__device__ __forceinline__ void ldsm4(u32* r, u32 addr) {
    asm volatile("ldmatrix.sync.aligned.m8n8.x4.shared.b16 {%0,%1,%2,%3}, [%4];"
        : "=r"(r[0]), "=r"(r[1]), "=r"(r[2]), "=r"(r[3]) : "r"(addr));
}
__device__ __forceinline__ void cpa16(u32 dst, const void* src) {
    asm volatile("cp.async.cg.shared.global [%0], [%1], 16;" :: "r"(dst), "l"(src));
}

// ===================== problem constants ====================================
#define BB    8
#define SS    1024
#define DD    128
#define NH    8
#define HD    16
#define NTOK  8192
#define HFF   512
#define NE    4

// ===================== scratch ==============================================
__device__ float         g_qkv  [NTOK * 384];
__device__ float         g_xB   [NTOK * DD];
__device__ float         g_xS   [NTOK * DD];
__device__ float         g_oB   [NTOK * DD];
__device__ float         g_oS   [NTOK * DD];
__device__ float         g_pre1 [NTOK * DD];
__device__ float         g_h    [NTOK * DD];
__device__ __nv_bfloat16 g_hbf  [NTOK * DD];
__device__ float         g_gates[NTOK * NE];
__device__ __nv_bfloat16 g_hid  [NTOK * NE * HFF];
__device__ float         g_ypart[4 * NTOK * DD];
__device__ float         g_pre2 [NTOK * DD];
__device__ __nv_bfloat16 g_w1bf [NE * HFF * DD];
__device__ __nv_bfloat16 g_w2bf [DD * NE * HFF];
__device__ float         g_wqkvB[384 * DD];
__device__ float         g_wqkvS[384 * DD];
__device__ float         g_woB  [DD * DD];
__device__ float         g_woS  [DD * DD];
__device__ float         g_part [BB * 16 * 2 * DD];

// ============================================================================
// ONE merged prep kernel: weight transposes + x tf32-split.
//  seg0 (48):   Wqkv -> wqkvB/S (tf32 b+s, transposed)
//  seg1 (16):   Wo   -> woB/S
//  seg2 (256):  W1   -> w1bf (bf16, transposed per expert)
//  seg3 (256):  W2   -> w2bf
//  seg4 (32):   x    -> xB/xS (elementwise tf32 split)
// ============================================================================
__global__ void __launch_bounds__(256) weight_prep(
    const float* __restrict__ Wqkv, const float* __restrict__ Wo,
    const float* __restrict__ W1,   const float* __restrict__ W2,
    const float* __restrict__ x,
    float* __restrict__ wqkvB, float* __restrict__ wqkvS,
    float* __restrict__ woB,   float* __restrict__ woS,
    __nv_bfloat16* __restrict__ w1bf, __nv_bfloat16* __restrict__ w2bf,
    float* __restrict__ xB, float* __restrict__ xS)
{
    int bid = blockIdx.x;
    if (bid >= 576) {                     // x split (elementwise)
        const long base = (long)(bid - 576) * 32768;
        for (int i = threadIdx.x * 4; i < 32768; i += 1024) {
            float4 v = *(const float4*)(x + base + i);
            u32 b0 = f2tf32(v.x), b1 = f2tf32(v.y), b2 = f2tf32(v.z), b3 = f2tf32(v.w);
            *(float4*)(xB + base + i) = make_float4(
                __uint_as_float(b0), __uint_as_float(b1),
                __uint_as_float(b2), __uint_as_float(b3));
            *(float4*)(xS + base + i) = make_float4(
                tf32f(v.x - __uint_as_float(b0)), tf32f(v.y - __uint_as_float(b1)),
                tf32f(v.z - __uint_as_float(b2)), tf32f(v.w - __uint_as_float(b3)));
        }
        return;
    }

    __shared__ float t[32][33];
    const float* src; int R, C, c0, r0, mode;
    float *dB = 0, *dS = 0; __nv_bfloat16* dH = 0;

    if (bid < 48) {
        src = Wqkv; R = 128; C = 384; mode = 0;
        c0 = (bid % 12) << 5; r0 = (bid / 12) << 5;
        dB = wqkvB; dS = wqkvS;
    } else if (bid < 64) {
        bid -= 48; src = Wo; R = 128; C = 128; mode = 0;
        c0 = (bid & 3) << 5; r0 = (bid >> 2) << 5;
        dB = woB; dS = woS;
    } else if (bid < 320) {
        bid -= 64;
        const int e = bid >> 6, rem = bid & 63;
        src = W1 + (long)e * 128 * 512; R = 128; C = 512; mode = 1;
        c0 = (rem & 15) << 5; r0 = (rem >> 4) << 5;
        dH = w1bf + (long)e * 512 * 128;
    } else {
        bid -= 320; src = W2; R = 2048; C = 128; mode = 1;
        c0 = (bid & 3) << 5; r0 = (bid >> 2) << 5;
        dH = w2bf;
    }

    for (int i = threadIdx.x; i < 1024; i += 256) {
        const int r = i >> 5, c = i & 31;
        t[r][c] = src[(long)(r0 + r) * C + c0 + c];
    }
    __syncthreads();
    for (int i = threadIdx.x; i < 1024; i += 256) {
        const int c = i >> 5, r = i & 31;
        const float v = t[r][c];
        const long o = (long)(c0 + c) * R + r0 + r;
        if (mode == 0) {
            const u32 big = f2tf32(v);
            dB[o] = __uint_as_float(big);
            dS[o] = __uint_as_float(f2tf32(v - __uint_as_float(big)));
        } else {
            dH[o] = __float2bfloat16(v);
        }
    }
}

// ============================================================================
// 3xTF32 mma GEMM with cp.async double-buffered staging of pre-split operands.
// Block 128x128, K-tile 32. Ab/As: [M,lda] tf32 big/small. Bb/Bs: [N,ldb] (B^T).
// smem: 2 stages x 4 arrays x [128][36] floats = 144 KB.
// part: optional fused InstanceNorm column stats (requires gridDim.x==1).
// ============================================================================
__global__ void __launch_bounds__(256) gemm_mma3(
    const float* __restrict__ Ab, const float* __restrict__ As,
    const float* __restrict__ Bb, const float* __restrict__ Bsm,
    const float* __restrict__ bias, const float* __restrict__ resid,
    float* __restrict__ C,
    int lda, int ldb, int ldc, int Kt, int ldres, float* __restrict__ part)
{
    extern __shared__ float dynsm[];
    const u32 smu = (u32)__cvta_generic_to_shared(dynsm);

    const int tid = threadIdx.x, wid = tid >> 5, lane = tid & 31;
    const int m0 = blockIdx.y << 7, n0 = blockIdx.x << 7;
    const int wm = wid >> 1, wn = wid & 1;
    const int lr = lane >> 2, lc = lane & 3;

    const float* Abase  = Ab  + (long)m0 * lda;
    const float* Asbase = As  + (long)m0 * lda;
    const float* Bbase  = Bb  + (long)n0 * ldb;
    const float* Bsbase = Bsm + (long)n0 * ldb;

    float acc[2][8][4];
    #pragma unroll
    for (int mi = 0; mi < 2; mi++)
        #pragma unroll
        for (int ni = 0; ni < 8; ni++)
            #pragma unroll
            for (int j = 0; j < 4; j++) acc[mi][ni][j] = 0.f;

#define STAGE3(KT, S) do { \
    const int _k0 = (KT) << 5; \
    const u32 _sb = smu + (S) * 73728; \
    _Pragma("unroll") \
    for (int c = 0; c < 4; c++) { \
        const int idx = tid + (c << 8); \
        const int row = idx >> 3, ch = (idx & 7) << 2; \
        const u32 off = (u32)(row * 36 + ch) * 4; \
        cpa16(_sb + off,         Abase  + (long)row * lda + _k0 + ch); \
        cpa16(_sb + 18432 + off, Asbase + (long)row * lda + _k0 + ch); \
        cpa16(_sb + 36864 + off, Bbase  + (long)row * ldb + _k0 + ch); \
        cpa16(_sb + 55296 + off, Bsbase + (long)row * ldb + _k0 + ch); \
    } \
    asm volatile("cp.async.commit_group;" ::: "memory"); \
} while (0)

    STAGE3(0, 0);
    for (int kt = 0; kt < Kt; kt++) {
        const int s = kt & 1;
        if (kt + 1 < Kt) {
            STAGE3(kt + 1, (kt + 1) & 1);
            asm volatile("cp.async.wait_group 1;" ::: "memory");
        } else {
            asm volatile("cp.async.wait_group 0;" ::: "memory");
        }
        __syncthreads();
        float* AbP = dynsm + s * 18432;
        float* AmP = AbP + 4608;
        float* BsP = AbP + 9216;
        float* BmP = AbP + 13824;
        #pragma unroll
        for (int k8 = 0; k8 < 4; k8++) {
            const int kc = (k8 << 3) + lc;
            u32 af[2][4], am[2][4];
            #pragma unroll
            for (int mi = 0; mi < 2; mi++) {
                const int r = wm * 32 + mi * 16 + lr;
                af[mi][0] = __float_as_uint(AbP[(r    ) * 36 + kc    ]);
                af[mi][1] = __float_as_uint(AbP[(r + 8) * 36 + kc    ]);
                af[mi][2] = __float_as_uint(AbP[(r    ) * 36 + kc + 4]);
                af[mi][3] = __float_as_uint(AbP[(r + 8) * 36 + kc + 4]);
                am[mi][0] = __float_as_uint(AmP[(r    ) * 36 + kc    ]);
                am[mi][1] = __float_as_uint(AmP[(r + 8) * 36 + kc    ]);
                am[mi][2] = __float_as_uint(AmP[(r    ) * 36 + kc + 4]);
                am[mi][3] = __float_as_uint(AmP[(r + 8) * 36 + kc + 4]);
            }
            #pragma unroll
            for (int ni = 0; ni < 8; ni++) {
                const int nr = wn * 64 + ni * 8 + lr;
                u32 b0 = __float_as_uint(BsP[nr * 36 + kc    ]);
                u32 b1 = __float_as_uint(BsP[nr * 36 + kc + 4]);
                u32 s0 = __float_as_uint(BmP[nr * 36 + kc    ]);
                u32 s1 = __float_as_uint(BmP[nr * 36 + kc + 4]);
                #pragma unroll
                for (int mi = 0; mi < 2; mi++) {
                    MMA_TF32(acc[mi][ni], am[mi][0], am[mi][1], am[mi][2], am[mi][3], b0, b1);
                    MMA_TF32(acc[mi][ni], af[mi][0], af[mi][1], af[mi][2], af[mi][3], s0, s1);
                    MMA_TF32(acc[mi][ni], af[mi][0], af[mi][1], af[mi][2], af[mi][3], b0, b1);
                }
            }
        }
        __syncthreads();
    }
#undef STAGE3

    float s16[16], q16[16];
    #pragma unroll
    for (int i = 0; i < 16; i++) { s16[i] = 0.f; q16[i] = 0.f; }

    #pragma unroll
    for (int mi = 0; mi < 2; mi++) {
        const int r0 = m0 + wm * 32 + mi * 16 + lr;
        const int r1 = r0 + 8;
        #pragma unroll
        for (int ni = 0; ni < 8; ni++) {
            const int col = wn * 64 + ni * 8 + (lc << 1);
            float v0 = acc[mi][ni][0], v1 = acc[mi][ni][1];
            float v2 = acc[mi][ni][2], v3 = acc[mi][ni][3];
            if (bias) {
                float bb0 = __ldg(&bias[n0 + col]), bb1 = __ldg(&bias[n0 + col + 1]);
                v0 += bb0; v1 += bb1; v2 += bb0; v3 += bb1;
            }
            if (resid) {
                v0 += __ldg(&resid[(long)r0 * ldres + n0 + col]);
                v1 += __ldg(&resid[(long)r0 * ldres + n0 + col + 1]);
                v2 += __ldg(&resid[(long)r1 * ldres + n0 + col]);
                v3 += __ldg(&resid[(long)r1 * ldres + n0 + col + 1]);
            }
            *(float2*)&C[(long)r0 * ldc + n0 + col] = make_float2(v0, v1);
            *(float2*)&C[(long)r1 * ldc + n0 + col] = make_float2(v2, v3);
            if (part) {
                s16[ni * 2 + 0] += v0 + v2;
                s16[ni * 2 + 1] += v1 + v3;
                q16[ni * 2 + 0] += v0 * v0 + v2 * v2;
                q16[ni * 2 + 1] += v1 * v1 + v3 * v3;
            }
        }
    }

    if (part) {
        #pragma unroll
        for (int i = 0; i < 16; i++) {
            s16[i] += __shfl_xor_sync(0xffffffffu, s16[i], 4);
            s16[i] += __shfl_xor_sync(0xffffffffu, s16[i], 8);
            s16[i] += __shfl_xor_sync(0xffffffffu, s16[i], 16);
            q16[i] += __shfl_xor_sync(0xffffffffu, q16[i], 4);
            q16[i] += __shfl_xor_sync(0xffffffffu, q16[i], 8);
            q16[i] += __shfl_xor_sync(0xffffffffu, q16[i], 16);
        }
        float* ssum = dynsm;
        float* ssq  = dynsm + 512;
        __syncthreads();
        if (lr == 0) {
            #pragma unroll
            for (int i = 0; i < 16; i++) {
                const int col = wn * 64 + (i >> 1) * 8 + (lc << 1) + (i & 1);
                ssum[wm * 128 + col] = s16[i];
                ssq [wm * 128 + col] = q16[i];
            }
        }
        __syncthreads();
        if (tid < 128) {
            float S = ssum[tid] + ssum[128 + tid] + ssum[256 + tid] + ssum[384 + tid];
            float Q = ssq[tid]  + ssq[128 + tid]  + ssq[256 + tid]  + ssq[384 + tid];
            part[blockIdx.y * 256 + tid] = S;
            part[blockIdx.y * 256 + 128 + tid] = Q;
        }
    }
}

// ============================================================================
// bf16 GEMM for MoE (unchanged).
// ============================================================================
#define SKB 40

__global__ void __launch_bounds__(256) gemm_bf16(
    const __nv_bfloat16* __restrict__ A, const __nv_bfloat16* __restrict__ B,
    const float* __restrict__ bias, const float* __restrict__ gate,
    void* __restrict__ Cout,
    int lda, int ldb, int ldc, int Kt,
    long strideBz, int strideKz, long strideBiasZ, long strideCz,
    int relu, int outBf16)
{
    __shared__ __align__(16) __nv_bfloat16 sA[2][128 * SKB];
    __shared__ __align__(16) __nv_bfloat16 sB[2][128 * SKB];

    const int tid = threadIdx.x, wid = tid >> 5, lane = tid & 31;
    const int z = blockIdx.z;
    const int m0 = blockIdx.y << 7, n0 = blockIdx.x << 7;
    const int wm = wid >> 1, wn = wid & 1;
    const int lr = lane >> 2, lc = lane & 3;
    const int koff = z * strideKz;

    const __nv_bfloat16* Ag = A + (long)m0 * lda + koff;
    const __nv_bfloat16* Bg = B + (long)z * strideBz + (long)n0 * ldb + koff;

    const u32 sAu = (u32)__cvta_generic_to_shared(&sA[0][0]);
    const u32 sBu = (u32)__cvta_generic_to_shared(&sB[0][0]);
    const u32 bufB = 128 * SKB * 2;

    const int rc = tid >> 2, kc = (tid & 3) << 3;

    const int sel = lane >> 3;
    u32 aoff[2], boff[4];
    {
        const int arow = wm * 32 + (lane & 7) + ((sel & 1) << 3);
        const int ak = (sel >> 1) << 3;
        aoff[0] = ((arow     ) * SKB + ak) * 2;
        aoff[1] = ((arow + 16) * SKB + ak) * 2;
        const int brow = wn * 64 + ((sel >> 1) << 3) + (lane & 7);
        const int bk = (sel & 1) << 3;
        #pragma unroll
        for (int nb = 0; nb < 4; nb++)
            boff[nb] = ((brow + nb * 16) * SKB + bk) * 2;
    }

    float acc[2][8][4];
    #pragma unroll
    for (int mi = 0; mi < 2; mi++)
        #pragma unroll
        for (int ni = 0; ni < 8; ni++)
            #pragma unroll
            for (int j = 0; j < 4; j++) acc[mi][ni][j] = 0.f;

#define STAGE(KT, S) do { \
    const int _k0 = (KT) << 5; \
    cpa16(sAu + (S) * bufB + (rc * SKB + kc) * 2,        Ag + (long)rc * lda + _k0 + kc); \
    cpa16(sAu + (S) * bufB + ((rc + 64) * SKB + kc) * 2, Ag + (long)(rc + 64) * lda + _k0 + kc); \
    cpa16(sBu + (S) * bufB + (rc * SKB + kc) * 2,        Bg + (long)rc * ldb + _k0 + kc); \
    cpa16(sBu + (S) * bufB + ((rc + 64) * SKB + kc) * 2, Bg + (long)(rc + 64) * ldb + _k0 + kc); \
    asm volatile("cp.async.commit_group;" ::: "memory"); \
} while (0)

    STAGE(0, 0);
    for (int kt = 0; kt < Kt; kt++) {
        const int s = kt & 1;
        if (kt + 1 < Kt) {
            STAGE(kt + 1, (kt + 1) & 1);
            asm volatile("cp.async.wait_group 1;" ::: "memory");
        } else {
            asm volatile("cp.async.wait_group 0;" ::: "memory");
        }
        __syncthreads();
        const u32 ab = sAu + s * bufB, bb = sBu + s * bufB;
        #pragma unroll
        for (int k16 = 0; k16 < 2; k16++) {
            u32 a0[4], a1[4];
            ldsm4(a0, ab + aoff[0] + k16 * 32);
            ldsm4(a1, ab + aoff[1] + k16 * 32);
            #pragma unroll
            for (int nb = 0; nb < 4; nb++) {
                u32 bf[4];
                ldsm4(bf, bb + boff[nb] + k16 * 32);
                MMA_BF16(acc[0][2 * nb    ], a0, bf[0], bf[1]);
                MMA_BF16(acc[1][2 * nb    ], a1, bf[0], bf[1]);
                MMA_BF16(acc[0][2 * nb + 1], a0, bf[2], bf[3]);
                MMA_BF16(acc[1][2 * nb + 1], a1, bf[2], bf[3]);
            }
        }
        __syncthreads();
    }
#undef STAGE

    const float* biasz = bias ? (bias + (long)z * strideBiasZ + n0) : (const float*)0;
    #pragma unroll
    for (int mi = 0; mi < 2; mi++) {
        const long r0 = m0 + wm * 32 + mi * 16 + lr;
        const long r1 = r0 + 8;
        float g0 = 1.f, g1 = 1.f;
        if (gate) { g0 = __ldg(&gate[r0 * NE + z]); g1 = __ldg(&gate[r1 * NE + z]); }
        #pragma unroll
        for (int ni = 0; ni < 8; ni++) {
            const int col = wn * 64 + ni * 8 + (lc << 1);
            float v0 = acc[mi][ni][0], v1 = acc[mi][ni][1];
            float v2 = acc[mi][ni][2], v3 = acc[mi][ni][3];
            if (biasz) {
                float bb0 = __ldg(&biasz[col]), bb1 = __ldg(&biasz[col + 1]);
                v0 += bb0; v1 += bb1; v2 += bb0; v3 += bb1;
            }
            if (relu) {
                v0 = fmaxf(v0, 0.f); v1 = fmaxf(v1, 0.f);
                v2 = fmaxf(v2, 0.f); v3 = fmaxf(v3, 0.f);
            }
            v0 *= g0; v1 *= g0; v2 *= g1; v3 *= g1;
            if (outBf16) {
                __nv_bfloat16* Cz = (__nv_bfloat16*)Cout + z * strideCz;
                *(__nv_bfloat162*)&Cz[r0 * ldc + n0 + col] = __floats2bfloat162_rn(v0, v1);
                *(__nv_bfloat162*)&Cz[r1 * ldc + n0 + col] = __floats2bfloat162_rn(v2, v3);
            } else {
                float* Cz = (float*)Cout + z * strideCz;
                *(float2*)&Cz[r0 * ldc + n0 + col] = make_float2(v0, v1);
                *(float2*)&Cz[r1 * ldc + n0 + col] = make_float2(v2, v3);
            }
        }
    }
}

// ============================================================================
// MMA flash attention; epilogue emits tf32 big/small split of o (for O-proj).
// ============================================================================
#define KSR 20
#define VSR 1044
#define PSR 132
#define SM_Q 0
#define SM_K (128 * KSR)
#define SM_V (SM_K + 1024 * KSR)
#define SM_P (SM_V + 16 * VSR)
#define ATTN_SMEM ((SM_P + 128 * PSR) * 4)

__global__ void __launch_bounds__(256) attn_mma(const float* __restrict__ qkv,
                                                float* __restrict__ oB,
                                                float* __restrict__ oS)
{
    extern __shared__ float sm[];
    const int bh = blockIdx.x, b = bh >> 3, h = bh & 7;
    const int qt = blockIdx.y;
    const int tid = threadIdx.x, wid = tid >> 5, lane = tid & 31;
    const int lr = lane >> 2, lc = lane & 3;
    const float* qkvb = qkv + (long)b * SS * 384;
    const int qoff = h * HD, koff = DD + h * HD, voff = 2 * DD + h * HD;

    for (int i = tid; i < SS * 4; i += 256) {
        const int s = i >> 2, c4 = (i & 3) << 2;
        float4 v = *(const float4*)(qkvb + (long)s * 384 + koff + c4);
        *(float4*)&sm[SM_K + s * KSR + c4] =
            make_float4(tf32f(v.x), tf32f(v.y), tf32f(v.z), tf32f(v.w));
        float4 w = *(const float4*)(qkvb + (long)s * 384 + voff + c4);
        sm[SM_V + (c4 + 0) * VSR + s] = tf32f(w.x);
        sm[SM_V + (c4 + 1) * VSR + s] = tf32f(w.y);
        sm[SM_V + (c4 + 2) * VSR + s] = tf32f(w.z);
        sm[SM_V + (c4 + 3) * VSR + s] = tf32f(w.w);
    }
    for (int i = tid; i < 128 * 4; i += 256) {
        const int s = i >> 2, c4 = (i & 3) << 2;
        float4 v = *(const float4*)(qkvb + (long)(qt * 128 + s) * 384 + qoff + c4);
        *(float4*)&sm[SM_Q + s * KSR + c4] =
            make_float4(tf32f(v.x * 0.25f), tf32f(v.y * 0.25f),
                        tf32f(v.z * 0.25f), tf32f(v.w * 0.25f));
    }
    __syncthreads();

    const int wq = wid << 4;
    u32 qf[2][4];
    #pragma unroll
    for (int k8 = 0; k8 < 2; k8++) {
        const int c = (k8 << 3) + lc;
        qf[k8][0] = __float_as_uint(sm[SM_Q + (wq + lr    ) * KSR + c    ]);
        qf[k8][1] = __float_as_uint(sm[SM_Q + (wq + lr + 8) * KSR + c    ]);
        qf[k8][2] = __float_as_uint(sm[SM_Q + (wq + lr    ) * KSR + c + 4]);
        qf[k8][3] = __float_as_uint(sm[SM_Q + (wq + lr + 8) * KSR + c + 4]);
    }

    float oacc[2][4];
    #pragma unroll
    for (int t = 0; t < 2; t++)
        #pragma unroll
        for (int j = 0; j < 4; j++) oacc[t][j] = 0.f;
    float sl0 = 0.f, sl1 = 0.f;

    float* Prow0 = &sm[SM_P + (wq + lr) * PSR];
    float* Prow1 = Prow0 + 8 * PSR;

    for (int kt = 0; kt < 8; kt++) {
        #pragma unroll
        for (int ni = 0; ni < 16; ni++) {
            const int krow = kt * 128 + ni * 8 + lr;
            const float* kp = &sm[SM_K + krow * KSR];
            u32 b00 = __float_as_uint(kp[lc]),      u01 = __float_as_uint(kp[lc + 4]);
            u32 b10 = __float_as_uint(kp[lc + 8]),  u11 = __float_as_uint(kp[lc + 12]);
            float sacc[4] = {0.f, 0.f, 0.f, 0.f};
            MMA_TF32(sacc, qf[0][0], qf[0][1], qf[0][2], qf[0][3], b00, u01);
            MMA_TF32(sacc, qf[1][0], qf[1][1], qf[1][2], qf[1][3], b10, u11);
            const float p0 = __expf(sacc[0]), p1 = __expf(sacc[1]);
            const float p2 = __expf(sacc[2]), p3 = __expf(sacc[3]);
            sl0 += p0 + p1;
            sl1 += p2 + p3;
            const int col = ni * 8 + (lc << 1);
            *(float2*)&Prow0[col] = make_float2(tf32f(p0), tf32f(p1));
            *(float2*)&Prow1[col] = make_float2(tf32f(p2), tf32f(p3));
        }
        __syncwarp();
        #pragma unroll
        for (int k8 = 0; k8 < 16; k8++) {
            const int kc2 = (k8 << 3) + lc;
            u32 a0 = __float_as_uint(Prow0[kc2]);
            u32 a1 = __float_as_uint(Prow1[kc2]);
            u32 a2 = __float_as_uint(Prow0[kc2 + 4]);
            u32 a3 = __float_as_uint(Prow1[kc2 + 4]);
            const int kg = kt * 128 + kc2;
            u32 v00 = __float_as_uint(sm[SM_V + (lr    ) * VSR + kg]);
            u32 v01 = __float_as_uint(sm[SM_V + (lr    ) * VSR + kg + 4]);
            u32 v10 = __float_as_uint(sm[SM_V + (lr + 8) * VSR + kg]);
            u32 v11 = __float_as_uint(sm[SM_V + (lr + 8) * VSR + kg + 4]);
            MMA_TF32(oacc[0], a0, a1, a2, a3, v00, v01);
            MMA_TF32(oacc[1], a0, a1, a2, a3, v10, v11);
        }
        __syncwarp();
    }

    sl0 += __shfl_xor_sync(0xffffffffu, sl0, 1);
    sl0 += __shfl_xor_sync(0xffffffffu, sl0, 2);
    sl1 += __shfl_xor_sync(0xffffffffu, sl1, 1);
    sl1 += __shfl_xor_sync(0xffffffffu, sl1, 2);
    const float i0 = 1.f / sl0, i1 = 1.f / sl1;

    const long r0 = (long)(b * SS + qt * 128 + wq + lr);
    const long r1 = r0 + 8;
    #pragma unroll
    for (int t = 0; t < 2; t++) {
        const int col = h * HD + t * 8 + (lc << 1);
        float w0 = oacc[t][0] * i0, w1 = oacc[t][1] * i0;
        float w2 = oacc[t][2] * i1, w3 = oacc[t][3] * i1;
        float bb0 = tf32f(w0), bb1 = tf32f(w1), bb2 = tf32f(w2), bb3 = tf32f(w3);
        *(float2*)&oB[r0 * DD + col] = make_float2(bb0, bb1);
        *(float2*)&oB[r1 * DD + col] = make_float2(bb2, bb3);
        *(float2*)&oS[r0 * DD + col] = make_float2(tf32f(w0 - bb0), tf32f(w1 - bb1));
        *(float2*)&oS[r1 * DD + col] = make_float2(tf32f(w2 - bb2), tf32f(w3 - bb3));
    }
}

// ============================================================================
// Norm-1 apply FUSED with gating + bf16 h emit (stats from O-proj epilogue).
// ============================================================================
__global__ void in_apply1(const float* __restrict__ in, const float* __restrict__ part,
                          const float* __restrict__ w, const float* __restrict__ bparm,
                          const float* __restrict__ wg,
                          float* __restrict__ hout, __nv_bfloat16* __restrict__ hbf,
                          float* __restrict__ gates)
{
    const int b = blockIdx.y, chunk = blockIdx.x;
    __shared__ float sc[DD], sf[DD], wgS[DD * NE];
    wgS[threadIdx.x] = wg[threadIdx.x];
    wgS[threadIdx.x + 256] = wg[threadIdx.x + 256];
    if (threadIdx.x < DD) {
        const int d = threadIdx.x;
        float s = 0.f, q = 0.f;
        for (int c = 0; c < 8; c++) {
            const float* p = part + (long)(b * 8 + c) * 256;
            s += p[d]; q += p[DD + d];
        }
        float mean = s * (1.f / 1024.f);
        float var  = q * (1.f / 1024.f) - mean * mean;
        float inv  = rsqrtf(var + 1e-5f);
        float scale = w[d] * inv;
        sc[d] = scale;
        sf[d] = bparm[d] - mean * scale;
    }
    __syncthreads();
    const long row0 = (long)b * SS + chunk * 64;
    const int c4 = threadIdx.x & 31, rg = threadIdx.x >> 5;
    const int c0 = c4 << 2;
    for (int r = rg; r < 64; r += 8) {
        const long tok = row0 + r;
        float4 v = *(const float4*)(in + tok * DD + c0);
        float4 o;
        o.x = v.x * sc[c0 + 0] + sf[c0 + 0];
        o.y = v.y * sc[c0 + 1] + sf[c0 + 1];
        o.z = v.z * sc[c0 + 2] + sf[c0 + 2];
        o.w = v.w * sc[c0 + 3] + sf[c0 + 3];
        *(float4*)(hout + tok * DD + c0) = o;
        __nv_bfloat162 p0 = __floats2bfloat162_rn(o.x, o.y);
        __nv_bfloat162 p1 = __floats2bfloat162_rn(o.z, o.w);
        *(uint2*)(hbf + tok * DD + c0) = make_uint2(*(u32*)&p0, *(u32*)&p1);
        float l0 = o.x * wgS[(c0 + 0) * NE + 0] + o.y * wgS[(c0 + 1) * NE + 0]
                 + o.z * wgS[(c0 + 2) * NE + 0] + o.w * wgS[(c0 + 3) * NE + 0];
        float l1 = o.x * wgS[(c0 + 0) * NE + 1] + o.y * wgS[(c0 + 1) * NE + 1]
                 + o.z * wgS[(c0 + 2) * NE + 1] + o.w * wgS[(c0 + 3) * NE + 1];
        float l2 = o.x * wgS[(c0 + 0) * NE + 2] + o.y * wgS[(c0 + 1) * NE + 2]
                 + o.z * wgS[(c0 + 2) * NE + 2] + o.w * wgS[(c0 + 3) * NE + 2];
        float l3 = o.x * wgS[(c0 + 0) * NE + 3] + o.y * wgS[(c0 + 1) * NE + 3]
                 + o.z * wgS[(c0 + 2) * NE + 3] + o.w * wgS[(c0 + 3) * NE + 3];
        #pragma unroll
        for (int off = 16; off; off >>= 1) {
            l0 += __shfl_xor_sync(0xffffffffu, l0, off);
            l1 += __shfl_xor_sync(0xffffffffu, l1, off);
            l2 += __shfl_xor_sync(0xffffffffu, l2, off);
            l3 += __shfl_xor_sync(0xffffffffu, l3, off);
        }
        if (c4 == 0) {
            float lg[4] = {l0, l1, l2, l3};
            int i1 = 0; float v1 = lg[0];
            #pragma unroll
            for (int e = 1; e < 4; e++) if (lg[e] > v1) { v1 = lg[e]; i1 = e; }
            int i2 = 0; float v2 = -3e38f;
            #pragma unroll
            for (int e = 0; e < 4; e++) if (e != i1 && lg[e] > v2) { v2 = lg[e]; i2 = e; }
            float e2  = expf(v2 - v1);
            float inv = 1.f / (1.f + e2);
            float* gp = gates + tok * NE;
            #pragma unroll
            for (int e = 0; e < 4; e++)
                gp[e] = (e == i1) ? inv : ((e == i2) ? e2 * inv : 0.f);
        }
    }
}

// ============================================================================
// Norm-2 apply
// ============================================================================
__global__ void in_apply2(const float* __restrict__ in, const float* __restrict__ part,
                          const float* __restrict__ w, const float* __restrict__ bb,
                          float* __restrict__ out)
{
    const int b = blockIdx.y, chunk = blockIdx.x;
    __shared__ float sc[DD], sf[DD];
    if (threadIdx.x < DD) {
        const int d = threadIdx.x;
        float s = 0.f, q = 0.f;
        for (int c = 0; c < 16; c++) {
            const float* p = part + (long)((b * 16 + c) * 2) * DD;
            s += p[d]; q += p[DD + d];
        }
        float mean = s * (1.f / 1024.f);
        float var  = q * (1.f / 1024.f) - mean * mean;
        float inv  = rsqrtf(var + 1e-5f);
        float scale = w[d] * inv;
        sc[d] = scale;
        sf[d] = bb[d] - mean * scale;
    }
    __syncthreads();
    const float* base = in + ((long)b * SS + chunk * 64) * DD;
    float* ob = out + ((long)b * SS + chunk * 64) * DD;
    const int c4 = threadIdx.x & 31, rg = threadIdx.x >> 5;
    for (int r = rg; r < 64; r += 8) {
        float4 v = *(const float4*)(base + (long)r * DD + (c4 << 2));
        float4 o;
        o.x = v.x * sc[(c4 << 2) + 0] + sf[(c4 << 2) + 0];
        o.y = v.y * sc[(c4 << 2) + 1] + sf[(c4 << 2) + 1];
        o.z = v.z * sc[(c4 << 2) + 2] + sf[(c4 << 2) + 2];
        o.w = v.w * sc[(c4 << 2) + 3] + sf[(c4 << 2) + 3];
        *(float4*)(ob + (long)r * DD + (c4 << 2)) = o;
    }
}

// ============================================================================
// FUSED: pre2 = sum split-K partials + h + gate.b2, plus norm-2 stats.
// ============================================================================
__global__ void add_stats(const float* __restrict__ yp, const float* __restrict__ h,
                          const float* __restrict__ gates, const float* __restrict__ b2,
                          float* __restrict__ pre2, float* __restrict__ part)
{
    const int b = blockIdx.y, chunk = blockIdx.x;
    __shared__ float b2s[NE * DD];
    b2s[threadIdx.x] = b2[threadIdx.x];
    b2s[threadIdx.x + 256] = b2[threadIdx.x + 256];
    __syncthreads();
    const long row0 = (long)b * SS + chunk * 64;
    const int c4 = threadIdx.x & 31, rg = threadIdx.x >> 5;
    const int c0 = c4 << 2;
    float4 s = make_float4(0.f, 0.f, 0.f, 0.f), q = s;
    for (int r = rg; r < 64; r += 8) {
        const long tok = row0 + r;
        const long idx = tok * DD + c0;
        const float* g = gates + tok * NE;
        const float g0 = g[0], g1 = g[1], g2 = g[2], g3 = g[3];
        float4 v = *(const float4*)(yp + idx);
        float4 v1 = *(const float4*)(yp + (long)NTOK * DD + idx);
        float4 v2 = *(const float4*)(yp + 2L * NTOK * DD + idx);
        float4 v3 = *(const float4*)(yp + 3L * NTOK * DD + idx);
        float4 hv = *(const float4*)(h + idx);
        float4 o;
        o.x = v.x + v1.x + v2.x + v3.x + hv.x
            + g0 * b2s[c0 + 0] + g1 * b2s[DD + c0 + 0] + g2 * b2s[2 * DD + c0 + 0] + g3 * b2s[3 * DD + c0 + 0];
        o.y = v.y + v1.y + v2.y + v3.y + hv.y
            + g0 * b2s[c0 + 1] + g1 * b2s[DD + c0 + 1] + g2 * b2s[2 * DD + c0 + 1] + g3 * b2s[3 * DD + c0 + 1];
        o.z = v.z + v1.z + v2.z + v3.z + hv.z
            + g0 * b2s[c0 + 2] + g1 * b2s[DD + c0 + 2] + g2 * b2s[2 * DD + c0 + 2] + g3 * b2s[3 * DD + c0 + 2];
        o.w = v.w + v1.w + v2.w + v3.w + hv.w
            + g0 * b2s[c0 + 3] + g1 * b2s[DD + c0 + 3] + g2 * b2s[2 * DD + c0 + 3] + g3 * b2s[3 * DD + c0 + 3];
        *(float4*)(pre2 + idx) = o;
        s.x += o.x; s.y += o.y; s.z += o.z; s.w += o.w;
        q.x += o.x * o.x; q.y += o.y * o.y; q.z += o.z * o.z; q.w += o.w * o.w;
    }
    __shared__ float4 sS[8][32], sQ[8][32];
    sS[rg][c4] = s; sQ[rg][c4] = q;
    __syncthreads();
    if (threadIdx.x < 32) {
        float4 ts = make_float4(0.f, 0.f, 0.f, 0.f), tq = ts;
        #pragma unroll
        for (int i = 0; i < 8; i++) {
            float4 a = sS[i][threadIdx.x], bq = sQ[i][threadIdx.x];
            ts.x += a.x; ts.y += a.y; ts.z += a.z; ts.w += a.w;
            tq.x += bq.x; tq.y += bq.y; tq.z += bq.z; tq.w += bq.w;
        }
        float* p = part + (long)((b * 16 + chunk) * 2) * DD;
        *(float4*)(p + (threadIdx.x << 2)) = ts;
        *(float4*)(p + DD + (threadIdx.x << 2)) = tq;
    }
}

// ============================================================================
// Launch (9 kernels)
// ============================================================================
extern "C" void kernel_launch(void* const* d_in, const int* in_sizes, int n_in,
                              void* d_out, int out_size)
{
    const float* x     = (const float*)d_in[0];
    const float* Wqkv  = (const float*)d_in[1];
    const float* bqkv  = (const float*)d_in[2];
    const float* Wo    = (const float*)d_in[3];
    const float* bo    = (const float*)d_in[4];
    const float* n1w   = (const float*)d_in[5];
    const float* n1b   = (const float*)d_in[6];
    const float* n2w   = (const float*)d_in[7];
    const float* n2b   = (const float*)d_in[8];
    const float* wg    = (const float*)d_in[9];
    const float* W1    = (const float*)d_in[10];
    const float* b1    = (const float*)d_in[11];
    const float* W2    = (const float*)d_in[12];
    const float* b2    = (const float*)d_in[13];

    float *qkv, *xB, *xS, *oB, *oS, *pre1, *h, *gates, *ypart, *pre2;
    float *wqkvB, *wqkvS, *woB, *woS, *part;
    __nv_bfloat16 *hbf, *hid, *w1bf, *w2bf;
    cudaGetSymbolAddress((void**)&qkv,   g_qkv);
    cudaGetSymbolAddress((void**)&xB,    g_xB);
    cudaGetSymbolAddress((void**)&xS,    g_xS);
    cudaGetSymbolAddress((void**)&oB,    g_oB);
    cudaGetSymbolAddress((void**)&oS,    g_oS);
    cudaGetSymbolAddress((void**)&pre1,  g_pre1);
    cudaGetSymbolAddress((void**)&h,     g_h);
    cudaGetSymbolAddress((void**)&hbf,   g_hbf);
    cudaGetSymbolAddress((void**)&gates, g_gates);
    cudaGetSymbolAddress((void**)&hid,   g_hid);
    cudaGetSymbolAddress((void**)&ypart, g_ypart);
    cudaGetSymbolAddress((void**)&pre2,  g_pre2);
    cudaGetSymbolAddress((void**)&w1bf,  g_w1bf);
    cudaGetSymbolAddress((void**)&w2bf,  g_w2bf);
    cudaGetSymbolAddress((void**)&wqkvB, g_wqkvB);
    cudaGetSymbolAddress((void**)&wqkvS, g_wqkvS);
    cudaGetSymbolAddress((void**)&woB,   g_woB);
    cudaGetSymbolAddress((void**)&woS,   g_woS);
    cudaGetSymbolAddress((void**)&part,  g_part);

    cudaFuncSetAttribute(attn_mma, cudaFuncAttributeMaxDynamicSharedMemorySize, ATTN_SMEM);
    cudaFuncSetAttribute(gemm_mma3, cudaFuncAttributeMaxDynamicSharedMemorySize, 147456);

    // 0. Merged prep: weight transposes + x tf32-split
    weight_prep<<<608, 256>>>(Wqkv, Wo, W1, W2, x,
                              wqkvB, wqkvS, woB, woS, w1bf, w2bf, xB, xS);

    // 1. QKV projection (3xTF32, cp.async pipelined)
    gemm_mma3<<<dim3(3, 64), 256, 147456>>>(xB, xS, wqkvB, wqkvS, bqkv, nullptr, qkv,
                                            128, 128, 384, 4, 0, nullptr);

    // 2. MMA flash attention (emits oB/oS tf32 split)
    attn_mma<<<dim3(64, 8), 256, ATTN_SMEM>>>(qkv, oB, oS);

    // 3. O-projection + bo + residual x ⊕ norm-1 stats (cp.async pipelined)
    gemm_mma3<<<dim3(1, 64), 256, 147456>>>(oB, oS, woB, woS, bo, x, pre1,
                                            128, 128, 128, 4, 128, part);

    // 4. Norm-1 apply ⊕ gating ⊕ bf16-h
    in_apply1<<<dim3(16, 8), 256>>>(pre1, part, n1w, n1b, wg, h, hbf, gates);

    // 5. MoE layer 1 (bf16)
    gemm_bf16<<<dim3(4, 64, 4), 256>>>(hbf, w1bf, b1, gates, hid,
                                       128, 128, 2048, 4,
                                       (long)HFF * DD, 0, HFF, HFF, 1, 1);

    // 6. MoE layer 2 (bf16, split-K by 4)
    gemm_bf16<<<dim3(1, 64, 4), 256>>>(hid, w2bf, nullptr, nullptr, ypart,
                                       2048, 2048, 128, 16,
                                       0, HFF, 0, (long)NTOK * DD, 0, 0);

    // 7. pre2 = Σ ypart + h + gate·b2 ⊕ norm-2 stats
    add_stats<<<dim3(16, 8), 256>>>(ypart, h, gates, b2, pre2, part);

    // 8. Norm-2 apply -> output
    in_apply2<<<dim3(16, 8), 256>>>(pre2, part, n2w, n2b, (float*)d_out);
}

// round 9
// speedup vs baseline: 1.0942x; 1.0942x over previous
#include <cuda_runtime.h>
#include <cuda_bf16.h>

typedef unsigned long long ull;
typedef unsigned int u32;

// ===================== helpers =======================
__device__ __forceinline__ u32 f2tf32(float x) {
    u32 u; asm("cvt.rna.tf32.f32 %0, %1;" : "=r"(u) : "f"(x)); return u;
}
__device__ __forceinline__ float tf32f(float x) {
    return __uint_as_float(f2tf32(x));
}
#define MMA_TF32(acc, a0, a1, a2, a3, b0, b1) \
    asm volatile( \
        "mma.sync.aligned.m16n8k8.row.col.f32.tf32.tf32.f32 " \
        "{%0,%1,%2,%3}, {%4,%5,%6,%7}, {%8,%9}, {%0,%1,%2,%3};" \
        : "+f"((acc)[0]), "+f"((acc)[1]), "+f"((acc)[2]), "+f"((acc)[3]) \
        : "r"(a0), "r"(a1), "r"(a2), "r"(a3), "r"(b0), "r"(b1))

#define MMA_BF16(acc, a, b0, b1) \
    asm volatile( \
        "mma.sync.aligned.m16n8k16.row.col.f32.bf16.bf16.f32 " \
        "{%0,%1,%2,%3}, {%4,%5,%6,%7}, {%8,%9}, {%0,%1,%2,%3};" \
        : "+f"((acc)[0]), "+f"((acc)[1]), "+f"((acc)[2]), "+f"((acc)[3]) \
        : "r"((a)[0]), "r"((a)[1]), "r"((a)[2]), "r"((a)[3]), "r"(b0), "r"(b1))

__device__ __forceinline__ void ldsm4(u32* r, u32 addr) {
    asm volatile("ldmatrix.sync.aligned.m8n8.x4.shared.b16 {%0,%1,%2,%3}, [%4];"
        : "=r"(r[0]), "=r"(r[1]), "=r"(r[2]), "=r"(r[3]) : "r"(addr));
}
__device__ __forceinline__ void cpa16(u32 dst, const void* src) {
    asm volatile("cp.async.cg.shared.global [%0], [%1], 16;" :: "r"(dst), "l"(src));
}

// ===================== problem constants ====================================
#define BB    8
#define SS    1024
#define DD    128
#define NH    8
#define HD    16
#define NTOK  8192
#define HFF   512
#define NE    4

// ===================== scratch ==============================================
__device__ float         g_qkv  [NTOK * 384];
__device__ float         g_xB   [NTOK * DD];
__device__ float         g_xS   [NTOK * DD];
__device__ float         g_oB   [NTOK * DD];
__device__ float         g_oS   [NTOK * DD];
__device__ float         g_pre1 [NTOK * DD];
__device__ float         g_h    [NTOK * DD];
__device__ __nv_bfloat16 g_hbf  [NTOK * DD];
__device__ float         g_gates[NTOK * NE];
__device__ float         g_y    [NTOK * DD];
__device__ float         g_pre2 [NTOK * DD];
__device__ __nv_bfloat16 g_w1bf [NE * HFF * DD];
__device__ __nv_bfloat16 g_w2bf [DD * NE * HFF];
__device__ float         g_wqkvB[384 * DD];
__device__ float         g_wqkvS[384 * DD];
__device__ float         g_woB  [DD * DD];
__device__ float         g_woS  [DD * DD];
__device__ float         g_part [128 * 256];

// ============================================================================
// Merged prep: weight transposes + x tf32-split (unchanged from round 8).
// ============================================================================
__global__ void __launch_bounds__(256) weight_prep(
    const float* __restrict__ Wqkv, const float* __restrict__ Wo,
    const float* __restrict__ W1,   const float* __restrict__ W2,
    const float* __restrict__ x,
    float* __restrict__ wqkvB, float* __restrict__ wqkvS,
    float* __restrict__ woB,   float* __restrict__ woS,
    __nv_bfloat16* __restrict__ w1bf, __nv_bfloat16* __restrict__ w2bf,
    float* __restrict__ xB, float* __restrict__ xS)
{
    int bid = blockIdx.x;
    if (bid >= 576) {
        const long base = (long)(bid - 576) * 32768;
        for (int i = threadIdx.x * 4; i < 32768; i += 1024) {
            float4 v = *(const float4*)(x + base + i);
            u32 b0 = f2tf32(v.x), b1 = f2tf32(v.y), b2 = f2tf32(v.z), b3 = f2tf32(v.w);
            *(float4*)(xB + base + i) = make_float4(
                __uint_as_float(b0), __uint_as_float(b1),
                __uint_as_float(b2), __uint_as_float(b3));
            *(float4*)(xS + base + i) = make_float4(
                tf32f(v.x - __uint_as_float(b0)), tf32f(v.y - __uint_as_float(b1)),
                tf32f(v.z - __uint_as_float(b2)), tf32f(v.w - __uint_as_float(b3)));
        }
        return;
    }

    __shared__ float t[32][33];
    const float* src; int R, C, c0, r0, mode;
    float *dB = 0, *dS = 0; __nv_bfloat16* dH = 0;

    if (bid < 48) {
        src = Wqkv; R = 128; C = 384; mode = 0;
        c0 = (bid % 12) << 5; r0 = (bid / 12) << 5;
        dB = wqkvB; dS = wqkvS;
    } else if (bid < 64) {
        bid -= 48; src = Wo; R = 128; C = 128; mode = 0;
        c0 = (bid & 3) << 5; r0 = (bid >> 2) << 5;
        dB = woB; dS = woS;
    } else if (bid < 320) {
        bid -= 64;
        const int e = bid >> 6, rem = bid & 63;
        src = W1 + (long)e * 128 * 512; R = 128; C = 512; mode = 1;
        c0 = (rem & 15) << 5; r0 = (rem >> 4) << 5;
        dH = w1bf + (long)e * 512 * 128;
    } else {
        bid -= 320; src = W2; R = 2048; C = 128; mode = 1;
        c0 = (bid & 3) << 5; r0 = (bid >> 2) << 5;
        dH = w2bf;
    }

    for (int i = threadIdx.x; i < 1024; i += 256) {
        const int r = i >> 5, c = i & 31;
        t[r][c] = src[(long)(r0 + r) * C + c0 + c];
    }
    __syncthreads();
    for (int i = threadIdx.x; i < 1024; i += 256) {
        const int c = i >> 5, r = i & 31;
        const float v = t[r][c];
        const long o = (long)(c0 + c) * R + r0 + r;
        if (mode == 0) {
            const u32 big = f2tf32(v);
            dB[o] = __uint_as_float(big);
            dS[o] = __uint_as_float(f2tf32(v - __uint_as_float(big)));
        } else {
            dH[o] = __float2bfloat16(v);
        }
    }
}

// ============================================================================
// 3xTF32 mma GEMM, BM=64 x BN=128, cp.async 2-stage. 8 warps (2m x 4n),
// warp tile 32x32. smem: 2 stages x 55296 B = 110592 B.
// part: optional fused column stats (gridDim.x==1); block owns 64 tokens.
// ============================================================================
__global__ void __launch_bounds__(256) gemm_mma3(
    const float* __restrict__ Ab, const float* __restrict__ As,
    const float* __restrict__ Bb, const float* __restrict__ Bsm,
    const float* __restrict__ bias, const float* __restrict__ resid,
    float* __restrict__ C,
    int lda, int ldb, int ldc, int Kt, int ldres, float* __restrict__ part)
{
    extern __shared__ float dynsm[];
    const u32 smu = (u32)__cvta_generic_to_shared(dynsm);

    const int tid = threadIdx.x, wid = tid >> 5, lane = tid & 31;
    const int m0 = blockIdx.y << 6, n0 = blockIdx.x << 7;
    const int wm = wid >> 2, wn = wid & 3;
    const int lr = lane >> 2, lc = lane & 3;

    const float* Abase  = Ab  + (long)m0 * lda;
    const float* Asbase = As  + (long)m0 * lda;
    const float* Bbase  = Bb  + (long)n0 * ldb;
    const float* Bsbase = Bsm + (long)n0 * ldb;

    float acc[2][4][4];
    #pragma unroll
    for (int mi = 0; mi < 2; mi++)
        #pragma unroll
        for (int ni = 0; ni < 4; ni++)
            #pragma unroll
            for (int j = 0; j < 4; j++) acc[mi][ni][j] = 0.f;

#define STAGE3(KT, S) do { \
    const int _k0 = (KT) << 5; \
    const u32 _sb = smu + (S) * 55296; \
    _Pragma("unroll") \
    for (int c = 0; c < 2; c++) { \
        const int idx = tid + (c << 8); \
        const int row = idx >> 3, ch = (idx & 7) << 2; \
        const u32 off = (u32)(row * 36 + ch) * 4; \
        cpa16(_sb + off,        Abase  + (long)row * lda + _k0 + ch); \
        cpa16(_sb + 9216 + off, Asbase + (long)row * lda + _k0 + ch); \
    } \
    _Pragma("unroll") \
    for (int c = 0; c < 4; c++) { \
        const int idx = tid + (c << 8); \
        const int row = idx >> 3, ch = (idx & 7) << 2; \
        const u32 off = (u32)(row * 36 + ch) * 4; \
        cpa16(_sb + 18432 + off, Bbase  + (long)row * ldb + _k0 + ch); \
        cpa16(_sb + 36864 + off, Bsbase + (long)row * ldb + _k0 + ch); \
    } \
    asm volatile("cp.async.commit_group;" ::: "memory"); \
} while (0)

    STAGE3(0, 0);
    for (int kt = 0; kt < Kt; kt++) {
        const int s = kt & 1;
        if (kt + 1 < Kt) {
            STAGE3(kt + 1, (kt + 1) & 1);
            asm volatile("cp.async.wait_group 1;" ::: "memory");
        } else {
            asm volatile("cp.async.wait_group 0;" ::: "memory");
        }
        __syncthreads();
        float* AbP = dynsm + s * 13824;
        float* AmP = AbP + 2304;
        float* BsP = AbP + 4608;
        float* BmP = AbP + 9216;
        #pragma unroll
        for (int k8 = 0; k8 < 4; k8++) {
            const int kc = (k8 << 3) + lc;
            u32 af[2][4], am[2][4];
            #pragma unroll
            for (int mi = 0; mi < 2; mi++) {
                const int r = wm * 32 + mi * 16 + lr;
                af[mi][0] = __float_as_uint(AbP[(r    ) * 36 + kc    ]);
                af[mi][1] = __float_as_uint(AbP[(r + 8) * 36 + kc    ]);
                af[mi][2] = __float_as_uint(AbP[(r    ) * 36 + kc + 4]);
                af[mi][3] = __float_as_uint(AbP[(r + 8) * 36 + kc + 4]);
                am[mi][0] = __float_as_uint(AmP[(r    ) * 36 + kc    ]);
                am[mi][1] = __float_as_uint(AmP[(r + 8) * 36 + kc    ]);
                am[mi][2] = __float_as_uint(AmP[(r    ) * 36 + kc + 4]);
                am[mi][3] = __float_as_uint(AmP[(r + 8) * 36 + kc + 4]);
            }
            #pragma unroll
            for (int ni = 0; ni < 4; ni++) {
                const int nr = wn * 32 + ni * 8 + lr;
                u32 b0 = __float_as_uint(BsP[nr * 36 + kc    ]);
                u32 b1 = __float_as_uint(BsP[nr * 36 + kc + 4]);
                u32 s0 = __float_as_uint(BmP[nr * 36 + kc    ]);
                u32 s1 = __float_as_uint(BmP[nr * 36 + kc + 4]);
                #pragma unroll
                for (int mi = 0; mi < 2; mi++) {
                    MMA_TF32(acc[mi][ni], am[mi][0], am[mi][1], am[mi][2], am[mi][3], b0, b1);
                    MMA_TF32(acc[mi][ni], af[mi][0], af[mi][1], af[mi][2], af[mi][3], s0, s1);
                    MMA_TF32(acc[mi][ni], af[mi][0], af[mi][1], af[mi][2], af[mi][3], b0, b1);
                }
            }
        }
        __syncthreads();
    }
#undef STAGE3

    float s8[8], q8[8];
    #pragma unroll
    for (int i = 0; i < 8; i++) { s8[i] = 0.f; q8[i] = 0.f; }

    #pragma unroll
    for (int mi = 0; mi < 2; mi++) {
        const int r0 = m0 + wm * 32 + mi * 16 + lr;
        const int r1 = r0 + 8;
        #pragma unroll
        for (int ni = 0; ni < 4; ni++) {
            const int col = wn * 32 + ni * 8 + (lc << 1);
            float v0 = acc[mi][ni][0], v1 = acc[mi][ni][1];
            float v2 = acc[mi][ni][2], v3 = acc[mi][ni][3];
            if (bias) {
                float bb0 = __ldg(&bias[n0 + col]), bb1 = __ldg(&bias[n0 + col + 1]);
                v0 += bb0; v1 += bb1; v2 += bb0; v3 += bb1;
            }
            if (resid) {
                v0 += __ldg(&resid[(long)r0 * ldres + n0 + col]);
                v1 += __ldg(&resid[(long)r0 * ldres + n0 + col + 1]);
                v2 += __ldg(&resid[(long)r1 * ldres + n0 + col]);
                v3 += __ldg(&resid[(long)r1 * ldres + n0 + col + 1]);
            }
            *(float2*)&C[(long)r0 * ldc + n0 + col] = make_float2(v0, v1);
            *(float2*)&C[(long)r1 * ldc + n0 + col] = make_float2(v2, v3);
            if (part) {
                s8[ni * 2 + 0] += v0 + v2;
                s8[ni * 2 + 1] += v1 + v3;
                q8[ni * 2 + 0] += v0 * v0 + v2 * v2;
                q8[ni * 2 + 1] += v1 * v1 + v3 * v3;
            }
        }
    }

    if (part) {
        #pragma unroll
        for (int i = 0; i < 8; i++) {
            s8[i] += __shfl_xor_sync(0xffffffffu, s8[i], 4);
            s8[i] += __shfl_xor_sync(0xffffffffu, s8[i], 8);
            s8[i] += __shfl_xor_sync(0xffffffffu, s8[i], 16);
            q8[i] += __shfl_xor_sync(0xffffffffu, q8[i], 4);
            q8[i] += __shfl_xor_sync(0xffffffffu, q8[i], 8);
            q8[i] += __shfl_xor_sync(0xffffffffu, q8[i], 16);
        }
        float* ssum = dynsm;
        float* ssq  = dynsm + 256;
        __syncthreads();
        if (lr == 0) {
            #pragma unroll
            for (int i = 0; i < 8; i++) {
                const int col = wn * 32 + (i >> 1) * 8 + (lc << 1) + (i & 1);
                ssum[wm * 128 + col] = s8[i];
                ssq [wm * 128 + col] = q8[i];
            }
        }
        __syncthreads();
        if (tid < 128) {
            part[blockIdx.y * 256 + tid]       = ssum[tid] + ssum[128 + tid];
            part[blockIdx.y * 256 + 128 + tid] = ssq[tid]  + ssq[128 + tid];
        }
    }
}

// ============================================================================
// FUSED MoE: y = sum_e gate[e] * (relu(h @ W1_e^T + b1_e) @ W2_e^T)
// Block = 64 tokens (grid 128). Per 64-col hid chunk: GEMM1 -> bf16 smem ->
// GEMM2 accumulate in registers. hid never touches DRAM.
// smem: A[64][136] + 2x W1[64][136] + 2x W2[128][72] + 2x H[64][72] = 107520 B
// ============================================================================
#define SA_OFF  0u
#define SW1_OFF 17408u
#define SW2_OFF 52224u
#define SH_OFF  89088u
#define MOE_SMEM 107520

__global__ void __launch_bounds__(256) moe_fused(
    const __nv_bfloat16* __restrict__ hbf, const __nv_bfloat16* __restrict__ w1bf,
    const __nv_bfloat16* __restrict__ w2bf, const float* __restrict__ b1,
    const float* __restrict__ gates, float* __restrict__ y)
{
    extern __shared__ char msm[];
    const u32 smu = (u32)__cvta_generic_to_shared(msm);

    const int tid = threadIdx.x, wid = tid >> 5, lane = tid & 31;
    const int lr = lane >> 2, lc = lane & 3, sel = lane >> 3;
    const int wm = wid >> 1, wn = wid & 1;
    const int m0 = blockIdx.x << 6;

    // ---- load A (64 tokens x 128) into smem
    #pragma unroll
    for (int j = 0; j < 4; j++) {
        const int idx = tid + (j << 8);
        const int row = idx >> 4, ch = (idx & 15) << 3;
        cpa16(smu + SA_OFF + (u32)(row * 136 + ch) * 2,
              hbf + (long)(m0 + row) * 128 + ch);
    }

#define MSTAGE(IT, S) do { \
    const int _e = (IT) >> 3, _c = (IT) & 7; \
    const __nv_bfloat16* _w1 = w1bf + (long)((_e << 9) + (_c << 6)) * 128; \
    const __nv_bfloat16* _w2 = w2bf + (_e << 9) + (_c << 6); \
    _Pragma("unroll") \
    for (int j = 0; j < 4; j++) { \
        const int idx = tid + (j << 8); \
        const int r1 = idx >> 4, ch1 = (idx & 15) << 3; \
        cpa16(smu + SW1_OFF + (S) * 17408u + (u32)(r1 * 136 + ch1) * 2, \
              _w1 + (long)r1 * 128 + ch1); \
        const int r2 = idx >> 3, ch2 = (idx & 7) << 3; \
        cpa16(smu + SW2_OFF + (S) * 18432u + (u32)(r2 * 72 + ch2) * 2, \
              _w2 + (long)r2 * 2048 + ch2); \
    } \
    asm volatile("cp.async.commit_group;" ::: "memory"); \
} while (0)

    MSTAGE(0, 0);   // group 0 also contains the A load

    // ---- ldmatrix offsets
    const u32 aoff1 = (u32)((wm * 16 + (lane & 7) + ((sel & 1) << 3)) * 136
                            + ((sel >> 1) << 3)) * 2;
    u32 boff1[2];
    #pragma unroll
    for (int nb = 0; nb < 2; nb++)
        boff1[nb] = (u32)((wn * 32 + nb * 16 + ((sel >> 1) << 3) + (lane & 7)) * 136
                          + ((sel & 1) << 3)) * 2;
    const u32 aoff2 = (u32)((wm * 16 + (lane & 7) + ((sel & 1) << 3)) * 72
                            + ((sel >> 1) << 3)) * 2;
    u32 boff2[4];
    #pragma unroll
    for (int nb = 0; nb < 4; nb++)
        boff2[nb] = (u32)((wn * 64 + nb * 16 + ((sel >> 1) << 3) + (lane & 7)) * 72
                          + ((sel & 1) << 3)) * 2;

    float acc2[8][4];
    #pragma unroll
    for (int ni = 0; ni < 8; ni++)
        #pragma unroll
        for (int j = 0; j < 4; j++) acc2[ni][j] = 0.f;

    const int row0 = wm * 16 + lr;        // local token rows
    const int gtok0 = m0 + row0, gtok1 = gtok0 + 8;

    for (int it = 0; it < 32; it++) {
        const int s = it & 1;
        const int e = it >> 3, c = it & 7;
        if (it + 1 < 32) {
            MSTAGE(it + 1, s ^ 1);
            asm volatile("cp.async.wait_group 1;" ::: "memory");
        } else {
            asm volatile("cp.async.wait_group 0;" ::: "memory");
        }
        __syncthreads();

        // ---- GEMM1: hidc[64][64] = A[64x128] @ W1chunk[64x128]^T
        const u32 w1b = smu + SW1_OFF + s * 17408u;
        const u32 ab  = smu + SA_OFF;
        float acc1[4][4];
        #pragma unroll
        for (int ni = 0; ni < 4; ni++)
            #pragma unroll
            for (int j = 0; j < 4; j++) acc1[ni][j] = 0.f;
        #pragma unroll
        for (int k16 = 0; k16 < 8; k16++) {
            u32 a[4];
            ldsm4(a, ab + aoff1 + k16 * 32);
            #pragma unroll
            for (int nb = 0; nb < 2; nb++) {
                u32 bf[4];
                ldsm4(bf, w1b + boff1[nb] + k16 * 32);
                MMA_BF16(acc1[2 * nb    ], a, bf[0], bf[1]);
                MMA_BF16(acc1[2 * nb + 1], a, bf[2], bf[3]);
            }
        }
        // ---- bias + relu + gate, store bf16 to hid chunk smem
        const float g0 = __ldg(&gates[(long)gtok0 * NE + e]);
        const float g1 = __ldg(&gates[(long)gtok1 * NE + e]);
        const u32 hbse = smu + SH_OFF + s * 9216u;
        #pragma unroll
        for (int ni = 0; ni < 4; ni++) {
            const int col = wn * 32 + ni * 8 + (lc << 1);
            const float bb0 = __ldg(&b1[(e << 9) + (c << 6) + col]);
            const float bb1 = __ldg(&b1[(e << 9) + (c << 6) + col + 1]);
            float v0 = fmaxf(acc1[ni][0] + bb0, 0.f) * g0;
            float v1 = fmaxf(acc1[ni][1] + bb1, 0.f) * g0;
            float v2 = fmaxf(acc1[ni][2] + bb0, 0.f) * g1;
            float v3 = fmaxf(acc1[ni][3] + bb1, 0.f) * g1;
            __nv_bfloat162 p0 = __floats2bfloat162_rn(v0, v1);
            __nv_bfloat162 p1 = __floats2bfloat162_rn(v2, v3);
            asm volatile("st.shared.b32 [%0], %1;" ::
                "r"(hbse + (u32)(row0 * 72 + col) * 2), "r"(*(u32*)&p0));
            asm volatile("st.shared.b32 [%0], %1;" ::
                "r"(hbse + (u32)((row0 + 8) * 72 + col) * 2), "r"(*(u32*)&p1));
        }
        __syncthreads();

        // ---- GEMM2: acc2 += hidc[64x64] @ W2chunk[128x64]^T
        const u32 w2b = smu + SW2_OFF + s * 18432u;
        #pragma unroll
        for (int k16 = 0; k16 < 4; k16++) {
            u32 a[4];
            ldsm4(a, hbse + aoff2 + k16 * 32);
            #pragma unroll
            for (int nb = 0; nb < 4; nb++) {
                u32 bf[4];
                ldsm4(bf, w2b + boff2[nb] + k16 * 32);
                MMA_BF16(acc2[2 * nb    ], a, bf[0], bf[1]);
                MMA_BF16(acc2[2 * nb + 1], a, bf[2], bf[3]);
            }
        }
        __syncthreads();
    }
#undef MSTAGE

    // ---- write y (fp32)
    #pragma unroll
    for (int ni = 0; ni < 8; ni++) {
        const int col = wn * 64 + ni * 8 + (lc << 1);
        *(float2*)&y[(long)gtok0 * DD + col] = make_float2(acc2[ni][0], acc2[ni][1]);
        *(float2*)&y[(long)gtok1 * DD + col] = make_float2(acc2[ni][2], acc2[ni][3]);
    }
}

// ============================================================================
// MMA flash attention (unchanged; emits oB/oS tf32 split).
// ============================================================================
#define KSR 20
#define VSR 1044
#define PSR 132
#define SM_Q 0
#define SM_K (128 * KSR)
#define SM_V (SM_K + 1024 * KSR)
#define SM_P (SM_V + 16 * VSR)
#define ATTN_SMEM ((SM_P + 128 * PSR) * 4)

__global__ void __launch_bounds__(256) attn_mma(const float* __restrict__ qkv,
                                                float* __restrict__ oB,
                                                float* __restrict__ oS)
{
    extern __shared__ float sm[];
    const int bh = blockIdx.x, b = bh >> 3, h = bh & 7;
    const int qt = blockIdx.y;
    const int tid = threadIdx.x, wid = tid >> 5, lane = tid & 31;
    const int lr = lane >> 2, lc = lane & 3;
    const float* qkvb = qkv + (long)b * SS * 384;
    const int qoff = h * HD, koff = DD + h * HD, voff = 2 * DD + h * HD;

    for (int i = tid; i < SS * 4; i += 256) {
        const int s = i >> 2, c4 = (i & 3) << 2;
        float4 v = *(const float4*)(qkvb + (long)s * 384 + koff + c4);
        *(float4*)&sm[SM_K + s * KSR + c4] =
            make_float4(tf32f(v.x), tf32f(v.y), tf32f(v.z), tf32f(v.w));
        float4 w = *(const float4*)(qkvb + (long)s * 384 + voff + c4);
        sm[SM_V + (c4 + 0) * VSR + s] = tf32f(w.x);
        sm[SM_V + (c4 + 1) * VSR + s] = tf32f(w.y);
        sm[SM_V + (c4 + 2) * VSR + s] = tf32f(w.z);
        sm[SM_V + (c4 + 3) * VSR + s] = tf32f(w.w);
    }
    for (int i = tid; i < 128 * 4; i += 256) {
        const int s = i >> 2, c4 = (i & 3) << 2;
        float4 v = *(const float4*)(qkvb + (long)(qt * 128 + s) * 384 + qoff + c4);
        *(float4*)&sm[SM_Q + s * KSR + c4] =
            make_float4(tf32f(v.x * 0.25f), tf32f(v.y * 0.25f),
                        tf32f(v.z * 0.25f), tf32f(v.w * 0.25f));
    }
    __syncthreads();

    const int wq = wid << 4;
    u32 qf[2][4];
    #pragma unroll
    for (int k8 = 0; k8 < 2; k8++) {
        const int c = (k8 << 3) + lc;
        qf[k8][0] = __float_as_uint(sm[SM_Q + (wq + lr    ) * KSR + c    ]);
        qf[k8][1] = __float_as_uint(sm[SM_Q + (wq + lr + 8) * KSR + c    ]);
        qf[k8][2] = __float_as_uint(sm[SM_Q + (wq + lr    ) * KSR + c + 4]);
        qf[k8][3] = __float_as_uint(sm[SM_Q + (wq + lr + 8) * KSR + c + 4]);
    }

    float oacc[2][4];
    #pragma unroll
    for (int t = 0; t < 2; t++)
        #pragma unroll
        for (int j = 0; j < 4; j++) oacc[t][j] = 0.f;
    float sl0 = 0.f, sl1 = 0.f;

    float* Prow0 = &sm[SM_P + (wq + lr) * PSR];
    float* Prow1 = Prow0 + 8 * PSR;

    for (int kt = 0; kt < 8; kt++) {
        #pragma unroll
        for (int ni = 0; ni < 16; ni++) {
            const int krow = kt * 128 + ni * 8 + lr;
            const float* kp = &sm[SM_K + krow * KSR];
            u32 b00 = __float_as_uint(kp[lc]),      u01 = __float_as_uint(kp[lc + 4]);
            u32 b10 = __float_as_uint(kp[lc + 8]),  u11 = __float_as_uint(kp[lc + 12]);
            float sacc[4] = {0.f, 0.f, 0.f, 0.f};
            MMA_TF32(sacc, qf[0][0], qf[0][1], qf[0][2], qf[0][3], b00, u01);
            MMA_TF32(sacc, qf[1][0], qf[1][1], qf[1][2], qf[1][3], b10, u11);
            const float p0 = __expf(sacc[0]), p1 = __expf(sacc[1]);
            const float p2 = __expf(sacc[2]), p3 = __expf(sacc[3]);
            sl0 += p0 + p1;
            sl1 += p2 + p3;
            const int col = ni * 8 + (lc << 1);
            *(float2*)&Prow0[col] = make_float2(tf32f(p0), tf32f(p1));
            *(float2*)&Prow1[col] = make_float2(tf32f(p2), tf32f(p3));
        }
        __syncwarp();
        #pragma unroll
        for (int k8 = 0; k8 < 16; k8++) {
            const int kc2 = (k8 << 3) + lc;
            u32 a0 = __float_as_uint(Prow0[kc2]);
            u32 a1 = __float_as_uint(Prow1[kc2]);
            u32 a2 = __float_as_uint(Prow0[kc2 + 4]);
            u32 a3 = __float_as_uint(Prow1[kc2 + 4]);
            const int kg = kt * 128 + kc2;
            u32 v00 = __float_as_uint(sm[SM_V + (lr    ) * VSR + kg]);
            u32 v01 = __float_as_uint(sm[SM_V + (lr    ) * VSR + kg + 4]);
            u32 v10 = __float_as_uint(sm[SM_V + (lr + 8) * VSR + kg]);
            u32 v11 = __float_as_uint(sm[SM_V + (lr + 8) * VSR + kg + 4]);
            MMA_TF32(oacc[0], a0, a1, a2, a3, v00, v01);
            MMA_TF32(oacc[1], a0, a1, a2, a3, v10, v11);
        }
        __syncwarp();
    }

    sl0 += __shfl_xor_sync(0xffffffffu, sl0, 1);
    sl0 += __shfl_xor_sync(0xffffffffu, sl0, 2);
    sl1 += __shfl_xor_sync(0xffffffffu, sl1, 1);
    sl1 += __shfl_xor_sync(0xffffffffu, sl1, 2);
    const float i0 = 1.f / sl0, i1 = 1.f / sl1;

    const long r0 = (long)(b * SS + qt * 128 + wq + lr);
    const long r1 = r0 + 8;
    #pragma unroll
    for (int t = 0; t < 2; t++) {
        const int col = h * HD + t * 8 + (lc << 1);
        float w0 = oacc[t][0] * i0, w1 = oacc[t][1] * i0;
        float w2 = oacc[t][2] * i1, w3 = oacc[t][3] * i1;
        float bb0 = tf32f(w0), bb1 = tf32f(w1), bb2 = tf32f(w2), bb3 = tf32f(w3);
        *(float2*)&oB[r0 * DD + col] = make_float2(bb0, bb1);
        *(float2*)&oB[r1 * DD + col] = make_float2(bb2, bb3);
        *(float2*)&oS[r0 * DD + col] = make_float2(tf32f(w0 - bb0), tf32f(w1 - bb1));
        *(float2*)&oS[r1 * DD + col] = make_float2(tf32f(w2 - bb2), tf32f(w3 - bb3));
    }
}

// ============================================================================
// Norm-1 apply FUSED with gating + bf16 h emit (stats: 16 x 64-token blocks).
// ============================================================================
__global__ void in_apply1(const float* __restrict__ in, const float* __restrict__ part,
                          const float* __restrict__ w, const float* __restrict__ bparm,
                          const float* __restrict__ wg,
                          float* __restrict__ hout, __nv_bfloat16* __restrict__ hbf,
                          float* __restrict__ gates)
{
    const int b = blockIdx.y, chunk = blockIdx.x;
    __shared__ float sc[DD], sf[DD], wgS[DD * NE];
    wgS[threadIdx.x] = wg[threadIdx.x];
    wgS[threadIdx.x + 256] = wg[threadIdx.x + 256];
    if (threadIdx.x < DD) {
        const int d = threadIdx.x;
        float s = 0.f, q = 0.f;
        for (int c = 0; c < 16; c++) {
            const float* p = part + (long)(b * 16 + c) * 256;
            s += p[d]; q += p[DD + d];
        }
        float mean = s * (1.f / 1024.f);
        float var  = q * (1.f / 1024.f) - mean * mean;
        float inv  = rsqrtf(var + 1e-5f);
        float scale = w[d] * inv;
        sc[d] = scale;
        sf[d] = bparm[d] - mean * scale;
    }
    __syncthreads();
    const long row0 = (long)b * SS + chunk * 64;
    const int c4 = threadIdx.x & 31, rg = threadIdx.x >> 5;
    const int c0 = c4 << 2;
    for (int r = rg; r < 64; r += 8) {
        const long tok = row0 + r;
        float4 v = *(const float4*)(in + tok * DD + c0);
        float4 o;
        o.x = v.x * sc[c0 + 0] + sf[c0 + 0];
        o.y = v.y * sc[c0 + 1] + sf[c0 + 1];
        o.z = v.z * sc[c0 + 2] + sf[c0 + 2];
        o.w = v.w * sc[c0 + 3] + sf[c0 + 3];
        *(float4*)(hout + tok * DD + c0) = o;
        __nv_bfloat162 p0 = __floats2bfloat162_rn(o.x, o.y);
        __nv_bfloat162 p1 = __floats2bfloat162_rn(o.z, o.w);
        *(uint2*)(hbf + tok * DD + c0) = make_uint2(*(u32*)&p0, *(u32*)&p1);
        float l0 = o.x * wgS[(c0 + 0) * NE + 0] + o.y * wgS[(c0 + 1) * NE + 0]
                 + o.z * wgS[(c0 + 2) * NE + 0] + o.w * wgS[(c0 + 3) * NE + 0];
        float l1 = o.x * wgS[(c0 + 0) * NE + 1] + o.y * wgS[(c0 + 1) * NE + 1]
                 + o.z * wgS[(c0 + 2) * NE + 1] + o.w * wgS[(c0 + 3) * NE + 1];
        float l2 = o.x * wgS[(c0 + 0) * NE + 2] + o.y * wgS[(c0 + 1) * NE + 2]
                 + o.z * wgS[(c0 + 2) * NE + 2] + o.w * wgS[(c0 + 3) * NE + 2];
        float l3 = o.x * wgS[(c0 + 0) * NE + 3] + o.y * wgS[(c0 + 1) * NE + 3]
                 + o.z * wgS[(c0 + 2) * NE + 3] + o.w * wgS[(c0 + 3) * NE + 3];
        #pragma unroll
        for (int off = 16; off; off >>= 1) {
            l0 += __shfl_xor_sync(0xffffffffu, l0, off);
            l1 += __shfl_xor_sync(0xffffffffu, l1, off);
            l2 += __shfl_xor_sync(0xffffffffu, l2, off);
            l3 += __shfl_xor_sync(0xffffffffu, l3, off);
        }
        if (c4 == 0) {
            float lg[4] = {l0, l1, l2, l3};
            int i1 = 0; float v1 = lg[0];
            #pragma unroll
            for (int e = 1; e < 4; e++) if (lg[e] > v1) { v1 = lg[e]; i1 = e; }
            int i2 = 0; float v2 = -3e38f;
            #pragma unroll
            for (int e = 0; e < 4; e++) if (e != i1 && lg[e] > v2) { v2 = lg[e]; i2 = e; }
            float e2  = expf(v2 - v1);
            float inv = 1.f / (1.f + e2);
            float* gp = gates + tok * NE;
            #pragma unroll
            for (int e = 0; e < 4; e++)
                gp[e] = (e == i1) ? inv : ((e == i2) ? e2 * inv : 0.f);
        }
    }
}

// ============================================================================
// Norm-2 apply (16-chunk layout from add_stats)
// ============================================================================
__global__ void in_apply2(const float* __restrict__ in, const float* __restrict__ part,
                          const float* __restrict__ w, const float* __restrict__ bb,
                          float* __restrict__ out)
{
    const int b = blockIdx.y, chunk = blockIdx.x;
    __shared__ float sc[DD], sf[DD];
    if (threadIdx.x < DD) {
        const int d = threadIdx.x;
        float s = 0.f, q = 0.f;
        for (int c = 0; c < 16; c++) {
            const float* p = part + (long)((b * 16 + c) * 2) * DD;
            s += p[d]; q += p[DD + d];
        }
        float mean = s * (1.f / 1024.f);
        float var  = q * (1.f / 1024.f) - mean * mean;
        float inv  = rsqrtf(var + 1e-5f);
        float scale = w[d] * inv;
        sc[d] = scale;
        sf[d] = bb[d] - mean * scale;
    }
    __syncthreads();
    const float* base = in + ((long)b * SS + chunk * 64) * DD;
    float* ob = out + ((long)b * SS + chunk * 64) * DD;
    const int c4 = threadIdx.x & 31, rg = threadIdx.x >> 5;
    for (int r = rg; r < 64; r += 8) {
        float4 v = *(const float4*)(base + (long)r * DD + (c4 << 2));
        float4 o;
        o.x = v.x * sc[(c4 << 2) + 0] + sf[(c4 << 2) + 0];
        o.y = v.y * sc[(c4 << 2) + 1] + sf[(c4 << 2) + 1];
        o.z = v.z * sc[(c4 << 2) + 2] + sf[(c4 << 2) + 2];
        o.w = v.w * sc[(c4 << 2) + 3] + sf[(c4 << 2) + 3];
        *(float4*)(ob + (long)r * DD + (c4 << 2)) = o;
    }
}

// ============================================================================
// FUSED: pre2 = y + h + gate.b2, plus norm-2 stats.
// ============================================================================
__global__ void add_stats(const float* __restrict__ y, const float* __restrict__ h,
                          const float* __restrict__ gates, const float* __restrict__ b2,
                          float* __restrict__ pre2, float* __restrict__ part)
{
    const int b = blockIdx.y, chunk = blockIdx.x;
    __shared__ float b2s[NE * DD];
    b2s[threadIdx.x] = b2[threadIdx.x];
    b2s[threadIdx.x + 256] = b2[threadIdx.x + 256];
    __syncthreads();
    const long row0 = (long)b * SS + chunk * 64;
    const int c4 = threadIdx.x & 31, rg = threadIdx.x >> 5;
    const int c0 = c4 << 2;
    float4 s = make_float4(0.f, 0.f, 0.f, 0.f), q = s;
    for (int r = rg; r < 64; r += 8) {
        const long tok = row0 + r;
        const long idx = tok * DD + c0;
        const float* g = gates + tok * NE;
        const float g0 = g[0], g1 = g[1], g2 = g[2], g3 = g[3];
        float4 v = *(const float4*)(y + idx);
        float4 hv = *(const float4*)(h + idx);
        float4 o;
        o.x = v.x + hv.x
            + g0 * b2s[c0 + 0] + g1 * b2s[DD + c0 + 0] + g2 * b2s[2 * DD + c0 + 0] + g3 * b2s[3 * DD + c0 + 0];
        o.y = v.y + hv.y
            + g0 * b2s[c0 + 1] + g1 * b2s[DD + c0 + 1] + g2 * b2s[2 * DD + c0 + 1] + g3 * b2s[3 * DD + c0 + 1];
        o.z = v.z + hv.z
            + g0 * b2s[c0 + 2] + g1 * b2s[DD + c0 + 2] + g2 * b2s[2 * DD + c0 + 2] + g3 * b2s[3 * DD + c0 + 2];
        o.w = v.w + hv.w
            + g0 * b2s[c0 + 3] + g1 * b2s[DD + c0 + 3] + g2 * b2s[2 * DD + c0 + 3] + g3 * b2s[3 * DD + c0 + 3];
        *(float4*)(pre2 + idx) = o;
        s.x += o.x; s.y += o.y; s.z += o.z; s.w += o.w;
        q.x += o.x * o.x; q.y += o.y * o.y; q.z += o.z * o.z; q.w += o.w * o.w;
    }
    __shared__ float4 sS[8][32], sQ[8][32];
    sS[rg][c4] = s; sQ[rg][c4] = q;
    __syncthreads();
    if (threadIdx.x < 32) {
        float4 ts = make_float4(0.f, 0.f, 0.f, 0.f), tq = ts;
        #pragma unroll
        for (int i = 0; i < 8; i++) {
            float4 a = sS[i][threadIdx.x], bq = sQ[i][threadIdx.x];
            ts.x += a.x; ts.y += a.y; ts.z += a.z; ts.w += a.w;
            tq.x += bq.x; tq.y += bq.y; tq.z += bq.z; tq.w += bq.w;
        }
        float* p = part + (long)((b * 16 + chunk) * 2) * DD;
        *(float4*)(p + (threadIdx.x << 2)) = ts;
        *(float4*)(p + DD + (threadIdx.x << 2)) = tq;
    }
}

// ============================================================================
// Launch (8 kernels)
// ============================================================================
extern "C" void kernel_launch(void* const* d_in, const int* in_sizes, int n_in,
                              void* d_out, int out_size)
{
    const float* x     = (const float*)d_in[0];
    const float* Wqkv  = (const float*)d_in[1];
    const float* bqkv  = (const float*)d_in[2];
    const float* Wo    = (const float*)d_in[3];
    const float* bo    = (const float*)d_in[4];
    const float* n1w   = (const float*)d_in[5];
    const float* n1b   = (const float*)d_in[6];
    const float* n2w   = (const float*)d_in[7];
    const float* n2b   = (const float*)d_in[8];
    const float* wg    = (const float*)d_in[9];
    const float* W1    = (const float*)d_in[10];
    const float* b1    = (const float*)d_in[11];
    const float* W2    = (const float*)d_in[12];
    const float* b2    = (const float*)d_in[13];

    float *qkv, *xB, *xS, *oB, *oS, *pre1, *h, *gates, *y, *pre2;
    float *wqkvB, *wqkvS, *woB, *woS, *part;
    __nv_bfloat16 *hbf, *w1bf, *w2bf;
    cudaGetSymbolAddress((void**)&qkv,   g_qkv);
    cudaGetSymbolAddress((void**)&xB,    g_xB);
    cudaGetSymbolAddress((void**)&xS,    g_xS);
    cudaGetSymbolAddress((void**)&oB,    g_oB);
    cudaGetSymbolAddress((void**)&oS,    g_oS);
    cudaGetSymbolAddress((void**)&pre1,  g_pre1);
    cudaGetSymbolAddress((void**)&h,     g_h);
    cudaGetSymbolAddress((void**)&hbf,   g_hbf);
    cudaGetSymbolAddress((void**)&gates, g_gates);
    cudaGetSymbolAddress((void**)&y,     g_y);
    cudaGetSymbolAddress((void**)&pre2,  g_pre2);
    cudaGetSymbolAddress((void**)&w1bf,  g_w1bf);
    cudaGetSymbolAddress((void**)&w2bf,  g_w2bf);
    cudaGetSymbolAddress((void**)&wqkvB, g_wqkvB);
    cudaGetSymbolAddress((void**)&wqkvS, g_wqkvS);
    cudaGetSymbolAddress((void**)&woB,   g_woB);
    cudaGetSymbolAddress((void**)&woS,   g_woS);
    cudaGetSymbolAddress((void**)&part,  g_part);

    cudaFuncSetAttribute(attn_mma, cudaFuncAttributeMaxDynamicSharedMemorySize, ATTN_SMEM);
    cudaFuncSetAttribute(gemm_mma3, cudaFuncAttributeMaxDynamicSharedMemorySize, 110592);
    cudaFuncSetAttribute(moe_fused, cudaFuncAttributeMaxDynamicSharedMemorySize, MOE_SMEM);

    // 0. Merged prep
    weight_prep<<<608, 256>>>(Wqkv, Wo, W1, W2, x,
                              wqkvB, wqkvS, woB, woS, w1bf, w2bf, xB, xS);

    // 1. QKV projection (3xTF32, BM=64, 384 blocks)
    gemm_mma3<<<dim3(3, 128), 256, 110592>>>(xB, xS, wqkvB, wqkvS, bqkv, nullptr, qkv,
                                             128, 128, 384, 4, 0, nullptr);

    // 2. MMA flash attention
    attn_mma<<<dim3(64, 8), 256, ATTN_SMEM>>>(qkv, oB, oS);

    // 3. O-projection + bo + residual x ⊕ norm-1 stats (128 blocks)
    gemm_mma3<<<dim3(1, 128), 256, 110592>>>(oB, oS, woB, woS, bo, x, pre1,
                                             128, 128, 128, 4, 128, part);

    // 4. Norm-1 apply ⊕ gating ⊕ bf16-h
    in_apply1<<<dim3(16, 8), 256>>>(pre1, part, n1w, n1b, wg, h, hbf, gates);

    // 5. FUSED MoE (hid never leaves smem)
    moe_fused<<<128, 256, MOE_SMEM>>>(hbf, w1bf, w2bf, b1, gates, y);

    // 6. pre2 = y + h + gate·b2 ⊕ norm-2 stats
    add_stats<<<dim3(16, 8), 256>>>(y, h, gates, b2, pre2, part);

    // 7. Norm-2 apply -> output
    in_apply2<<<dim3(16, 8), 256>>>(pre2, part, n2w, n2b, (float*)d_out);
}

// round 10
// speedup vs baseline: 1.1261x; 1.0291x over previous
#include <cuda_runtime.h>
#include <cuda_bf16.h>

typedef unsigned long long ull;
typedef unsigned int u32;

// ===================== helpers =======================
__device__ __forceinline__ u32 f2tf32(float x) {
    u32 u; asm("cvt.rna.tf32.f32 %0, %1;" : "=r"(u) : "f"(x)); return u;
}
__device__ __forceinline__ float tf32f(float x) {
    return __uint_as_float(f2tf32(x));
}
#define MMA_TF32(acc, a0, a1, a2, a3, b0, b1) \
    asm volatile( \
        "mma.sync.aligned.m16n8k8.row.col.f32.tf32.tf32.f32 " \
        "{%0,%1,%2,%3}, {%4,%5,%6,%7}, {%8,%9}, {%0,%1,%2,%3};" \
        : "+f"((acc)[0]), "+f"((acc)[1]), "+f"((acc)[2]), "+f"((acc)[3]) \
        : "r"(a0), "r"(a1), "r"(a2), "r"(a3), "r"(b0), "r"(b1))

#define MMA_BF16(acc, a, b0, b1) \
    asm volatile( \
        "mma.sync.aligned.m16n8k16.row.col.f32.bf16.bf16.f32 " \
        "{%0,%1,%2,%3}, {%4,%5,%6,%7}, {%8,%9}, {%0,%1,%2,%3};" \
        : "+f"((acc)[0]), "+f"((acc)[1]), "+f"((acc)[2]), "+f"((acc)[3]) \
        : "r"((a)[0]), "r"((a)[1]), "r"((a)[2]), "r"((a)[3]), "r"(b0), "r"(b1))

__device__ __forceinline__ void ldsm4(u32* r, u32 addr) {
    asm volatile("ldmatrix.sync.aligned.m8n8.x4.shared.b16 {%0,%1,%2,%3}, [%4];"
        : "=r"(r[0]), "=r"(r[1]), "=r"(r[2]), "=r"(r[3]) : "r"(addr));
}
__device__ __forceinline__ void cpa16(u32 dst, const void* src) {
    asm volatile("cp.async.cg.shared.global [%0], [%1], 16;" :: "r"(dst), "l"(src));
}

// ===================== problem constants ====================================
#define BB    8
#define SS    1024
#define DD    128
#define NH    8
#define HD    16
#define NTOK  8192
#define HFF   512
#define NE    4

// ===================== scratch ==============================================
__device__ float         g_qkv  [NTOK * 384];
__device__ float         g_xB   [NTOK * DD];
__device__ float         g_xS   [NTOK * DD];
__device__ float         g_oB   [NTOK * DD];
__device__ float         g_oS   [NTOK * DD];
__device__ float         g_pre1 [NTOK * DD];
__device__ float         g_h    [NTOK * DD];
__device__ __nv_bfloat16 g_hbf  [NTOK * DD];
__device__ float         g_gates[NTOK * NE];
__device__ float         g_ypart[2 * NTOK * DD];
__device__ float         g_pre2 [NTOK * DD];
__device__ __nv_bfloat16 g_w1bf [NE * HFF * DD];
__device__ __nv_bfloat16 g_w2bf [DD * NE * HFF];
__device__ float         g_wqkvB[384 * DD];
__device__ float         g_wqkvS[384 * DD];
__device__ float         g_woB  [DD * DD];
__device__ float         g_woS  [DD * DD];
__device__ float         g_part [128 * 256];

// ============================================================================
// Merged prep: weight transposes + x tf32-split.
// ============================================================================
__global__ void __launch_bounds__(256) weight_prep(
    const float* __restrict__ Wqkv, const float* __restrict__ Wo,
    const float* __restrict__ W1,   const float* __restrict__ W2,
    const float* __restrict__ x,
    float* __restrict__ wqkvB, float* __restrict__ wqkvS,
    float* __restrict__ woB,   float* __restrict__ woS,
    __nv_bfloat16* __restrict__ w1bf, __nv_bfloat16* __restrict__ w2bf,
    float* __restrict__ xB, float* __restrict__ xS)
{
    int bid = blockIdx.x;
    if (bid >= 576) {
        const long base = (long)(bid - 576) * 32768;
        for (int i = threadIdx.x * 4; i < 32768; i += 1024) {
            float4 v = *(const float4*)(x + base + i);
            u32 b0 = f2tf32(v.x), b1 = f2tf32(v.y), b2 = f2tf32(v.z), b3 = f2tf32(v.w);
            *(float4*)(xB + base + i) = make_float4(
                __uint_as_float(b0), __uint_as_float(b1),
                __uint_as_float(b2), __uint_as_float(b3));
            *(float4*)(xS + base + i) = make_float4(
                tf32f(v.x - __uint_as_float(b0)), tf32f(v.y - __uint_as_float(b1)),
                tf32f(v.z - __uint_as_float(b2)), tf32f(v.w - __uint_as_float(b3)));
        }
        return;
    }

    __shared__ float t[32][33];
    const float* src; int R, C, c0, r0, mode;
    float *dB = 0, *dS = 0; __nv_bfloat16* dH = 0;

    if (bid < 48) {
        src = Wqkv; R = 128; C = 384; mode = 0;
        c0 = (bid % 12) << 5; r0 = (bid / 12) << 5;
        dB = wqkvB; dS = wqkvS;
    } else if (bid < 64) {
        bid -= 48; src = Wo; R = 128; C = 128; mode = 0;
        c0 = (bid & 3) << 5; r0 = (bid >> 2) << 5;
        dB = woB; dS = woS;
    } else if (bid < 320) {
        bid -= 64;
        const int e = bid >> 6, rem = bid & 63;
        src = W1 + (long)e * 128 * 512; R = 128; C = 512; mode = 1;
        c0 = (rem & 15) << 5; r0 = (rem >> 4) << 5;
        dH = w1bf + (long)e * 512 * 128;
    } else {
        bid -= 320; src = W2; R = 2048; C = 128; mode = 1;
        c0 = (bid & 3) << 5; r0 = (bid >> 2) << 5;
        dH = w2bf;
    }

    for (int i = threadIdx.x; i < 1024; i += 256) {
        const int r = i >> 5, c = i & 31;
        t[r][c] = src[(long)(r0 + r) * C + c0 + c];
    }
    __syncthreads();
    for (int i = threadIdx.x; i < 1024; i += 256) {
        const int c = i >> 5, r = i & 31;
        const float v = t[r][c];
        const long o = (long)(c0 + c) * R + r0 + r;
        if (mode == 0) {
            const u32 big = f2tf32(v);
            dB[o] = __uint_as_float(big);
            dS[o] = __uint_as_float(f2tf32(v - __uint_as_float(big)));
        } else {
            dH[o] = __float2bfloat16(v);
        }
    }
}

// ============================================================================
// 3xTF32 mma GEMM, BM=64 x BN=128, BK=16, cp.async 2-stage.
// stage = Ab[64*20] Am[64*20] Bb[128*20] Bm[128*20] floats = 30720 B.
// Total smem 61440 B -> 2 blocks/SM co-resident.
// part: optional fused column stats (gridDim.x==1); block owns 64 tokens.
// ============================================================================
__global__ void __launch_bounds__(256) gemm_mma3(
    const float* __restrict__ Ab, const float* __restrict__ As,
    const float* __restrict__ Bb, const float* __restrict__ Bsm,
    const float* __restrict__ bias, const float* __restrict__ resid,
    float* __restrict__ C,
    int lda, int ldb, int ldc, int Kt, int ldres, float* __restrict__ part)
{
    extern __shared__ float dynsm[];
    const u32 smu = (u32)__cvta_generic_to_shared(dynsm);

    const int tid = threadIdx.x, wid = tid >> 5, lane = tid & 31;
    const int m0 = blockIdx.y << 6, n0 = blockIdx.x << 7;
    const int wm = wid >> 2, wn = wid & 3;
    const int lr = lane >> 2, lc = lane & 3;

    const float* Abase  = Ab  + (long)m0 * lda;
    const float* Asbase = As  + (long)m0 * lda;
    const float* Bbase  = Bb  + (long)n0 * ldb;
    const float* Bsbase = Bsm + (long)n0 * ldb;

    float acc[2][4][4];
    #pragma unroll
    for (int mi = 0; mi < 2; mi++)
        #pragma unroll
        for (int ni = 0; ni < 4; ni++)
            #pragma unroll
            for (int j = 0; j < 4; j++) acc[mi][ni][j] = 0.f;

#define STAGE3(KT, S) do { \
    const int _k0 = (KT) << 4; \
    const u32 _sb = smu + (S) * 30720; \
    { \
        const int row = tid >> 2, ch = (tid & 3) << 2; \
        const u32 off = (u32)(row * 20 + ch) * 4; \
        cpa16(_sb + off,        Abase  + (long)row * lda + _k0 + ch); \
        cpa16(_sb + 5120 + off, Asbase + (long)row * lda + _k0 + ch); \
    } \
    _Pragma("unroll") \
    for (int c = 0; c < 2; c++) { \
        const int idx = tid + (c << 8); \
        const int row = idx >> 2, ch = (idx & 3) << 2; \
        const u32 off = (u32)(row * 20 + ch) * 4; \
        cpa16(_sb + 10240 + off, Bbase  + (long)row * ldb + _k0 + ch); \
        cpa16(_sb + 20480 + off, Bsbase + (long)row * ldb + _k0 + ch); \
    } \
    asm volatile("cp.async.commit_group;" ::: "memory"); \
} while (0)

    STAGE3(0, 0);
    for (int kt = 0; kt < Kt; kt++) {
        const int s = kt & 1;
        if (kt + 1 < Kt) {
            STAGE3(kt + 1, (kt + 1) & 1);
            asm volatile("cp.async.wait_group 1;" ::: "memory");
        } else {
            asm volatile("cp.async.wait_group 0;" ::: "memory");
        }
        __syncthreads();
        float* AbP = dynsm + s * 7680;
        float* AmP = AbP + 1280;
        float* BsP = AbP + 2560;
        float* BmP = AbP + 5120;
        #pragma unroll
        for (int k8 = 0; k8 < 2; k8++) {
            const int kc = (k8 << 3) + lc;
            u32 af[2][4], am[2][4];
            #pragma unroll
            for (int mi = 0; mi < 2; mi++) {
                const int r = wm * 32 + mi * 16 + lr;
                af[mi][0] = __float_as_uint(AbP[(r    ) * 20 + kc    ]);
                af[mi][1] = __float_as_uint(AbP[(r + 8) * 20 + kc    ]);
                af[mi][2] = __float_as_uint(AbP[(r    ) * 20 + kc + 4]);
                af[mi][3] = __float_as_uint(AbP[(r + 8) * 20 + kc + 4]);
                am[mi][0] = __float_as_uint(AmP[(r    ) * 20 + kc    ]);
                am[mi][1] = __float_as_uint(AmP[(r + 8) * 20 + kc    ]);
                am[mi][2] = __float_as_uint(AmP[(r    ) * 20 + kc + 4]);
                am[mi][3] = __float_as_uint(AmP[(r + 8) * 20 + kc + 4]);
            }
            #pragma unroll
            for (int ni = 0; ni < 4; ni++) {
                const int nr = wn * 32 + ni * 8 + lr;
                u32 b0 = __float_as_uint(BsP[nr * 20 + kc    ]);
                u32 b1 = __float_as_uint(BsP[nr * 20 + kc + 4]);
                u32 s0 = __float_as_uint(BmP[nr * 20 + kc    ]);
                u32 s1 = __float_as_uint(BmP[nr * 20 + kc + 4]);
                #pragma unroll
                for (int mi = 0; mi < 2; mi++) {
                    MMA_TF32(acc[mi][ni], am[mi][0], am[mi][1], am[mi][2], am[mi][3], b0, b1);
                    MMA_TF32(acc[mi][ni], af[mi][0], af[mi][1], af[mi][2], af[mi][3], s0, s1);
                    MMA_TF32(acc[mi][ni], af[mi][0], af[mi][1], af[mi][2], af[mi][3], b0, b1);
                }
            }
        }
        __syncthreads();
    }
#undef STAGE3

    float s8[8], q8[8];
    #pragma unroll
    for (int i = 0; i < 8; i++) { s8[i] = 0.f; q8[i] = 0.f; }

    #pragma unroll
    for (int mi = 0; mi < 2; mi++) {
        const int r0 = m0 + wm * 32 + mi * 16 + lr;
        const int r1 = r0 + 8;
        #pragma unroll
        for (int ni = 0; ni < 4; ni++) {
            const int col = wn * 32 + ni * 8 + (lc << 1);
            float v0 = acc[mi][ni][0], v1 = acc[mi][ni][1];
            float v2 = acc[mi][ni][2], v3 = acc[mi][ni][3];
            if (bias) {
                float2 bbv = *(const float2*)&bias[n0 + col];
                v0 += bbv.x; v1 += bbv.y; v2 += bbv.x; v3 += bbv.y;
            }
            if (resid) {
                float2 ra = *(const float2*)&resid[(long)r0 * ldres + n0 + col];
                float2 rb = *(const float2*)&resid[(long)r1 * ldres + n0 + col];
                v0 += ra.x; v1 += ra.y; v2 += rb.x; v3 += rb.y;
            }
            *(float2*)&C[(long)r0 * ldc + n0 + col] = make_float2(v0, v1);
            *(float2*)&C[(long)r1 * ldc + n0 + col] = make_float2(v2, v3);
            if (part) {
                s8[ni * 2 + 0] += v0 + v2;
                s8[ni * 2 + 1] += v1 + v3;
                q8[ni * 2 + 0] += v0 * v0 + v2 * v2;
                q8[ni * 2 + 1] += v1 * v1 + v3 * v3;
            }
        }
    }

    if (part) {
        #pragma unroll
        for (int i = 0; i < 8; i++) {
            s8[i] += __shfl_xor_sync(0xffffffffu, s8[i], 4);
            s8[i] += __shfl_xor_sync(0xffffffffu, s8[i], 8);
            s8[i] += __shfl_xor_sync(0xffffffffu, s8[i], 16);
            q8[i] += __shfl_xor_sync(0xffffffffu, q8[i], 4);
            q8[i] += __shfl_xor_sync(0xffffffffu, q8[i], 8);
            q8[i] += __shfl_xor_sync(0xffffffffu, q8[i], 16);
        }
        float* ssum = dynsm;
        float* ssq  = dynsm + 256;
        __syncthreads();
        if (lr == 0) {
            #pragma unroll
            for (int i = 0; i < 8; i++) {
                const int col = wn * 32 + (i >> 1) * 8 + (lc << 1) + (i & 1);
                ssum[wm * 128 + col] = s8[i];
                ssq [wm * 128 + col] = q8[i];
            }
        }
        __syncthreads();
        if (tid < 128) {
            part[blockIdx.y * 256 + tid]       = ssum[tid] + ssum[128 + tid];
            part[blockIdx.y * 256 + 128 + tid] = ssq[tid]  + ssq[128 + tid];
        }
    }
}

// ============================================================================
// FUSED MoE, expert-split: grid (128, 2). Block (m, z) computes
// ypart[z] = sum_{e in {2z,2z+1}} gate[e] * (relu(h @ W1_e^T + b1_e) @ W2_e^T)
// for 64 tokens. hid never touches DRAM. 16 chunk-iterations per block.
// ============================================================================
#define SA_OFF  0u
#define SW1_OFF 17408u
#define SW2_OFF 52224u
#define SH_OFF  89088u
#define MOE_SMEM 107520

__global__ void __launch_bounds__(256) moe_fused(
    const __nv_bfloat16* __restrict__ hbf, const __nv_bfloat16* __restrict__ w1bf,
    const __nv_bfloat16* __restrict__ w2bf, const float* __restrict__ b1,
    const float* __restrict__ gates, float* __restrict__ ypart)
{
    extern __shared__ char msm[];
    const u32 smu = (u32)__cvta_generic_to_shared(msm);

    const int tid = threadIdx.x, wid = tid >> 5, lane = tid & 31;
    const int lr = lane >> 2, lc = lane & 3, sel = lane >> 3;
    const int wm = wid >> 1, wn = wid & 1;
    const int m0 = blockIdx.x << 6;
    const int e0 = blockIdx.y << 1;

    // ---- load A (64 tokens x 128) into smem
    #pragma unroll
    for (int j = 0; j < 4; j++) {
        const int idx = tid + (j << 8);
        const int row = idx >> 4, ch = (idx & 15) << 3;
        cpa16(smu + SA_OFF + (u32)(row * 136 + ch) * 2,
              hbf + (long)(m0 + row) * 128 + ch);
    }

#define MSTAGE(IT, S) do { \
    const int _e = e0 + ((IT) >> 3), _c = (IT) & 7; \
    const __nv_bfloat16* _w1 = w1bf + (long)((_e << 9) + (_c << 6)) * 128; \
    const __nv_bfloat16* _w2 = w2bf + (_e << 9) + (_c << 6); \
    _Pragma("unroll") \
    for (int j = 0; j < 4; j++) { \
        const int idx = tid + (j << 8); \
        const int r1 = idx >> 4, ch1 = (idx & 15) << 3; \
        cpa16(smu + SW1_OFF + (S) * 17408u + (u32)(r1 * 136 + ch1) * 2, \
              _w1 + (long)r1 * 128 + ch1); \
        const int r2 = idx >> 3, ch2 = (idx & 7) << 3; \
        cpa16(smu + SW2_OFF + (S) * 18432u + (u32)(r2 * 72 + ch2) * 2, \
              _w2 + (long)r2 * 2048 + ch2); \
    } \
    asm volatile("cp.async.commit_group;" ::: "memory"); \
} while (0)

    MSTAGE(0, 0);

    const u32 aoff1 = (u32)((wm * 16 + (lane & 7) + ((sel & 1) << 3)) * 136
                            + ((sel >> 1) << 3)) * 2;
    u32 boff1[2];
    #pragma unroll
    for (int nb = 0; nb < 2; nb++)
        boff1[nb] = (u32)((wn * 32 + nb * 16 + ((sel >> 1) << 3) + (lane & 7)) * 136
                          + ((sel & 1) << 3)) * 2;
    const u32 aoff2 = (u32)((wm * 16 + (lane & 7) + ((sel & 1) << 3)) * 72
                            + ((sel >> 1) << 3)) * 2;
    u32 boff2[4];
    #pragma unroll
    for (int nb = 0; nb < 4; nb++)
        boff2[nb] = (u32)((wn * 64 + nb * 16 + ((sel >> 1) << 3) + (lane & 7)) * 72
                          + ((sel & 1) << 3)) * 2;

    float acc2[8][4];
    #pragma unroll
    for (int ni = 0; ni < 8; ni++)
        #pragma unroll
        for (int j = 0; j < 4; j++) acc2[ni][j] = 0.f;

    const int row0 = wm * 16 + lr;
    const int gtok0 = m0 + row0, gtok1 = gtok0 + 8;

    for (int it = 0; it < 16; it++) {
        const int s = it & 1;
        const int e = e0 + (it >> 3), c = it & 7;
        if (it + 1 < 16) {
            MSTAGE(it + 1, s ^ 1);
            asm volatile("cp.async.wait_group 1;" ::: "memory");
        } else {
            asm volatile("cp.async.wait_group 0;" ::: "memory");
        }
        __syncthreads();

        // ---- GEMM1
        const u32 w1b = smu + SW1_OFF + s * 17408u;
        const u32 ab  = smu + SA_OFF;
        float acc1[4][4];
        #pragma unroll
        for (int ni = 0; ni < 4; ni++)
            #pragma unroll
            for (int j = 0; j < 4; j++) acc1[ni][j] = 0.f;
        #pragma unroll
        for (int k16 = 0; k16 < 8; k16++) {
            u32 a[4];
            ldsm4(a, ab + aoff1 + k16 * 32);
            #pragma unroll
            for (int nb = 0; nb < 2; nb++) {
                u32 bf[4];
                ldsm4(bf, w1b + boff1[nb] + k16 * 32);
                MMA_BF16(acc1[2 * nb    ], a, bf[0], bf[1]);
                MMA_BF16(acc1[2 * nb + 1], a, bf[2], bf[3]);
            }
        }
        // ---- bias + relu + gate -> bf16 smem
        const float g0 = __ldg(&gates[(long)gtok0 * NE + e]);
        const float g1 = __ldg(&gates[(long)gtok1 * NE + e]);
        const u32 hbse = smu + SH_OFF + s * 9216u;
        #pragma unroll
        for (int ni = 0; ni < 4; ni++) {
            const int col = wn * 32 + ni * 8 + (lc << 1);
            const float bb0 = __ldg(&b1[(e << 9) + (c << 6) + col]);
            const float bb1 = __ldg(&b1[(e << 9) + (c << 6) + col + 1]);
            float v0 = fmaxf(acc1[ni][0] + bb0, 0.f) * g0;
            float v1 = fmaxf(acc1[ni][1] + bb1, 0.f) * g0;
            float v2 = fmaxf(acc1[ni][2] + bb0, 0.f) * g1;
            float v3 = fmaxf(acc1[ni][3] + bb1, 0.f) * g1;
            __nv_bfloat162 p0 = __floats2bfloat162_rn(v0, v1);
            __nv_bfloat162 p1 = __floats2bfloat162_rn(v2, v3);
            asm volatile("st.shared.b32 [%0], %1;" ::
                "r"(hbse + (u32)(row0 * 72 + col) * 2), "r"(*(u32*)&p0));
            asm volatile("st.shared.b32 [%0], %1;" ::
                "r"(hbse + (u32)((row0 + 8) * 72 + col) * 2), "r"(*(u32*)&p1));
        }
        __syncthreads();

        // ---- GEMM2
        const u32 w2b = smu + SW2_OFF + s * 18432u;
        #pragma unroll
        for (int k16 = 0; k16 < 4; k16++) {
            u32 a[4];
            ldsm4(a, hbse + aoff2 + k16 * 32);
            #pragma unroll
            for (int nb = 0; nb < 4; nb++) {
                u32 bf[4];
                ldsm4(bf, w2b + boff2[nb] + k16 * 32);
                MMA_BF16(acc2[2 * nb    ], a, bf[0], bf[1]);
                MMA_BF16(acc2[2 * nb + 1], a, bf[2], bf[3]);
            }
        }
        __syncthreads();
    }
#undef MSTAGE

    float* yz = ypart + (long)blockIdx.y * NTOK * DD;
    #pragma unroll
    for (int ni = 0; ni < 8; ni++) {
        const int col = wn * 64 + ni * 8 + (lc << 1);
        *(float2*)&yz[(long)gtok0 * DD + col] = make_float2(acc2[ni][0], acc2[ni][1]);
        *(float2*)&yz[(long)gtok1 * DD + col] = make_float2(acc2[ni][2], acc2[ni][3]);
    }
}

// ============================================================================
// MMA flash attention (unchanged; emits oB/oS tf32 split).
// ============================================================================
#define KSR 20
#define VSR 1044
#define PSR 132
#define SM_Q 0
#define SM_K (128 * KSR)
#define SM_V (SM_K + 1024 * KSR)
#define SM_P (SM_V + 16 * VSR)
#define ATTN_SMEM ((SM_P + 128 * PSR) * 4)

__global__ void __launch_bounds__(256) attn_mma(const float* __restrict__ qkv,
                                                float* __restrict__ oB,
                                                float* __restrict__ oS)
{
    extern __shared__ float sm[];
    const int bh = blockIdx.x, b = bh >> 3, h = bh & 7;
    const int qt = blockIdx.y;
    const int tid = threadIdx.x, wid = tid >> 5, lane = tid & 31;
    const int lr = lane >> 2, lc = lane & 3;
    const float* qkvb = qkv + (long)b * SS * 384;
    const int qoff = h * HD, koff = DD + h * HD, voff = 2 * DD + h * HD;

    for (int i = tid; i < SS * 4; i += 256) {
        const int s = i >> 2, c4 = (i & 3) << 2;
        float4 v = *(const float4*)(qkvb + (long)s * 384 + koff + c4);
        *(float4*)&sm[SM_K + s * KSR + c4] =
            make_float4(tf32f(v.x), tf32f(v.y), tf32f(v.z), tf32f(v.w));
        float4 w = *(const float4*)(qkvb + (long)s * 384 + voff + c4);
        sm[SM_V + (c4 + 0) * VSR + s] = tf32f(w.x);
        sm[SM_V + (c4 + 1) * VSR + s] = tf32f(w.y);
        sm[SM_V + (c4 + 2) * VSR + s] = tf32f(w.z);
        sm[SM_V + (c4 + 3) * VSR + s] = tf32f(w.w);
    }
    for (int i = tid; i < 128 * 4; i += 256) {
        const int s = i >> 2, c4 = (i & 3) << 2;
        float4 v = *(const float4*)(qkvb + (long)(qt * 128 + s) * 384 + qoff + c4);
        *(float4*)&sm[SM_Q + s * KSR + c4] =
            make_float4(tf32f(v.x * 0.25f), tf32f(v.y * 0.25f),
                        tf32f(v.z * 0.25f), tf32f(v.w * 0.25f));
    }
    __syncthreads();

    const int wq = wid << 4;
    u32 qf[2][4];
    #pragma unroll
    for (int k8 = 0; k8 < 2; k8++) {
        const int c = (k8 << 3) + lc;
        qf[k8][0] = __float_as_uint(sm[SM_Q + (wq + lr    ) * KSR + c    ]);
        qf[k8][1] = __float_as_uint(sm[SM_Q + (wq + lr + 8) * KSR + c    ]);
        qf[k8][2] = __float_as_uint(sm[SM_Q + (wq + lr    ) * KSR + c + 4]);
        qf[k8][3] = __float_as_uint(sm[SM_Q + (wq + lr + 8) * KSR + c + 4]);
    }

    float oacc[2][4];
    #pragma unroll
    for (int t = 0; t < 2; t++)
        #pragma unroll
        for (int j = 0; j < 4; j++) oacc[t][j] = 0.f;
    float sl0 = 0.f, sl1 = 0.f;

    float* Prow0 = &sm[SM_P + (wq + lr) * PSR];
    float* Prow1 = Prow0 + 8 * PSR;

    for (int kt = 0; kt < 8; kt++) {
        #pragma unroll
        for (int ni = 0; ni < 16; ni++) {
            const int krow = kt * 128 + ni * 8 + lr;
            const float* kp = &sm[SM_K + krow * KSR];
            u32 b00 = __float_as_uint(kp[lc]),      u01 = __float_as_uint(kp[lc + 4]);
            u32 b10 = __float_as_uint(kp[lc + 8]),  u11 = __float_as_uint(kp[lc + 12]);
            float sacc[4] = {0.f, 0.f, 0.f, 0.f};
            MMA_TF32(sacc, qf[0][0], qf[0][1], qf[0][2], qf[0][3], b00, u01);
            MMA_TF32(sacc, qf[1][0], qf[1][1], qf[1][2], qf[1][3], b10, u11);
            const float p0 = __expf(sacc[0]), p1 = __expf(sacc[1]);
            const float p2 = __expf(sacc[2]), p3 = __expf(sacc[3]);
            sl0 += p0 + p1;
            sl1 += p2 + p3;
            const int col = ni * 8 + (lc << 1);
            *(float2*)&Prow0[col] = make_float2(tf32f(p0), tf32f(p1));
            *(float2*)&Prow1[col] = make_float2(tf32f(p2), tf32f(p3));
        }
        __syncwarp();
        #pragma unroll
        for (int k8 = 0; k8 < 16; k8++) {
            const int kc2 = (k8 << 3) + lc;
            u32 a0 = __float_as_uint(Prow0[kc2]);
            u32 a1 = __float_as_uint(Prow1[kc2]);
            u32 a2 = __float_as_uint(Prow0[kc2 + 4]);
            u32 a3 = __float_as_uint(Prow1[kc2 + 4]);
            const int kg = kt * 128 + kc2;
            u32 v00 = __float_as_uint(sm[SM_V + (lr    ) * VSR + kg]);
            u32 v01 = __float_as_uint(sm[SM_V + (lr    ) * VSR + kg + 4]);
            u32 v10 = __float_as_uint(sm[SM_V + (lr + 8) * VSR + kg]);
            u32 v11 = __float_as_uint(sm[SM_V + (lr + 8) * VSR + kg + 4]);
            MMA_TF32(oacc[0], a0, a1, a2, a3, v00, v01);
            MMA_TF32(oacc[1], a0, a1, a2, a3, v10, v11);
        }
        __syncwarp();
    }

    sl0 += __shfl_xor_sync(0xffffffffu, sl0, 1);
    sl0 += __shfl_xor_sync(0xffffffffu, sl0, 2);
    sl1 += __shfl_xor_sync(0xffffffffu, sl1, 1);
    sl1 += __shfl_xor_sync(0xffffffffu, sl1, 2);
    const float i0 = 1.f / sl0, i1 = 1.f / sl1;

    const long r0 = (long)(b * SS + qt * 128 + wq + lr);
    const long r1 = r0 + 8;
    #pragma unroll
    for (int t = 0; t < 2; t++) {
        const int col = h * HD + t * 8 + (lc << 1);
        float w0 = oacc[t][0] * i0, w1 = oacc[t][1] * i0;
        float w2 = oacc[t][2] * i1, w3 = oacc[t][3] * i1;
        float bb0 = tf32f(w0), bb1 = tf32f(w1), bb2 = tf32f(w2), bb3 = tf32f(w3);
        *(float2*)&oB[r0 * DD + col] = make_float2(bb0, bb1);
        *(float2*)&oB[r1 * DD + col] = make_float2(bb2, bb3);
        *(float2*)&oS[r0 * DD + col] = make_float2(tf32f(w0 - bb0), tf32f(w1 - bb1));
        *(float2*)&oS[r1 * DD + col] = make_float2(tf32f(w2 - bb2), tf32f(w3 - bb3));
    }
}

// ============================================================================
// Norm-1 apply FUSED with gating + bf16 h emit (stats from O-proj epilogue).
// ============================================================================
__global__ void in_apply1(const float* __restrict__ in, const float* __restrict__ part,
                          const float* __restrict__ w, const float* __restrict__ bparm,
                          const float* __restrict__ wg,
                          float* __restrict__ hout, __nv_bfloat16* __restrict__ hbf,
                          float* __restrict__ gates)
{
    const int b = blockIdx.y, chunk = blockIdx.x;
    __shared__ float sc[DD], sf[DD], wgS[DD * NE];
    wgS[threadIdx.x] = wg[threadIdx.x];
    wgS[threadIdx.x + 256] = wg[threadIdx.x + 256];
    if (threadIdx.x < DD) {
        const int d = threadIdx.x;
        float s = 0.f, q = 0.f;
        for (int c = 0; c < 16; c++) {
            const float* p = part + (long)(b * 16 + c) * 256;
            s += p[d]; q += p[DD + d];
        }
        float mean = s * (1.f / 1024.f);
        float var  = q * (1.f / 1024.f) - mean * mean;
        float inv  = rsqrtf(var + 1e-5f);
        float scale = w[d] * inv;
        sc[d] = scale;
        sf[d] = bparm[d] - mean * scale;
    }
    __syncthreads();
    const long row0 = (long)b * SS + chunk * 64;
    const int c4 = threadIdx.x & 31, rg = threadIdx.x >> 5;
    const int c0 = c4 << 2;
    for (int r = rg; r < 64; r += 8) {
        const long tok = row0 + r;
        float4 v = *(const float4*)(in + tok * DD + c0);
        float4 o;
        o.x = v.x * sc[c0 + 0] + sf[c0 + 0];
        o.y = v.y * sc[c0 + 1] + sf[c0 + 1];
        o.z = v.z * sc[c0 + 2] + sf[c0 + 2];
        o.w = v.w * sc[c0 + 3] + sf[c0 + 3];
        *(float4*)(hout + tok * DD + c0) = o;
        __nv_bfloat162 p0 = __floats2bfloat162_rn(o.x, o.y);
        __nv_bfloat162 p1 = __floats2bfloat162_rn(o.z, o.w);
        *(uint2*)(hbf + tok * DD + c0) = make_uint2(*(u32*)&p0, *(u32*)&p1);
        float l0 = o.x * wgS[(c0 + 0) * NE + 0] + o.y * wgS[(c0 + 1) * NE + 0]
                 + o.z * wgS[(c0 + 2) * NE + 0] + o.w * wgS[(c0 + 3) * NE + 0];
        float l1 = o.x * wgS[(c0 + 0) * NE + 1] + o.y * wgS[(c0 + 1) * NE + 1]
                 + o.z * wgS[(c0 + 2) * NE + 1] + o.w * wgS[(c0 + 3) * NE + 1];
        float l2 = o.x * wgS[(c0 + 0) * NE + 2] + o.y * wgS[(c0 + 1) * NE + 2]
                 + o.z * wgS[(c0 + 2) * NE + 2] + o.w * wgS[(c0 + 3) * NE + 2];
        float l3 = o.x * wgS[(c0 + 0) * NE + 3] + o.y * wgS[(c0 + 1) * NE + 3]
                 + o.z * wgS[(c0 + 2) * NE + 3] + o.w * wgS[(c0 + 3) * NE + 3];
        #pragma unroll
        for (int off = 16; off; off >>= 1) {
            l0 += __shfl_xor_sync(0xffffffffu, l0, off);
            l1 += __shfl_xor_sync(0xffffffffu, l1, off);
            l2 += __shfl_xor_sync(0xffffffffu, l2, off);
            l3 += __shfl_xor_sync(0xffffffffu, l3, off);
        }
        if (c4 == 0) {
            float lg[4] = {l0, l1, l2, l3};
            int i1 = 0; float v1 = lg[0];
            #pragma unroll
            for (int e = 1; e < 4; e++) if (lg[e] > v1) { v1 = lg[e]; i1 = e; }
            int i2 = 0; float v2 = -3e38f;
            #pragma unroll
            for (int e = 0; e < 4; e++) if (e != i1 && lg[e] > v2) { v2 = lg[e]; i2 = e; }
            float e2  = expf(v2 - v1);
            float inv = 1.f / (1.f + e2);
            float* gp = gates + tok * NE;
            #pragma unroll
            for (int e = 0; e < 4; e++)
                gp[e] = (e == i1) ? inv : ((e == i2) ? e2 * inv : 0.f);
        }
    }
}

// ============================================================================
// Norm-2 apply
// ============================================================================
__global__ void in_apply2(const float* __restrict__ in, const float* __restrict__ part,
                          const float* __restrict__ w, const float* __restrict__ bb,
                          float* __restrict__ out)
{
    const int b = blockIdx.y, chunk = blockIdx.x;
    __shared__ float sc[DD], sf[DD];
    if (threadIdx.x < DD) {
        const int d = threadIdx.x;
        float s = 0.f, q = 0.f;
        for (int c = 0; c < 16; c++) {
            const float* p = part + (long)((b * 16 + c) * 2) * DD;
            s += p[d]; q += p[DD + d];
        }
        float mean = s * (1.f / 1024.f);
        float var  = q * (1.f / 1024.f) - mean * mean;
        float inv  = rsqrtf(var + 1e-5f);
        float scale = w[d] * inv;
        sc[d] = scale;
        sf[d] = bb[d] - mean * scale;
    }
    __syncthreads();
    const float* base = in + ((long)b * SS + chunk * 64) * DD;
    float* ob = out + ((long)b * SS + chunk * 64) * DD;
    const int c4 = threadIdx.x & 31, rg = threadIdx.x >> 5;
    for (int r = rg; r < 64; r += 8) {
        float4 v = *(const float4*)(base + (long)r * DD + (c4 << 2));
        float4 o;
        o.x = v.x * sc[(c4 << 2) + 0] + sf[(c4 << 2) + 0];
        o.y = v.y * sc[(c4 << 2) + 1] + sf[(c4 << 2) + 1];
        o.z = v.z * sc[(c4 << 2) + 2] + sf[(c4 << 2) + 2];
        o.w = v.w * sc[(c4 << 2) + 3] + sf[(c4 << 2) + 3];
        *(float4*)(ob + (long)r * DD + (c4 << 2)) = o;
    }
}

// ============================================================================
// FUSED: pre2 = ypart[0] + ypart[1] + h + gate.b2, plus norm-2 stats.
// ============================================================================
__global__ void add_stats(const float* __restrict__ yp, const float* __restrict__ h,
                          const float* __restrict__ gates, const float* __restrict__ b2,
                          float* __restrict__ pre2, float* __restrict__ part)
{
    const int b = blockIdx.y, chunk = blockIdx.x;
    __shared__ float b2s[NE * DD];
    b2s[threadIdx.x] = b2[threadIdx.x];
    b2s[threadIdx.x + 256] = b2[threadIdx.x + 256];
    __syncthreads();
    const long row0 = (long)b * SS + chunk * 64;
    const int c4 = threadIdx.x & 31, rg = threadIdx.x >> 5;
    const int c0 = c4 << 2;
    float4 s = make_float4(0.f, 0.f, 0.f, 0.f), q = s;
    for (int r = rg; r < 64; r += 8) {
        const long tok = row0 + r;
        const long idx = tok * DD + c0;
        const float* g = gates + tok * NE;
        const float g0 = g[0], g1 = g[1], g2 = g[2], g3 = g[3];
        float4 v = *(const float4*)(yp + idx);
        float4 v1 = *(const float4*)(yp + (long)NTOK * DD + idx);
        float4 hv = *(const float4*)(h + idx);
        float4 o;
        o.x = v.x + v1.x + hv.x
            + g0 * b2s[c0 + 0] + g1 * b2s[DD + c0 + 0] + g2 * b2s[2 * DD + c0 + 0] + g3 * b2s[3 * DD + c0 + 0];
        o.y = v.y + v1.y + hv.y
            + g0 * b2s[c0 + 1] + g1 * b2s[DD + c0 + 1] + g2 * b2s[2 * DD + c0 + 1] + g3 * b2s[3 * DD + c0 + 1];
        o.z = v.z + v1.z + hv.z
            + g0 * b2s[c0 + 2] + g1 * b2s[DD + c0 + 2] + g2 * b2s[2 * DD + c0 + 2] + g3 * b2s[3 * DD + c0 + 2];
        o.w = v.w + v1.w + hv.w
            + g0 * b2s[c0 + 3] + g1 * b2s[DD + c0 + 3] + g2 * b2s[2 * DD + c0 + 3] + g3 * b2s[3 * DD + c0 + 3];
        *(float4*)(pre2 + idx) = o;
        s.x += o.x; s.y += o.y; s.z += o.z; s.w += o.w;
        q.x += o.x * o.x; q.y += o.y * o.y; q.z += o.z * o.z; q.w += o.w * o.w;
    }
    __shared__ float4 sS[8][32], sQ[8][32];
    sS[rg][c4] = s; sQ[rg][c4] = q;
    __syncthreads();
    if (threadIdx.x < 32) {
        float4 ts = make_float4(0.f, 0.f, 0.f, 0.f), tq = ts;
        #pragma unroll
        for (int i = 0; i < 8; i++) {
            float4 a = sS[i][threadIdx.x], bq = sQ[i][threadIdx.x];
            ts.x += a.x; ts.y += a.y; ts.z += a.z; ts.w += a.w;
            tq.x += bq.x; tq.y += bq.y; tq.z += bq.z; tq.w += bq.w;
        }
        float* p = part + (long)((b * 16 + chunk) * 2) * DD;
        *(float4*)(p + (threadIdx.x << 2)) = ts;
        *(float4*)(p + DD + (threadIdx.x << 2)) = tq;
    }
}

// ============================================================================
// Launch (8 kernels)
// ============================================================================
extern "C" void kernel_launch(void* const* d_in, const int* in_sizes, int n_in,
                              void* d_out, int out_size)
{
    const float* x     = (const float*)d_in[0];
    const float* Wqkv  = (const float*)d_in[1];
    const float* bqkv  = (const float*)d_in[2];
    const float* Wo    = (const float*)d_in[3];
    const float* bo    = (const float*)d_in[4];
    const float* n1w   = (const float*)d_in[5];
    const float* n1b   = (const float*)d_in[6];
    const float* n2w   = (const float*)d_in[7];
    const float* n2b   = (const float*)d_in[8];
    const float* wg    = (const float*)d_in[9];
    const float* W1    = (const float*)d_in[10];
    const float* b1    = (const float*)d_in[11];
    const float* W2    = (const float*)d_in[12];
    const float* b2    = (const float*)d_in[13];

    float *qkv, *xB, *xS, *oB, *oS, *pre1, *h, *gates, *ypart, *pre2;
    float *wqkvB, *wqkvS, *woB, *woS, *part;
    __nv_bfloat16 *hbf, *w1bf, *w2bf;
    cudaGetSymbolAddress((void**)&qkv,   g_qkv);
    cudaGetSymbolAddress((void**)&xB,    g_xB);
    cudaGetSymbolAddress((void**)&xS,    g_xS);
    cudaGetSymbolAddress((void**)&oB,    g_oB);
    cudaGetSymbolAddress((void**)&oS,    g_oS);
    cudaGetSymbolAddress((void**)&pre1,  g_pre1);
    cudaGetSymbolAddress((void**)&h,     g_h);
    cudaGetSymbolAddress((void**)&hbf,   g_hbf);
    cudaGetSymbolAddress((void**)&gates, g_gates);
    cudaGetSymbolAddress((void**)&ypart, g_ypart);
    cudaGetSymbolAddress((void**)&pre2,  g_pre2);
    cudaGetSymbolAddress((void**)&w1bf,  g_w1bf);
    cudaGetSymbolAddress((void**)&w2bf,  g_w2bf);
    cudaGetSymbolAddress((void**)&wqkvB, g_wqkvB);
    cudaGetSymbolAddress((void**)&wqkvS, g_wqkvS);
    cudaGetSymbolAddress((void**)&woB,   g_woB);
    cudaGetSymbolAddress((void**)&woS,   g_woS);
    cudaGetSymbolAddress((void**)&part,  g_part);

    cudaFuncSetAttribute(attn_mma, cudaFuncAttributeMaxDynamicSharedMemorySize, ATTN_SMEM);
    cudaFuncSetAttribute(gemm_mma3, cudaFuncAttributeMaxDynamicSharedMemorySize, 61440);
    cudaFuncSetAttribute(moe_fused, cudaFuncAttributeMaxDynamicSharedMemorySize, MOE_SMEM);

    // 0. Merged prep
    weight_prep<<<608, 256>>>(Wqkv, Wo, W1, W2, x,
                              wqkvB, wqkvS, woB, woS, w1bf, w2bf, xB, xS);

    // 1. QKV projection (3xTF32, BK=16, 2 blocks/SM)
    gemm_mma3<<<dim3(3, 128), 256, 61440>>>(xB, xS, wqkvB, wqkvS, bqkv, nullptr, qkv,
                                            128, 128, 384, 8, 0, nullptr);

    // 2. MMA flash attention
    attn_mma<<<dim3(64, 8), 256, ATTN_SMEM>>>(qkv, oB, oS);

    // 3. O-projection + bo + residual x ⊕ norm-1 stats
    gemm_mma3<<<dim3(1, 128), 256, 61440>>>(oB, oS, woB, woS, bo, x, pre1,
                                            128, 128, 128, 8, 128, part);

    // 4. Norm-1 apply ⊕ gating ⊕ bf16-h
    in_apply1<<<dim3(16, 8), 256>>>(pre1, part, n1w, n1b, wg, h, hbf, gates);

    // 5. FUSED MoE (expert-split, grid 128x2 — all SMs covered)
    moe_fused<<<dim3(128, 2), 256, MOE_SMEM>>>(hbf, w1bf, w2bf, b1, gates, ypart);

    // 6. pre2 = ypart0 + ypart1 + h + gate·b2 ⊕ norm-2 stats
    add_stats<<<dim3(16, 8), 256>>>(ypart, h, gates, b2, pre2, part);

    // 7. Norm-2 apply -> output
    in_apply2<<<dim3(16, 8), 256>>>(pre2, part, n2w, n2b, (float*)d_out);
}

// round 11
// speedup vs baseline: 1.1835x; 1.0510x over previous
#include <cuda_runtime.h>
#include <cuda_bf16.h>

typedef unsigned long long ull;
typedef unsigned int u32;

// ===================== helpers =======================
__device__ __forceinline__ u32 f2tf32(float x) {
    u32 u; asm("cvt.rna.tf32.f32 %0, %1;" : "=r"(u) : "f"(x)); return u;
}
__device__ __forceinline__ float tf32f(float x) {
    return __uint_as_float(f2tf32(x));
}
#define MMA_TF32(acc, a0, a1, a2, a3, b0, b1) \
    asm volatile( \
        "mma.sync.aligned.m16n8k8.row.col.f32.tf32.tf32.f32 " \
        "{%0,%1,%2,%3}, {%4,%5,%6,%7}, {%8,%9}, {%0,%1,%2,%3};" \
        : "+f"((acc)[0]), "+f"((acc)[1]), "+f"((acc)[2]), "+f"((acc)[3]) \
        : "r"(a0), "r"(a1), "r"(a2), "r"(a3), "r"(b0), "r"(b1))

#define MMA_BF16(acc, a, b0, b1) \
    asm volatile( \
        "mma.sync.aligned.m16n8k16.row.col.f32.bf16.bf16.f32 " \
        "{%0,%1,%2,%3}, {%4,%5,%6,%7}, {%8,%9}, {%0,%1,%2,%3};" \
        : "+f"((acc)[0]), "+f"((acc)[1]), "+f"((acc)[2]), "+f"((acc)[3]) \
        : "r"((a)[0]), "r"((a)[1]), "r"((a)[2]), "r"((a)[3]), "r"(b0), "r"(b1))

__device__ __forceinline__ void ldsm4(u32* r, u32 addr) {
    asm volatile("ldmatrix.sync.aligned.m8n8.x4.shared.b16 {%0,%1,%2,%3}, [%4];"
        : "=r"(r[0]), "=r"(r[1]), "=r"(r[2]), "=r"(r[3]) : "r"(addr));
}
__device__ __forceinline__ void cpa16(u32 dst, const void* src) {
    asm volatile("cp.async.cg.shared.global [%0], [%1], 16;" :: "r"(dst), "l"(src));
}

// ===================== problem constants ====================================
#define BB    8
#define SS    1024
#define DD    128
#define NH    8
#define HD    16
#define NTOK  8192
#define HFF   512
#define NE    4

// ===================== scratch ==============================================
__device__ float         g_qkv  [NTOK * 384];
__device__ float         g_xB   [NTOK * DD];
__device__ float         g_xS   [NTOK * DD];
__device__ float         g_oB   [NTOK * DD];
__device__ float         g_oS   [NTOK * DD];
__device__ float         g_pre1 [NTOK * DD];
__device__ float         g_h    [NTOK * DD];
__device__ __nv_bfloat16 g_hbf  [NTOK * DD];
__device__ float         g_gates[NTOK * NE];
__device__ float         g_ypart[2 * NTOK * DD];
__device__ float         g_pre2 [NTOK * DD];
__device__ __nv_bfloat16 g_w1bf [NE * HFF * DD];
__device__ __nv_bfloat16 g_w2bf [DD * NE * HFF];
__device__ float         g_wqkvB[384 * DD];
__device__ float         g_wqkvS[384 * DD];
__device__ float         g_woB  [DD * DD];
__device__ float         g_woS  [DD * DD];
__device__ float         g_part [128 * 256];

// ============================================================================
// Merged prep: weight transposes + x tf32-split (unchanged).
// ============================================================================
__global__ void __launch_bounds__(256) weight_prep(
    const float* __restrict__ Wqkv, const float* __restrict__ Wo,
    const float* __restrict__ W1,   const float* __restrict__ W2,
    const float* __restrict__ x,
    float* __restrict__ wqkvB, float* __restrict__ wqkvS,
    float* __restrict__ woB,   float* __restrict__ woS,
    __nv_bfloat16* __restrict__ w1bf, __nv_bfloat16* __restrict__ w2bf,
    float* __restrict__ xB, float* __restrict__ xS)
{
    int bid = blockIdx.x;
    if (bid >= 576) {
        const long base = (long)(bid - 576) * 32768;
        for (int i = threadIdx.x * 4; i < 32768; i += 1024) {
            float4 v = *(const float4*)(x + base + i);
            u32 b0 = f2tf32(v.x), b1 = f2tf32(v.y), b2 = f2tf32(v.z), b3 = f2tf32(v.w);
            *(float4*)(xB + base + i) = make_float4(
                __uint_as_float(b0), __uint_as_float(b1),
                __uint_as_float(b2), __uint_as_float(b3));
            *(float4*)(xS + base + i) = make_float4(
                tf32f(v.x - __uint_as_float(b0)), tf32f(v.y - __uint_as_float(b1)),
                tf32f(v.z - __uint_as_float(b2)), tf32f(v.w - __uint_as_float(b3)));
        }
        return;
    }

    __shared__ float t[32][33];
    const float* src; int R, C, c0, r0, mode;
    float *dB = 0, *dS = 0; __nv_bfloat16* dH = 0;

    if (bid < 48) {
        src = Wqkv; R = 128; C = 384; mode = 0;
        c0 = (bid % 12) << 5; r0 = (bid / 12) << 5;
        dB = wqkvB; dS = wqkvS;
    } else if (bid < 64) {
        bid -= 48; src = Wo; R = 128; C = 128; mode = 0;
        c0 = (bid & 3) << 5; r0 = (bid >> 2) << 5;
        dB = woB; dS = woS;
    } else if (bid < 320) {
        bid -= 64;
        const int e = bid >> 6, rem = bid & 63;
        src = W1 + (long)e * 128 * 512; R = 128; C = 512; mode = 1;
        c0 = (rem & 15) << 5; r0 = (rem >> 4) << 5;
        dH = w1bf + (long)e * 512 * 128;
    } else {
        bid -= 320; src = W2; R = 2048; C = 128; mode = 1;
        c0 = (bid & 3) << 5; r0 = (bid >> 2) << 5;
        dH = w2bf;
    }

    for (int i = threadIdx.x; i < 1024; i += 256) {
        const int r = i >> 5, c = i & 31;
        t[r][c] = src[(long)(r0 + r) * C + c0 + c];
    }
    __syncthreads();
    for (int i = threadIdx.x; i < 1024; i += 256) {
        const int c = i >> 5, r = i & 31;
        const float v = t[r][c];
        const long o = (long)(c0 + c) * R + r0 + r;
        if (mode == 0) {
            const u32 big = f2tf32(v);
            dB[o] = __uint_as_float(big);
            dS[o] = __uint_as_float(f2tf32(v - __uint_as_float(big)));
        } else {
            dH[o] = __float2bfloat16(v);
        }
    }
}

// ============================================================================
// 3xTF32 mma GEMM (unchanged from round 10).
// ============================================================================
__global__ void __launch_bounds__(256) gemm_mma3(
    const float* __restrict__ Ab, const float* __restrict__ As,
    const float* __restrict__ Bb, const float* __restrict__ Bsm,
    const float* __restrict__ bias, const float* __restrict__ resid,
    float* __restrict__ C,
    int lda, int ldb, int ldc, int Kt, int ldres, float* __restrict__ part)
{
    extern __shared__ float dynsm[];
    const u32 smu = (u32)__cvta_generic_to_shared(dynsm);

    const int tid = threadIdx.x, wid = tid >> 5, lane = tid & 31;
    const int m0 = blockIdx.y << 6, n0 = blockIdx.x << 7;
    const int wm = wid >> 2, wn = wid & 3;
    const int lr = lane >> 2, lc = lane & 3;

    const float* Abase  = Ab  + (long)m0 * lda;
    const float* Asbase = As  + (long)m0 * lda;
    const float* Bbase  = Bb  + (long)n0 * ldb;
    const float* Bsbase = Bsm + (long)n0 * ldb;

    float acc[2][4][4];
    #pragma unroll
    for (int mi = 0; mi < 2; mi++)
        #pragma unroll
        for (int ni = 0; ni < 4; ni++)
            #pragma unroll
            for (int j = 0; j < 4; j++) acc[mi][ni][j] = 0.f;

#define STAGE3(KT, S) do { \
    const int _k0 = (KT) << 4; \
    const u32 _sb = smu + (S) * 30720; \
    { \
        const int row = tid >> 2, ch = (tid & 3) << 2; \
        const u32 off = (u32)(row * 20 + ch) * 4; \
        cpa16(_sb + off,        Abase  + (long)row * lda + _k0 + ch); \
        cpa16(_sb + 5120 + off, Asbase + (long)row * lda + _k0 + ch); \
    } \
    _Pragma("unroll") \
    for (int c = 0; c < 2; c++) { \
        const int idx = tid + (c << 8); \
        const int row = idx >> 2, ch = (idx & 3) << 2; \
        const u32 off = (u32)(row * 20 + ch) * 4; \
        cpa16(_sb + 10240 + off, Bbase  + (long)row * ldb + _k0 + ch); \
        cpa16(_sb + 20480 + off, Bsbase + (long)row * ldb + _k0 + ch); \
    } \
    asm volatile("cp.async.commit_group;" ::: "memory"); \
} while (0)

    STAGE3(0, 0);
    for (int kt = 0; kt < Kt; kt++) {
        const int s = kt & 1;
        if (kt + 1 < Kt) {
            STAGE3(kt + 1, (kt + 1) & 1);
            asm volatile("cp.async.wait_group 1;" ::: "memory");
        } else {
            asm volatile("cp.async.wait_group 0;" ::: "memory");
        }
        __syncthreads();
        float* AbP = dynsm + s * 7680;
        float* AmP = AbP + 1280;
        float* BsP = AbP + 2560;
        float* BmP = AbP + 5120;
        #pragma unroll
        for (int k8 = 0; k8 < 2; k8++) {
            const int kc = (k8 << 3) + lc;
            u32 af[2][4], am[2][4];
            #pragma unroll
            for (int mi = 0; mi < 2; mi++) {
                const int r = wm * 32 + mi * 16 + lr;
                af[mi][0] = __float_as_uint(AbP[(r    ) * 20 + kc    ]);
                af[mi][1] = __float_as_uint(AbP[(r + 8) * 20 + kc    ]);
                af[mi][2] = __float_as_uint(AbP[(r    ) * 20 + kc + 4]);
                af[mi][3] = __float_as_uint(AbP[(r + 8) * 20 + kc + 4]);
                am[mi][0] = __float_as_uint(AmP[(r    ) * 20 + kc    ]);
                am[mi][1] = __float_as_uint(AmP[(r + 8) * 20 + kc    ]);
                am[mi][2] = __float_as_uint(AmP[(r    ) * 20 + kc + 4]);
                am[mi][3] = __float_as_uint(AmP[(r + 8) * 20 + kc + 4]);
            }
            #pragma unroll
            for (int ni = 0; ni < 4; ni++) {
                const int nr = wn * 32 + ni * 8 + lr;
                u32 b0 = __float_as_uint(BsP[nr * 20 + kc    ]);
                u32 b1 = __float_as_uint(BsP[nr * 20 + kc + 4]);
                u32 s0 = __float_as_uint(BmP[nr * 20 + kc    ]);
                u32 s1 = __float_as_uint(BmP[nr * 20 + kc + 4]);
                #pragma unroll
                for (int mi = 0; mi < 2; mi++) {
                    MMA_TF32(acc[mi][ni], am[mi][0], am[mi][1], am[mi][2], am[mi][3], b0, b1);
                    MMA_TF32(acc[mi][ni], af[mi][0], af[mi][1], af[mi][2], af[mi][3], s0, s1);
                    MMA_TF32(acc[mi][ni], af[mi][0], af[mi][1], af[mi][2], af[mi][3], b0, b1);
                }
            }
        }
        __syncthreads();
    }
#undef STAGE3

    float s8[8], q8[8];
    #pragma unroll
    for (int i = 0; i < 8; i++) { s8[i] = 0.f; q8[i] = 0.f; }

    #pragma unroll
    for (int mi = 0; mi < 2; mi++) {
        const int r0 = m0 + wm * 32 + mi * 16 + lr;
        const int r1 = r0 + 8;
        #pragma unroll
        for (int ni = 0; ni < 4; ni++) {
            const int col = wn * 32 + ni * 8 + (lc << 1);
            float v0 = acc[mi][ni][0], v1 = acc[mi][ni][1];
            float v2 = acc[mi][ni][2], v3 = acc[mi][ni][3];
            if (bias) {
                float2 bbv = *(const float2*)&bias[n0 + col];
                v0 += bbv.x; v1 += bbv.y; v2 += bbv.x; v3 += bbv.y;
            }
            if (resid) {
                float2 ra = *(const float2*)&resid[(long)r0 * ldres + n0 + col];
                float2 rb = *(const float2*)&resid[(long)r1 * ldres + n0 + col];
                v0 += ra.x; v1 += ra.y; v2 += rb.x; v3 += rb.y;
            }
            *(float2*)&C[(long)r0 * ldc + n0 + col] = make_float2(v0, v1);
            *(float2*)&C[(long)r1 * ldc + n0 + col] = make_float2(v2, v3);
            if (part) {
                s8[ni * 2 + 0] += v0 + v2;
                s8[ni * 2 + 1] += v1 + v3;
                q8[ni * 2 + 0] += v0 * v0 + v2 * v2;
                q8[ni * 2 + 1] += v1 * v1 + v3 * v3;
            }
        }
    }

    if (part) {
        #pragma unroll
        for (int i = 0; i < 8; i++) {
            s8[i] += __shfl_xor_sync(0xffffffffu, s8[i], 4);
            s8[i] += __shfl_xor_sync(0xffffffffu, s8[i], 8);
            s8[i] += __shfl_xor_sync(0xffffffffu, s8[i], 16);
            q8[i] += __shfl_xor_sync(0xffffffffu, q8[i], 4);
            q8[i] += __shfl_xor_sync(0xffffffffu, q8[i], 8);
            q8[i] += __shfl_xor_sync(0xffffffffu, q8[i], 16);
        }
        float* ssum = dynsm;
        float* ssq  = dynsm + 256;
        __syncthreads();
        if (lr == 0) {
            #pragma unroll
            for (int i = 0; i < 8; i++) {
                const int col = wn * 32 + (i >> 1) * 8 + (lc << 1) + (i & 1);
                ssum[wm * 128 + col] = s8[i];
                ssq [wm * 128 + col] = q8[i];
            }
        }
        __syncthreads();
        if (tid < 128) {
            part[blockIdx.y * 256 + tid]       = ssum[tid] + ssum[128 + tid];
            part[blockIdx.y * 256 + 128 + tid] = ssq[tid]  + ssq[128 + tid];
        }
    }
}

// ============================================================================
// FUSED MoE, expert-split (unchanged from round 10).
// ============================================================================
#define SA_OFF  0u
#define SW1_OFF 17408u
#define SW2_OFF 52224u
#define SH_OFF  89088u
#define MOE_SMEM 107520

__global__ void __launch_bounds__(256) moe_fused(
    const __nv_bfloat16* __restrict__ hbf, const __nv_bfloat16* __restrict__ w1bf,
    const __nv_bfloat16* __restrict__ w2bf, const float* __restrict__ b1,
    const float* __restrict__ gates, float* __restrict__ ypart)
{
    extern __shared__ char msm[];
    const u32 smu = (u32)__cvta_generic_to_shared(msm);

    const int tid = threadIdx.x, wid = tid >> 5, lane = tid & 31;
    const int lr = lane >> 2, lc = lane & 3, sel = lane >> 3;
    const int wm = wid >> 1, wn = wid & 1;
    const int m0 = blockIdx.x << 6;
    const int e0 = blockIdx.y << 1;

    #pragma unroll
    for (int j = 0; j < 4; j++) {
        const int idx = tid + (j << 8);
        const int row = idx >> 4, ch = (idx & 15) << 3;
        cpa16(smu + SA_OFF + (u32)(row * 136 + ch) * 2,
              hbf + (long)(m0 + row) * 128 + ch);
    }

#define MSTAGE(IT, S) do { \
    const int _e = e0 + ((IT) >> 3), _c = (IT) & 7; \
    const __nv_bfloat16* _w1 = w1bf + (long)((_e << 9) + (_c << 6)) * 128; \
    const __nv_bfloat16* _w2 = w2bf + (_e << 9) + (_c << 6); \
    _Pragma("unroll") \
    for (int j = 0; j < 4; j++) { \
        const int idx = tid + (j << 8); \
        const int r1 = idx >> 4, ch1 = (idx & 15) << 3; \
        cpa16(smu + SW1_OFF + (S) * 17408u + (u32)(r1 * 136 + ch1) * 2, \
              _w1 + (long)r1 * 128 + ch1); \
        const int r2 = idx >> 3, ch2 = (idx & 7) << 3; \
        cpa16(smu + SW2_OFF + (S) * 18432u + (u32)(r2 * 72 + ch2) * 2, \
              _w2 + (long)r2 * 2048 + ch2); \
    } \
    asm volatile("cp.async.commit_group;" ::: "memory"); \
} while (0)

    MSTAGE(0, 0);

    const u32 aoff1 = (u32)((wm * 16 + (lane & 7) + ((sel & 1) << 3)) * 136
                            + ((sel >> 1) << 3)) * 2;
    u32 boff1[2];
    #pragma unroll
    for (int nb = 0; nb < 2; nb++)
        boff1[nb] = (u32)((wn * 32 + nb * 16 + ((sel >> 1) << 3) + (lane & 7)) * 136
                          + ((sel & 1) << 3)) * 2;
    const u32 aoff2 = (u32)((wm * 16 + (lane & 7) + ((sel & 1) << 3)) * 72
                            + ((sel >> 1) << 3)) * 2;
    u32 boff2[4];
    #pragma unroll
    for (int nb = 0; nb < 4; nb++)
        boff2[nb] = (u32)((wn * 64 + nb * 16 + ((sel >> 1) << 3) + (lane & 7)) * 72
                          + ((sel & 1) << 3)) * 2;

    float acc2[8][4];
    #pragma unroll
    for (int ni = 0; ni < 8; ni++)
        #pragma unroll
        for (int j = 0; j < 4; j++) acc2[ni][j] = 0.f;

    const int row0 = wm * 16 + lr;
    const int gtok0 = m0 + row0, gtok1 = gtok0 + 8;

    for (int it = 0; it < 16; it++) {
        const int s = it & 1;
        const int e = e0 + (it >> 3), c = it & 7;
        if (it + 1 < 16) {
            MSTAGE(it + 1, s ^ 1);
            asm volatile("cp.async.wait_group 1;" ::: "memory");
        } else {
            asm volatile("cp.async.wait_group 0;" ::: "memory");
        }
        __syncthreads();

        const u32 w1b = smu + SW1_OFF + s * 17408u;
        const u32 ab  = smu + SA_OFF;
        float acc1[4][4];
        #pragma unroll
        for (int ni = 0; ni < 4; ni++)
            #pragma unroll
            for (int j = 0; j < 4; j++) acc1[ni][j] = 0.f;
        #pragma unroll
        for (int k16 = 0; k16 < 8; k16++) {
            u32 a[4];
            ldsm4(a, ab + aoff1 + k16 * 32);
            #pragma unroll
            for (int nb = 0; nb < 2; nb++) {
                u32 bf[4];
                ldsm4(bf, w1b + boff1[nb] + k16 * 32);
                MMA_BF16(acc1[2 * nb    ], a, bf[0], bf[1]);
                MMA_BF16(acc1[2 * nb + 1], a, bf[2], bf[3]);
            }
        }
        const float g0 = __ldg(&gates[(long)gtok0 * NE + e]);
        const float g1 = __ldg(&gates[(long)gtok1 * NE + e]);
        const u32 hbse = smu + SH_OFF + s * 9216u;
        #pragma unroll
        for (int ni = 0; ni < 4; ni++) {
            const int col = wn * 32 + ni * 8 + (lc << 1);
            const float bb0 = __ldg(&b1[(e << 9) + (c << 6) + col]);
            const float bb1 = __ldg(&b1[(e << 9) + (c << 6) + col + 1]);
            float v0 = fmaxf(acc1[ni][0] + bb0, 0.f) * g0;
            float v1 = fmaxf(acc1[ni][1] + bb1, 0.f) * g0;
            float v2 = fmaxf(acc1[ni][2] + bb0, 0.f) * g1;
            float v3 = fmaxf(acc1[ni][3] + bb1, 0.f) * g1;
            __nv_bfloat162 p0 = __floats2bfloat162_rn(v0, v1);
            __nv_bfloat162 p1 = __floats2bfloat162_rn(v2, v3);
            asm volatile("st.shared.b32 [%0], %1;" ::
                "r"(hbse + (u32)(row0 * 72 + col) * 2), "r"(*(u32*)&p0));
            asm volatile("st.shared.b32 [%0], %1;" ::
                "r"(hbse + (u32)((row0 + 8) * 72 + col) * 2), "r"(*(u32*)&p1));
        }
        __syncthreads();

        const u32 w2b = smu + SW2_OFF + s * 18432u;
        #pragma unroll
        for (int k16 = 0; k16 < 4; k16++) {
            u32 a[4];
            ldsm4(a, hbse + aoff2 + k16 * 32);
            #pragma unroll
            for (int nb = 0; nb < 4; nb++) {
                u32 bf[4];
                ldsm4(bf, w2b + boff2[nb] + k16 * 32);
                MMA_BF16(acc2[2 * nb    ], a, bf[0], bf[1]);
                MMA_BF16(acc2[2 * nb + 1], a, bf[2], bf[3]);
            }
        }
        __syncthreads();
    }
#undef MSTAGE

    float* yz = ypart + (long)blockIdx.y * NTOK * DD;
    #pragma unroll
    for (int ni = 0; ni < 8; ni++) {
        const int col = wn * 64 + ni * 8 + (lc << 1);
        *(float2*)&yz[(long)gtok0 * DD + col] = make_float2(acc2[ni][0], acc2[ni][1]);
        *(float2*)&yz[(long)gtok1 * DD + col] = make_float2(acc2[ni][2], acc2[ni][3]);
    }
}

// ============================================================================
// MMA flash attention v2: block = (b,h) x 4 query tiles (grid 64x2 = 1 wave).
// K staged permuted-dense [1024][16] -> QK B-frag is ONE conflict-free LDS.128.
// V^T token-pair-permuted -> PV V-frag is 2 LDS.64. Q frags from gmem per tile.
// ============================================================================
#define VSR 1044
#define PSR 132
#define SM_K 0
#define SM_V (1024 * 16)                  // 16384 floats
#define SM_P (SM_V + 16 * VSR)            // 33088
#define ATTN_SMEM ((SM_P + 128 * PSR) * 4)  // 199936 B

__global__ void __launch_bounds__(256) attn_mma(const float* __restrict__ qkv,
                                                float* __restrict__ oB,
                                                float* __restrict__ oS)
{
    extern __shared__ float sm[];
    const int bh = blockIdx.x, b = bh >> 3, h = bh & 7;
    const int tid = threadIdx.x, wid = tid >> 5, lane = tid & 31;
    const int lr = lane >> 2, lc = lane & 3;
    const float* qkvb = qkv + (long)b * SS * 384;
    const int qoff = h * HD, koff = DD + h * HD, voff = 2 * DD + h * HD;

    // ---- stage K permuted-dense: pos 4t+c holds orig col 4c+t (tf32)
    // ---- stage V^T with token permute: within-8 pos 2(t&3)+(t>>2) holds token t
    for (int i = tid; i < SS * 4; i += 256) {
        const int s = i >> 2, c4 = i & 3;
        float4 v = *(const float4*)(qkvb + (long)s * 384 + koff + (c4 << 2));
        float* kp = &sm[SM_K + (s << 4)];
        kp[c4]      = tf32f(v.x);
        kp[c4 + 4]  = tf32f(v.y);
        kp[c4 + 8]  = tf32f(v.z);
        kp[c4 + 12] = tf32f(v.w);
        float4 w = *(const float4*)(qkvb + (long)s * 384 + voff + (c4 << 2));
        const int colp = (s & ~7) + ((s & 3) << 1) + ((s & 7) >> 2);
        sm[SM_V + ((c4 << 2) + 0) * VSR + colp] = tf32f(w.x);
        sm[SM_V + ((c4 << 2) + 1) * VSR + colp] = tf32f(w.y);
        sm[SM_V + ((c4 << 2) + 2) * VSR + colp] = tf32f(w.z);
        sm[SM_V + ((c4 << 2) + 3) * VSR + colp] = tf32f(w.w);
    }
    __syncthreads();

    const int wq = wid << 4;
    float* Prow0 = &sm[SM_P + (wq + lr) * PSR];
    float* Prow1 = Prow0 + 8 * PSR;

    for (int j = 0; j < 4; j++) {
        const int qt = (blockIdx.y << 2) + j;

        // ---- Q fragments directly from gmem (scaled, tf32)
        const float* qp0 = qkvb + (long)(qt * 128 + wq + lr) * 384 + qoff;
        const float* qp1 = qp0 + 8 * 384;
        u32 qf[2][4];
        #pragma unroll
        for (int k8 = 0; k8 < 2; k8++) {
            const int c = (k8 << 3) + lc;
            qf[k8][0] = f2tf32(__ldg(&qp0[c])     * 0.25f);
            qf[k8][1] = f2tf32(__ldg(&qp1[c])     * 0.25f);
            qf[k8][2] = f2tf32(__ldg(&qp0[c + 4]) * 0.25f);
            qf[k8][3] = f2tf32(__ldg(&qp1[c + 4]) * 0.25f);
        }

        float oacc[2][4];
        #pragma unroll
        for (int t = 0; t < 2; t++)
            #pragma unroll
            for (int jj = 0; jj < 4; jj++) oacc[t][jj] = 0.f;
        float sl0 = 0.f, sl1 = 0.f;

        for (int kt = 0; kt < 8; kt++) {
            // ---- QK^T + exp + stage P
            #pragma unroll
            for (int ni = 0; ni < 16; ni++) {
                const int krow = kt * 128 + ni * 8 + lr;
                float4 kv = *(const float4*)&sm[SM_K + (krow << 4) + (lc << 2)];
                float sacc[4] = {0.f, 0.f, 0.f, 0.f};
                MMA_TF32(sacc, qf[0][0], qf[0][1], qf[0][2], qf[0][3],
                         __float_as_uint(kv.x), __float_as_uint(kv.y));
                MMA_TF32(sacc, qf[1][0], qf[1][1], qf[1][2], qf[1][3],
                         __float_as_uint(kv.z), __float_as_uint(kv.w));
                const float p0 = __expf(sacc[0]), p1 = __expf(sacc[1]);
                const float p2 = __expf(sacc[2]), p3 = __expf(sacc[3]);
                sl0 += p0 + p1;
                sl1 += p2 + p3;
                const int col = ni * 8 + (lc << 1);
                *(float2*)&Prow0[col] = make_float2(tf32f(p0), tf32f(p1));
                *(float2*)&Prow1[col] = make_float2(tf32f(p2), tf32f(p3));
            }
            __syncwarp();
            // ---- P . V
            #pragma unroll
            for (int k8 = 0; k8 < 16; k8++) {
                const int kc2 = (k8 << 3) + lc;
                u32 a0 = __float_as_uint(Prow0[kc2]);
                u32 a1 = __float_as_uint(Prow1[kc2]);
                u32 a2 = __float_as_uint(Prow0[kc2 + 4]);
                u32 a3 = __float_as_uint(Prow1[kc2 + 4]);
                const int kgb = kt * 128 + (k8 << 3) + (lc << 1);
                float2 va = *(const float2*)&sm[SM_V + (lr    ) * VSR + kgb];
                float2 vb = *(const float2*)&sm[SM_V + (lr + 8) * VSR + kgb];
                MMA_TF32(oacc[0], a0, a1, a2, a3,
                         __float_as_uint(va.x), __float_as_uint(va.y));
                MMA_TF32(oacc[1], a0, a1, a2, a3,
                         __float_as_uint(vb.x), __float_as_uint(vb.y));
            }
            __syncwarp();
        }

        float s0 = sl0, s1 = sl1;
        s0 += __shfl_xor_sync(0xffffffffu, s0, 1);
        s0 += __shfl_xor_sync(0xffffffffu, s0, 2);
        s1 += __shfl_xor_sync(0xffffffffu, s1, 1);
        s1 += __shfl_xor_sync(0xffffffffu, s1, 2);
        const float i0 = 1.f / s0, i1 = 1.f / s1;

        const long r0 = (long)(b * SS + qt * 128 + wq + lr);
        const long r1 = r0 + 8;
        #pragma unroll
        for (int t = 0; t < 2; t++) {
            const int col = h * HD + t * 8 + (lc << 1);
            float w0 = oacc[t][0] * i0, w1 = oacc[t][1] * i0;
            float w2 = oacc[t][2] * i1, w3 = oacc[t][3] * i1;
            float bb0 = tf32f(w0), bb1 = tf32f(w1), bb2 = tf32f(w2), bb3 = tf32f(w3);
            *(float2*)&oB[r0 * DD + col] = make_float2(bb0, bb1);
            *(float2*)&oB[r1 * DD + col] = make_float2(bb2, bb3);
            *(float2*)&oS[r0 * DD + col] = make_float2(tf32f(w0 - bb0), tf32f(w1 - bb1));
            *(float2*)&oS[r1 * DD + col] = make_float2(tf32f(w2 - bb2), tf32f(w3 - bb3));
        }
    }
}

// ============================================================================
// Norm-1 apply FUSED with gating + bf16 h emit (unchanged).
// ============================================================================
__global__ void in_apply1(const float* __restrict__ in, const float* __restrict__ part,
                          const float* __restrict__ w, const float* __restrict__ bparm,
                          const float* __restrict__ wg,
                          float* __restrict__ hout, __nv_bfloat16* __restrict__ hbf,
                          float* __restrict__ gates)
{
    const int b = blockIdx.y, chunk = blockIdx.x;
    __shared__ float sc[DD], sf[DD], wgS[DD * NE];
    wgS[threadIdx.x] = wg[threadIdx.x];
    wgS[threadIdx.x + 256] = wg[threadIdx.x + 256];
    if (threadIdx.x < DD) {
        const int d = threadIdx.x;
        float s = 0.f, q = 0.f;
        for (int c = 0; c < 16; c++) {
            const float* p = part + (long)(b * 16 + c) * 256;
            s += p[d]; q += p[DD + d];
        }
        float mean = s * (1.f / 1024.f);
        float var  = q * (1.f / 1024.f) - mean * mean;
        float inv  = rsqrtf(var + 1e-5f);
        float scale = w[d] * inv;
        sc[d] = scale;
        sf[d] = bparm[d] - mean * scale;
    }
    __syncthreads();
    const long row0 = (long)b * SS + chunk * 64;
    const int c4 = threadIdx.x & 31, rg = threadIdx.x >> 5;
    const int c0 = c4 << 2;
    for (int r = rg; r < 64; r += 8) {
        const long tok = row0 + r;
        float4 v = *(const float4*)(in + tok * DD + c0);
        float4 o;
        o.x = v.x * sc[c0 + 0] + sf[c0 + 0];
        o.y = v.y * sc[c0 + 1] + sf[c0 + 1];
        o.z = v.z * sc[c0 + 2] + sf[c0 + 2];
        o.w = v.w * sc[c0 + 3] + sf[c0 + 3];
        *(float4*)(hout + tok * DD + c0) = o;
        __nv_bfloat162 p0 = __floats2bfloat162_rn(o.x, o.y);
        __nv_bfloat162 p1 = __floats2bfloat162_rn(o.z, o.w);
        *(uint2*)(hbf + tok * DD + c0) = make_uint2(*(u32*)&p0, *(u32*)&p1);
        float l0 = o.x * wgS[(c0 + 0) * NE + 0] + o.y * wgS[(c0 + 1) * NE + 0]
                 + o.z * wgS[(c0 + 2) * NE + 0] + o.w * wgS[(c0 + 3) * NE + 0];
        float l1 = o.x * wgS[(c0 + 0) * NE + 1] + o.y * wgS[(c0 + 1) * NE + 1]
                 + o.z * wgS[(c0 + 2) * NE + 1] + o.w * wgS[(c0 + 3) * NE + 1];
        float l2 = o.x * wgS[(c0 + 0) * NE + 2] + o.y * wgS[(c0 + 1) * NE + 2]
                 + o.z * wgS[(c0 + 2) * NE + 2] + o.w * wgS[(c0 + 3) * NE + 2];
        float l3 = o.x * wgS[(c0 + 0) * NE + 3] + o.y * wgS[(c0 + 1) * NE + 3]
                 + o.z * wgS[(c0 + 2) * NE + 3] + o.w * wgS[(c0 + 3) * NE + 3];
        #pragma unroll
        for (int off = 16; off; off >>= 1) {
            l0 += __shfl_xor_sync(0xffffffffu, l0, off);
            l1 += __shfl_xor_sync(0xffffffffu, l1, off);
            l2 += __shfl_xor_sync(0xffffffffu, l2, off);
            l3 += __shfl_xor_sync(0xffffffffu, l3, off);
        }
        if (c4 == 0) {
            float lg[4] = {l0, l1, l2, l3};
            int i1 = 0; float v1 = lg[0];
            #pragma unroll
            for (int e = 1; e < 4; e++) if (lg[e] > v1) { v1 = lg[e]; i1 = e; }
            int i2 = 0; float v2 = -3e38f;
            #pragma unroll
            for (int e = 0; e < 4; e++) if (e != i1 && lg[e] > v2) { v2 = lg[e]; i2 = e; }
            float e2  = expf(v2 - v1);
            float inv = 1.f / (1.f + e2);
            float* gp = gates + tok * NE;
            #pragma unroll
            for (int e = 0; e < 4; e++)
                gp[e] = (e == i1) ? inv : ((e == i2) ? e2 * inv : 0.f);
        }
    }
}

// ============================================================================
// Norm-2 apply (unchanged)
// ============================================================================
__global__ void in_apply2(const float* __restrict__ in, const float* __restrict__ part,
                          const float* __restrict__ w, const float* __restrict__ bb,
                          float* __restrict__ out)
{
    const int b = blockIdx.y, chunk = blockIdx.x;
    __shared__ float sc[DD], sf[DD];
    if (threadIdx.x < DD) {
        const int d = threadIdx.x;
        float s = 0.f, q = 0.f;
        for (int c = 0; c < 16; c++) {
            const float* p = part + (long)((b * 16 + c) * 2) * DD;
            s += p[d]; q += p[DD + d];
        }
        float mean = s * (1.f / 1024.f);
        float var  = q * (1.f / 1024.f) - mean * mean;
        float inv  = rsqrtf(var + 1e-5f);
        float scale = w[d] * inv;
        sc[d] = scale;
        sf[d] = bb[d] - mean * scale;
    }
    __syncthreads();
    const float* base = in + ((long)b * SS + chunk * 64) * DD;
    float* ob = out + ((long)b * SS + chunk * 64) * DD;
    const int c4 = threadIdx.x & 31, rg = threadIdx.x >> 5;
    for (int r = rg; r < 64; r += 8) {
        float4 v = *(const float4*)(base + (long)r * DD + (c4 << 2));
        float4 o;
        o.x = v.x * sc[(c4 << 2) + 0] + sf[(c4 << 2) + 0];
        o.y = v.y * sc[(c4 << 2) + 1] + sf[(c4 << 2) + 1];
        o.z = v.z * sc[(c4 << 2) + 2] + sf[(c4 << 2) + 2];
        o.w = v.w * sc[(c4 << 2) + 3] + sf[(c4 << 2) + 3];
        *(float4*)(ob + (long)r * DD + (c4 << 2)) = o;
    }
}

// ============================================================================
// FUSED: pre2 = ypart[0] + ypart[1] + h + gate.b2, plus norm-2 stats (unchanged).
// ============================================================================
__global__ void add_stats(const float* __restrict__ yp, const float* __restrict__ h,
                          const float* __restrict__ gates, const float* __restrict__ b2,
                          float* __restrict__ pre2, float* __restrict__ part)
{
    const int b = blockIdx.y, chunk = blockIdx.x;
    __shared__ float b2s[NE * DD];
    b2s[threadIdx.x] = b2[threadIdx.x];
    b2s[threadIdx.x + 256] = b2[threadIdx.x + 256];
    __syncthreads();
    const long row0 = (long)b * SS + chunk * 64;
    const int c4 = threadIdx.x & 31, rg = threadIdx.x >> 5;
    const int c0 = c4 << 2;
    float4 s = make_float4(0.f, 0.f, 0.f, 0.f), q = s;
    for (int r = rg; r < 64; r += 8) {
        const long tok = row0 + r;
        const long idx = tok * DD + c0;
        const float* g = gates + tok * NE;
        const float g0 = g[0], g1 = g[1], g2 = g[2], g3 = g[3];
        float4 v = *(const float4*)(yp + idx);
        float4 v1 = *(const float4*)(yp + (long)NTOK * DD + idx);
        float4 hv = *(const float4*)(h + idx);
        float4 o;
        o.x = v.x + v1.x + hv.x
            + g0 * b2s[c0 + 0] + g1 * b2s[DD + c0 + 0] + g2 * b2s[2 * DD + c0 + 0] + g3 * b2s[3 * DD + c0 + 0];
        o.y = v.y + v1.y + hv.y
            + g0 * b2s[c0 + 1] + g1 * b2s[DD + c0 + 1] + g2 * b2s[2 * DD + c0 + 1] + g3 * b2s[3 * DD + c0 + 1];
        o.z = v.z + v1.z + hv.z
            + g0 * b2s[c0 + 2] + g1 * b2s[DD + c0 + 2] + g2 * b2s[2 * DD + c0 + 2] + g3 * b2s[3 * DD + c0 + 2];
        o.w = v.w + v1.w + hv.w
            + g0 * b2s[c0 + 3] + g1 * b2s[DD + c0 + 3] + g2 * b2s[2 * DD + c0 + 3] + g3 * b2s[3 * DD + c0 + 3];
        *(float4*)(pre2 + idx) = o;
        s.x += o.x; s.y += o.y; s.z += o.z; s.w += o.w;
        q.x += o.x * o.x; q.y += o.y * o.y; q.z += o.z * o.z; q.w += o.w * o.w;
    }
    __shared__ float4 sS[8][32], sQ[8][32];
    sS[rg][c4] = s; sQ[rg][c4] = q;
    __syncthreads();
    if (threadIdx.x < 32) {
        float4 ts = make_float4(0.f, 0.f, 0.f, 0.f), tq = ts;
        #pragma unroll
        for (int i = 0; i < 8; i++) {
            float4 a = sS[i][threadIdx.x], bq = sQ[i][threadIdx.x];
            ts.x += a.x; ts.y += a.y; ts.z += a.z; ts.w += a.w;
            tq.x += bq.x; tq.y += bq.y; tq.z += bq.z; tq.w += bq.w;
        }
        float* p = part + (long)((b * 16 + chunk) * 2) * DD;
        *(float4*)(p + (threadIdx.x << 2)) = ts;
        *(float4*)(p + DD + (threadIdx.x << 2)) = tq;
    }
}

// ============================================================================
// Launch (8 kernels)
// ============================================================================
extern "C" void kernel_launch(void* const* d_in, const int* in_sizes, int n_in,
                              void* d_out, int out_size)
{
    const float* x     = (const float*)d_in[0];
    const float* Wqkv  = (const float*)d_in[1];
    const float* bqkv  = (const float*)d_in[2];
    const float* Wo    = (const float*)d_in[3];
    const float* bo    = (const float*)d_in[4];
    const float* n1w   = (const float*)d_in[5];
    const float* n1b   = (const float*)d_in[6];
    const float* n2w   = (const float*)d_in[7];
    const float* n2b   = (const float*)d_in[8];
    const float* wg    = (const float*)d_in[9];
    const float* W1    = (const float*)d_in[10];
    const float* b1    = (const float*)d_in[11];
    const float* W2    = (const float*)d_in[12];
    const float* b2    = (const float*)d_in[13];

    float *qkv, *xB, *xS, *oB, *oS, *pre1, *h, *gates, *ypart, *pre2;
    float *wqkvB, *wqkvS, *woB, *woS, *part;
    __nv_bfloat16 *hbf, *w1bf, *w2bf;
    cudaGetSymbolAddress((void**)&qkv,   g_qkv);
    cudaGetSymbolAddress((void**)&xB,    g_xB);
    cudaGetSymbolAddress((void**)&xS,    g_xS);
    cudaGetSymbolAddress((void**)&oB,    g_oB);
    cudaGetSymbolAddress((void**)&oS,    g_oS);
    cudaGetSymbolAddress((void**)&pre1,  g_pre1);
    cudaGetSymbolAddress((void**)&h,     g_h);
    cudaGetSymbolAddress((void**)&hbf,   g_hbf);
    cudaGetSymbolAddress((void**)&gates, g_gates);
    cudaGetSymbolAddress((void**)&ypart, g_ypart);
    cudaGetSymbolAddress((void**)&pre2,  g_pre2);
    cudaGetSymbolAddress((void**)&w1bf,  g_w1bf);
    cudaGetSymbolAddress((void**)&w2bf,  g_w2bf);
    cudaGetSymbolAddress((void**)&wqkvB, g_wqkvB);
    cudaGetSymbolAddress((void**)&wqkvS, g_wqkvS);
    cudaGetSymbolAddress((void**)&woB,   g_woB);
    cudaGetSymbolAddress((void**)&woS,   g_woS);
    cudaGetSymbolAddress((void**)&part,  g_part);

    cudaFuncSetAttribute(attn_mma, cudaFuncAttributeMaxDynamicSharedMemorySize, ATTN_SMEM);
    cudaFuncSetAttribute(gemm_mma3, cudaFuncAttributeMaxDynamicSharedMemorySize, 61440);
    cudaFuncSetAttribute(moe_fused, cudaFuncAttributeMaxDynamicSharedMemorySize, MOE_SMEM);

    // 0. Merged prep
    weight_prep<<<608, 256>>>(Wqkv, Wo, W1, W2, x,
                              wqkvB, wqkvS, woB, woS, w1bf, w2bf, xB, xS);

    // 1. QKV projection (3xTF32, BK=16)
    gemm_mma3<<<dim3(3, 128), 256, 61440>>>(xB, xS, wqkvB, wqkvS, bqkv, nullptr, qkv,
                                            128, 128, 384, 8, 0, nullptr);

    // 2. MMA flash attention v2 (4 q-tiles/block, 1 wave, float4 K frags)
    attn_mma<<<dim3(64, 2), 256, ATTN_SMEM>>>(qkv, oB, oS);

    // 3. O-projection + bo + residual x ⊕ norm-1 stats
    gemm_mma3<<<dim3(1, 128), 256, 61440>>>(oB, oS, woB, woS, bo, x, pre1,
                                            128, 128, 128, 8, 128, part);

    // 4. Norm-1 apply ⊕ gating ⊕ bf16-h
    in_apply1<<<dim3(16, 8), 256>>>(pre1, part, n1w, n1b, wg, h, hbf, gates);

    // 5. FUSED MoE (expert-split)
    moe_fused<<<dim3(128, 2), 256, MOE_SMEM>>>(hbf, w1bf, w2bf, b1, gates, ypart);

    // 6. pre2 = ypart0 + ypart1 + h + gate·b2 ⊕ norm-2 stats
    add_stats<<<dim3(16, 8), 256>>>(ypart, h, gates, b2, pre2, part);

    // 7. Norm-2 apply -> output
    in_apply2<<<dim3(16, 8), 256>>>(pre2, part, n2w, n2b, (float*)d_out);
}

// round 12
// speedup vs baseline: 1.2082x; 1.0208x over previous
#include <cuda_runtime.h>
#include <cuda_bf16.h>

typedef unsigned long long ull;
typedef unsigned int u32;

// ===================== helpers =======================
__device__ __forceinline__ u32 f2tf32(float x) {
    u32 u; asm("cvt.rna.tf32.f32 %0, %1;" : "=r"(u) : "f"(x)); return u;
}
__device__ __forceinline__ float tf32f(float x) {
    return __uint_as_float(f2tf32(x));
}
#define MMA_TF32(acc, a0, a1, a2, a3, b0, b1) \
    asm volatile( \
        "mma.sync.aligned.m16n8k8.row.col.f32.tf32.tf32.f32 " \
        "{%0,%1,%2,%3}, {%4,%5,%6,%7}, {%8,%9}, {%0,%1,%2,%3};" \
        : "+f"((acc)[0]), "+f"((acc)[1]), "+f"((acc)[2]), "+f"((acc)[3]) \
        : "r"(a0), "r"(a1), "r"(a2), "r"(a3), "r"(b0), "r"(b1))

#define MMA_BF16(acc, a, b0, b1) \
    asm volatile( \
        "mma.sync.aligned.m16n8k16.row.col.f32.bf16.bf16.f32 " \
        "{%0,%1,%2,%3}, {%4,%5,%6,%7}, {%8,%9}, {%0,%1,%2,%3};" \
        : "+f"((acc)[0]), "+f"((acc)[1]), "+f"((acc)[2]), "+f"((acc)[3]) \
        : "r"((a)[0]), "r"((a)[1]), "r"((a)[2]), "r"((a)[3]), "r"(b0), "r"(b1))

__device__ __forceinline__ void ldsm4(u32* r, u32 addr) {
    asm volatile("ldmatrix.sync.aligned.m8n8.x4.shared.b16 {%0,%1,%2,%3}, [%4];"
        : "=r"(r[0]), "=r"(r[1]), "=r"(r[2]), "=r"(r[3]) : "r"(addr));
}
__device__ __forceinline__ void cpa16(u32 dst, const void* src) {
    asm volatile("cp.async.cg.shared.global [%0], [%1], 16;" :: "r"(dst), "l"(src));
}

// ===================== problem constants ====================================
#define BB    8
#define SS    1024
#define DD    128
#define NH    8
#define HD    16
#define NTOK  8192
#define HFF   512
#define NE    4

// ===================== scratch ==============================================
__device__ float         g_qkv  [NTOK * 384];
__device__ float         g_xB   [NTOK * DD];
__device__ float         g_xS   [NTOK * DD];
__device__ float         g_oB   [NTOK * DD];
__device__ float         g_oS   [NTOK * DD];
__device__ float         g_pre1 [NTOK * DD];
__device__ float         g_h    [NTOK * DD];
__device__ float         g_gates[NTOK * NE];
__device__ float         g_ypart[2 * NTOK * DD];
__device__ float         g_pre2 [NTOK * DD];
__device__ __nv_bfloat16 g_w1bf [NE * HFF * DD];
__device__ __nv_bfloat16 g_w2bf [DD * NE * HFF];
__device__ float         g_wqkvB[384 * DD];
__device__ float         g_wqkvS[384 * DD];
__device__ float         g_woB  [DD * DD];
__device__ float         g_woS  [DD * DD];
__device__ float         g_part [128 * 256];

// ============================================================================
// Merged prep: weight transposes + x tf32-split (unchanged).
// ============================================================================
__global__ void __launch_bounds__(256) weight_prep(
    const float* __restrict__ Wqkv, const float* __restrict__ Wo,
    const float* __restrict__ W1,   const float* __restrict__ W2,
    const float* __restrict__ x,
    float* __restrict__ wqkvB, float* __restrict__ wqkvS,
    float* __restrict__ woB,   float* __restrict__ woS,
    __nv_bfloat16* __restrict__ w1bf, __nv_bfloat16* __restrict__ w2bf,
    float* __restrict__ xB, float* __restrict__ xS)
{
    int bid = blockIdx.x;
    if (bid >= 576) {
        const long base = (long)(bid - 576) * 32768;
        for (int i = threadIdx.x * 4; i < 32768; i += 1024) {
            float4 v = *(const float4*)(x + base + i);
            u32 b0 = f2tf32(v.x), b1 = f2tf32(v.y), b2 = f2tf32(v.z), b3 = f2tf32(v.w);
            *(float4*)(xB + base + i) = make_float4(
                __uint_as_float(b0), __uint_as_float(b1),
                __uint_as_float(b2), __uint_as_float(b3));
            *(float4*)(xS + base + i) = make_float4(
                tf32f(v.x - __uint_as_float(b0)), tf32f(v.y - __uint_as_float(b1)),
                tf32f(v.z - __uint_as_float(b2)), tf32f(v.w - __uint_as_float(b3)));
        }
        return;
    }

    __shared__ float t[32][33];
    const float* src; int R, C, c0, r0, mode;
    float *dB = 0, *dS = 0; __nv_bfloat16* dH = 0;

    if (bid < 48) {
        src = Wqkv; R = 128; C = 384; mode = 0;
        c0 = (bid % 12) << 5; r0 = (bid / 12) << 5;
        dB = wqkvB; dS = wqkvS;
    } else if (bid < 64) {
        bid -= 48; src = Wo; R = 128; C = 128; mode = 0;
        c0 = (bid & 3) << 5; r0 = (bid >> 2) << 5;
        dB = woB; dS = woS;
    } else if (bid < 320) {
        bid -= 64;
        const int e = bid >> 6, rem = bid & 63;
        src = W1 + (long)e * 128 * 512; R = 128; C = 512; mode = 1;
        c0 = (rem & 15) << 5; r0 = (rem >> 4) << 5;
        dH = w1bf + (long)e * 512 * 128;
    } else {
        bid -= 320; src = W2; R = 2048; C = 128; mode = 1;
        c0 = (bid & 3) << 5; r0 = (bid >> 2) << 5;
        dH = w2bf;
    }

    for (int i = threadIdx.x; i < 1024; i += 256) {
        const int r = i >> 5, c = i & 31;
        t[r][c] = src[(long)(r0 + r) * C + c0 + c];
    }
    __syncthreads();
    for (int i = threadIdx.x; i < 1024; i += 256) {
        const int c = i >> 5, r = i & 31;
        const float v = t[r][c];
        const long o = (long)(c0 + c) * R + r0 + r;
        if (mode == 0) {
            const u32 big = f2tf32(v);
            dB[o] = __uint_as_float(big);
            dS[o] = __uint_as_float(f2tf32(v - __uint_as_float(big)));
        } else {
            dH[o] = __float2bfloat16(v);
        }
    }
}

// ============================================================================
// 3xTF32 mma GEMM (unchanged from round 11).
// ============================================================================
__global__ void __launch_bounds__(256) gemm_mma3(
    const float* __restrict__ Ab, const float* __restrict__ As,
    const float* __restrict__ Bb, const float* __restrict__ Bsm,
    const float* __restrict__ bias, const float* __restrict__ resid,
    float* __restrict__ C,
    int lda, int ldb, int ldc, int Kt, int ldres, float* __restrict__ part)
{
    extern __shared__ float dynsm[];
    const u32 smu = (u32)__cvta_generic_to_shared(dynsm);

    const int tid = threadIdx.x, wid = tid >> 5, lane = tid & 31;
    const int m0 = blockIdx.y << 6, n0 = blockIdx.x << 7;
    const int wm = wid >> 2, wn = wid & 3;
    const int lr = lane >> 2, lc = lane & 3;

    const float* Abase  = Ab  + (long)m0 * lda;
    const float* Asbase = As  + (long)m0 * lda;
    const float* Bbase  = Bb  + (long)n0 * ldb;
    const float* Bsbase = Bsm + (long)n0 * ldb;

    float acc[2][4][4];
    #pragma unroll
    for (int mi = 0; mi < 2; mi++)
        #pragma unroll
        for (int ni = 0; ni < 4; ni++)
            #pragma unroll
            for (int j = 0; j < 4; j++) acc[mi][ni][j] = 0.f;

#define STAGE3(KT, S) do { \
    const int _k0 = (KT) << 4; \
    const u32 _sb = smu + (S) * 30720; \
    { \
        const int row = tid >> 2, ch = (tid & 3) << 2; \
        const u32 off = (u32)(row * 20 + ch) * 4; \
        cpa16(_sb + off,        Abase  + (long)row * lda + _k0 + ch); \
        cpa16(_sb + 5120 + off, Asbase + (long)row * lda + _k0 + ch); \
    } \
    _Pragma("unroll") \
    for (int c = 0; c < 2; c++) { \
        const int idx = tid + (c << 8); \
        const int row = idx >> 2, ch = (idx & 3) << 2; \
        const u32 off = (u32)(row * 20 + ch) * 4; \
        cpa16(_sb + 10240 + off, Bbase  + (long)row * ldb + _k0 + ch); \
        cpa16(_sb + 20480 + off, Bsbase + (long)row * ldb + _k0 + ch); \
    } \
    asm volatile("cp.async.commit_group;" ::: "memory"); \
} while (0)

    STAGE3(0, 0);
    for (int kt = 0; kt < Kt; kt++) {
        const int s = kt & 1;
        if (kt + 1 < Kt) {
            STAGE3(kt + 1, (kt + 1) & 1);
            asm volatile("cp.async.wait_group 1;" ::: "memory");
        } else {
            asm volatile("cp.async.wait_group 0;" ::: "memory");
        }
        __syncthreads();
        float* AbP = dynsm + s * 7680;
        float* AmP = AbP + 1280;
        float* BsP = AbP + 2560;
        float* BmP = AbP + 5120;
        #pragma unroll
        for (int k8 = 0; k8 < 2; k8++) {
            const int kc = (k8 << 3) + lc;
            u32 af[2][4], am[2][4];
            #pragma unroll
            for (int mi = 0; mi < 2; mi++) {
                const int r = wm * 32 + mi * 16 + lr;
                af[mi][0] = __float_as_uint(AbP[(r    ) * 20 + kc    ]);
                af[mi][1] = __float_as_uint(AbP[(r + 8) * 20 + kc    ]);
                af[mi][2] = __float_as_uint(AbP[(r    ) * 20 + kc + 4]);
                af[mi][3] = __float_as_uint(AbP[(r + 8) * 20 + kc + 4]);
                am[mi][0] = __float_as_uint(AmP[(r    ) * 20 + kc    ]);
                am[mi][1] = __float_as_uint(AmP[(r + 8) * 20 + kc    ]);
                am[mi][2] = __float_as_uint(AmP[(r    ) * 20 + kc + 4]);
                am[mi][3] = __float_as_uint(AmP[(r + 8) * 20 + kc + 4]);
            }
            #pragma unroll
            for (int ni = 0; ni < 4; ni++) {
                const int nr = wn * 32 + ni * 8 + lr;
                u32 b0 = __float_as_uint(BsP[nr * 20 + kc    ]);
                u32 b1 = __float_as_uint(BsP[nr * 20 + kc + 4]);
                u32 s0 = __float_as_uint(BmP[nr * 20 + kc    ]);
                u32 s1 = __float_as_uint(BmP[nr * 20 + kc + 4]);
                #pragma unroll
                for (int mi = 0; mi < 2; mi++) {
                    MMA_TF32(acc[mi][ni], am[mi][0], am[mi][1], am[mi][2], am[mi][3], b0, b1);
                    MMA_TF32(acc[mi][ni], af[mi][0], af[mi][1], af[mi][2], af[mi][3], s0, s1);
                    MMA_TF32(acc[mi][ni], af[mi][0], af[mi][1], af[mi][2], af[mi][3], b0, b1);
                }
            }
        }
        __syncthreads();
    }
#undef STAGE3

    float s8[8], q8[8];
    #pragma unroll
    for (int i = 0; i < 8; i++) { s8[i] = 0.f; q8[i] = 0.f; }

    #pragma unroll
    for (int mi = 0; mi < 2; mi++) {
        const int r0 = m0 + wm * 32 + mi * 16 + lr;
        const int r1 = r0 + 8;
        #pragma unroll
        for (int ni = 0; ni < 4; ni++) {
            const int col = wn * 32 + ni * 8 + (lc << 1);
            float v0 = acc[mi][ni][0], v1 = acc[mi][ni][1];
            float v2 = acc[mi][ni][2], v3 = acc[mi][ni][3];
            if (bias) {
                float2 bbv = *(const float2*)&bias[n0 + col];
                v0 += bbv.x; v1 += bbv.y; v2 += bbv.x; v3 += bbv.y;
            }
            if (resid) {
                float2 ra = *(const float2*)&resid[(long)r0 * ldres + n0 + col];
                float2 rb = *(const float2*)&resid[(long)r1 * ldres + n0 + col];
                v0 += ra.x; v1 += ra.y; v2 += rb.x; v3 += rb.y;
            }
            *(float2*)&C[(long)r0 * ldc + n0 + col] = make_float2(v0, v1);
            *(float2*)&C[(long)r1 * ldc + n0 + col] = make_float2(v2, v3);
            if (part) {
                s8[ni * 2 + 0] += v0 + v2;
                s8[ni * 2 + 1] += v1 + v3;
                q8[ni * 2 + 0] += v0 * v0 + v2 * v2;
                q8[ni * 2 + 1] += v1 * v1 + v3 * v3;
            }
        }
    }

    if (part) {
        #pragma unroll
        for (int i = 0; i < 8; i++) {
            s8[i] += __shfl_xor_sync(0xffffffffu, s8[i], 4);
            s8[i] += __shfl_xor_sync(0xffffffffu, s8[i], 8);
            s8[i] += __shfl_xor_sync(0xffffffffu, s8[i], 16);
            q8[i] += __shfl_xor_sync(0xffffffffu, q8[i], 4);
            q8[i] += __shfl_xor_sync(0xffffffffu, q8[i], 8);
            q8[i] += __shfl_xor_sync(0xffffffffu, q8[i], 16);
        }
        float* ssum = dynsm;
        float* ssq  = dynsm + 256;
        __syncthreads();
        if (lr == 0) {
            #pragma unroll
            for (int i = 0; i < 8; i++) {
                const int col = wn * 32 + (i >> 1) * 8 + (lc << 1) + (i & 1);
                ssum[wm * 128 + col] = s8[i];
                ssq [wm * 128 + col] = q8[i];
            }
        }
        __syncthreads();
        if (tid < 128) {
            part[blockIdx.y * 256 + tid]       = ssum[tid] + ssum[128 + tid];
            part[blockIdx.y * 256 + 128 + tid] = ssq[tid]  + ssq[128 + tid];
        }
    }
}

// ============================================================================
// FUSED MoE + norm-1 apply + gating. Block (m, z): 64 tokens, experts {2z,2z+1}.
// Phase 0: h = norm1(pre1) (stats from part), gating, bf16 h -> smem A tile.
// Then per 64-col hid chunk: GEMM1 -> bf16 smem -> GEMM2 accumulate.
// z==0 blocks also emit h and gates to gmem for add_stats.
// Overlay (scale/shift/wg/gates tables) lives in W1 stage-1 buffer (unused
// until iteration 0 issues MSTAGE(1,1)); gates pulled to registers first.
// ============================================================================
#define SA_OFF  0u
#define SW1_OFF 17408u
#define SW2_OFF 52224u
#define SH_OFF  89088u
#define MOE_SMEM 107520

__global__ void __launch_bounds__(256) moe_fused(
    const float* __restrict__ pre1, const float* __restrict__ part,
    const float* __restrict__ n1w, const float* __restrict__ n1b,
    const float* __restrict__ wg,
    const __nv_bfloat16* __restrict__ w1bf, const __nv_bfloat16* __restrict__ w2bf,
    const float* __restrict__ b1,
    float* __restrict__ hout, float* __restrict__ gatesOut,
    float* __restrict__ ypart)
{
    extern __shared__ char msm[];
    const u32 smu = (u32)__cvta_generic_to_shared(msm);

    const int tid = threadIdx.x, wid = tid >> 5, lane = tid & 31;
    const int lr = lane >> 2, lc = lane & 3, sel = lane >> 3;
    const int wm = wid >> 1, wn = wid & 1;
    const int m0 = blockIdx.x << 6;
    const int e0 = blockIdx.y << 1;
    const int b  = m0 >> 10;

#define MSTAGE(IT, S) do { \
    const int _e = e0 + ((IT) >> 3), _c = (IT) & 7; \
    const __nv_bfloat16* _w1 = w1bf + (long)((_e << 9) + (_c << 6)) * 128; \
    const __nv_bfloat16* _w2 = w2bf + (_e << 9) + (_c << 6); \
    _Pragma("unroll") \
    for (int j = 0; j < 4; j++) { \
        const int idx = tid + (j << 8); \
        const int r1 = idx >> 4, ch1 = (idx & 15) << 3; \
        cpa16(smu + SW1_OFF + (S) * 17408u + (u32)(r1 * 136 + ch1) * 2, \
              _w1 + (long)r1 * 128 + ch1); \
        const int r2 = idx >> 3, ch2 = (idx & 7) << 3; \
        cpa16(smu + SW2_OFF + (S) * 18432u + (u32)(r2 * 72 + ch2) * 2, \
              _w2 + (long)r2 * 2048 + ch2); \
    } \
    asm volatile("cp.async.commit_group;" ::: "memory"); \
} while (0)

    MSTAGE(0, 0);    // weight chunk 0 in flight during phase 0

    // ---- phase 0: norm-1 apply + gating (overlay in W1 stage-1 buffer)
    float* ovl    = (float*)(msm + SW1_OFF + 17408u);
    float* scA    = ovl;           // 128
    float* sfA    = ovl + 128;     // 128
    float* wgS    = ovl + 256;     // 512
    float* gatesS = ovl + 768;     // 64*4
    wgS[tid] = wg[tid];
    wgS[tid + 256] = wg[tid + 256];
    if (tid < DD) {
        const int d = tid;
        float s = 0.f, q = 0.f;
        for (int c = 0; c < 16; c++) {
            const float* p = part + (long)(b * 16 + c) * 256;
            s += p[d]; q += p[DD + d];
        }
        float mean = s * (1.f / 1024.f);
        float var  = q * (1.f / 1024.f) - mean * mean;
        float inv  = rsqrtf(var + 1e-5f);
        float scale = n1w[d] * inv;
        scA[d] = scale;
        sfA[d] = n1b[d] - mean * scale;
    }
    __syncthreads();

    {
        const int c4 = tid & 31, rg = tid >> 5;
        const int c0 = c4 << 2;
        for (int r = rg; r < 64; r += 8) {
            const long tok = m0 + r;
            float4 v = *(const float4*)(pre1 + tok * DD + c0);
            float4 o;
            o.x = v.x * scA[c0 + 0] + sfA[c0 + 0];
            o.y = v.y * scA[c0 + 1] + sfA[c0 + 1];
            o.z = v.z * scA[c0 + 2] + sfA[c0 + 2];
            o.w = v.w * scA[c0 + 3] + sfA[c0 + 3];
            if (e0 == 0) *(float4*)(hout + tok * DD + c0) = o;
            __nv_bfloat162 p0 = __floats2bfloat162_rn(o.x, o.y);
            __nv_bfloat162 p1 = __floats2bfloat162_rn(o.z, o.w);
            asm volatile("st.shared.v2.b32 [%0], {%1, %2};" ::
                "r"(smu + SA_OFF + (u32)(r * 136 + c0) * 2),
                "r"(*(u32*)&p0), "r"(*(u32*)&p1));
            float l0 = o.x * wgS[(c0 + 0) * NE + 0] + o.y * wgS[(c0 + 1) * NE + 0]
                     + o.z * wgS[(c0 + 2) * NE + 0] + o.w * wgS[(c0 + 3) * NE + 0];
            float l1 = o.x * wgS[(c0 + 0) * NE + 1] + o.y * wgS[(c0 + 1) * NE + 1]
                     + o.z * wgS[(c0 + 2) * NE + 1] + o.w * wgS[(c0 + 3) * NE + 1];
            float l2 = o.x * wgS[(c0 + 0) * NE + 2] + o.y * wgS[(c0 + 1) * NE + 2]
                     + o.z * wgS[(c0 + 2) * NE + 2] + o.w * wgS[(c0 + 3) * NE + 2];
            float l3 = o.x * wgS[(c0 + 0) * NE + 3] + o.y * wgS[(c0 + 1) * NE + 3]
                     + o.z * wgS[(c0 + 2) * NE + 3] + o.w * wgS[(c0 + 3) * NE + 3];
            #pragma unroll
            for (int off = 16; off; off >>= 1) {
                l0 += __shfl_xor_sync(0xffffffffu, l0, off);
                l1 += __shfl_xor_sync(0xffffffffu, l1, off);
                l2 += __shfl_xor_sync(0xffffffffu, l2, off);
                l3 += __shfl_xor_sync(0xffffffffu, l3, off);
            }
            if (c4 == 0) {
                float lg[4] = {l0, l1, l2, l3};
                int i1 = 0; float v1 = lg[0];
                #pragma unroll
                for (int e = 1; e < 4; e++) if (lg[e] > v1) { v1 = lg[e]; i1 = e; }
                int i2 = 0; float v2 = -3e38f;
                #pragma unroll
                for (int e = 0; e < 4; e++) if (e != i1 && lg[e] > v2) { v2 = lg[e]; i2 = e; }
                float e2  = expf(v2 - v1);
                float inv = 1.f / (1.f + e2);
                #pragma unroll
                for (int e = 0; e < 4; e++) {
                    const float gv = (e == i1) ? inv : ((e == i2) ? e2 * inv : 0.f);
                    gatesS[r * NE + e] = gv;
                    if (e0 == 0) gatesOut[tok * NE + e] = gv;
                }
            }
        }
    }
    __syncthreads();

    const int row0 = wm * 16 + lr;
    const float g00 = gatesS[(row0    ) * NE + e0];
    const float g01 = gatesS[(row0    ) * NE + e0 + 1];
    const float g10 = gatesS[(row0 + 8) * NE + e0];
    const float g11 = gatesS[(row0 + 8) * NE + e0 + 1];
    __syncthreads();      // all gate reads done before MSTAGE(1,1) overwrites overlay

    // ---- ldmatrix offsets
    const u32 aoff1 = (u32)((wm * 16 + (lane & 7) + ((sel & 1) << 3)) * 136
                            + ((sel >> 1) << 3)) * 2;
    u32 boff1[2];
    #pragma unroll
    for (int nb = 0; nb < 2; nb++)
        boff1[nb] = (u32)((wn * 32 + nb * 16 + ((sel >> 1) << 3) + (lane & 7)) * 136
                          + ((sel & 1) << 3)) * 2;
    const u32 aoff2 = (u32)((wm * 16 + (lane & 7) + ((sel & 1) << 3)) * 72
                            + ((sel >> 1) << 3)) * 2;
    u32 boff2[4];
    #pragma unroll
    for (int nb = 0; nb < 4; nb++)
        boff2[nb] = (u32)((wn * 64 + nb * 16 + ((sel >> 1) << 3) + (lane & 7)) * 72
                          + ((sel & 1) << 3)) * 2;

    float acc2[8][4];
    #pragma unroll
    for (int ni = 0; ni < 8; ni++)
        #pragma unroll
        for (int j = 0; j < 4; j++) acc2[ni][j] = 0.f;

    const int gtok0 = m0 + row0, gtok1 = gtok0 + 8;

    for (int it = 0; it < 16; it++) {
        const int s = it & 1;
        const int e = e0 + (it >> 3), c = it & 7;
        if (it + 1 < 16) {
            MSTAGE(it + 1, s ^ 1);
            asm volatile("cp.async.wait_group 1;" ::: "memory");
        } else {
            asm volatile("cp.async.wait_group 0;" ::: "memory");
        }
        __syncthreads();

        // ---- GEMM1
        const u32 w1b = smu + SW1_OFF + s * 17408u;
        const u32 ab  = smu + SA_OFF;
        float acc1[4][4];
        #pragma unroll
        for (int ni = 0; ni < 4; ni++)
            #pragma unroll
            for (int j = 0; j < 4; j++) acc1[ni][j] = 0.f;
        #pragma unroll
        for (int k16 = 0; k16 < 8; k16++) {
            u32 a[4];
            ldsm4(a, ab + aoff1 + k16 * 32);
            #pragma unroll
            for (int nb = 0; nb < 2; nb++) {
                u32 bf[4];
                ldsm4(bf, w1b + boff1[nb] + k16 * 32);
                MMA_BF16(acc1[2 * nb    ], a, bf[0], bf[1]);
                MMA_BF16(acc1[2 * nb + 1], a, bf[2], bf[3]);
            }
        }
        // ---- bias + relu + gate -> bf16 smem (H rows shared within warp pair)
        const float g0 = (it >> 3) ? g01 : g00;
        const float g1 = (it >> 3) ? g11 : g10;
        const u32 hbse = smu + SH_OFF + s * 9216u;
        #pragma unroll
        for (int ni = 0; ni < 4; ni++) {
            const int col = wn * 32 + ni * 8 + (lc << 1);
            const float bb0 = __ldg(&b1[(e << 9) + (c << 6) + col]);
            const float bb1 = __ldg(&b1[(e << 9) + (c << 6) + col + 1]);
            float v0 = fmaxf(acc1[ni][0] + bb0, 0.f) * g0;
            float v1 = fmaxf(acc1[ni][1] + bb1, 0.f) * g0;
            float v2 = fmaxf(acc1[ni][2] + bb0, 0.f) * g1;
            float v3 = fmaxf(acc1[ni][3] + bb1, 0.f) * g1;
            __nv_bfloat162 p0 = __floats2bfloat162_rn(v0, v1);
            __nv_bfloat162 p1 = __floats2bfloat162_rn(v2, v3);
            asm volatile("st.shared.b32 [%0], %1;" ::
                "r"(hbse + (u32)(row0 * 72 + col) * 2), "r"(*(u32*)&p0));
            asm volatile("st.shared.b32 [%0], %1;" ::
                "r"(hbse + (u32)((row0 + 8) * 72 + col) * 2), "r"(*(u32*)&p1));
        }
        // H row-block wm*16..+15 is produced/consumed only by warps (wm,0),(wm,1)
        asm volatile("bar.sync %0, 64;" :: "r"(wm + 1) : "memory");

        // ---- GEMM2
        const u32 w2b = smu + SW2_OFF + s * 18432u;
        #pragma unroll
        for (int k16 = 0; k16 < 4; k16++) {
            u32 a[4];
            ldsm4(a, hbse + aoff2 + k16 * 32);
            #pragma unroll
            for (int nb = 0; nb < 4; nb++) {
                u32 bf[4];
                ldsm4(bf, w2b + boff2[nb] + k16 * 32);
                MMA_BF16(acc2[2 * nb    ], a, bf[0], bf[1]);
                MMA_BF16(acc2[2 * nb + 1], a, bf[2], bf[3]);
            }
        }
        __syncthreads();
    }
#undef MSTAGE

    float* yz = ypart + (long)blockIdx.y * NTOK * DD;
    #pragma unroll
    for (int ni = 0; ni < 8; ni++) {
        const int col = wn * 64 + ni * 8 + (lc << 1);
        *(float2*)&yz[(long)gtok0 * DD + col] = make_float2(acc2[ni][0], acc2[ni][1]);
        *(float2*)&yz[(long)gtok1 * DD + col] = make_float2(acc2[ni][2], acc2[ni][3]);
    }
}

// ============================================================================
// MMA flash attention v2 (round 11) — P staged raw fp32 (HW truncates to tf32).
// ============================================================================
#define VSR 1044
#define PSR 132
#define SM_K 0
#define SM_V (1024 * 16)
#define SM_P (SM_V + 16 * VSR)
#define ATTN_SMEM ((SM_P + 128 * PSR) * 4)

__global__ void __launch_bounds__(256) attn_mma(const float* __restrict__ qkv,
                                                float* __restrict__ oB,
                                                float* __restrict__ oS)
{
    extern __shared__ float sm[];
    const int bh = blockIdx.x, b = bh >> 3, h = bh & 7;
    const int tid = threadIdx.x, wid = tid >> 5, lane = tid & 31;
    const int lr = lane >> 2, lc = lane & 3;
    const float* qkvb = qkv + (long)b * SS * 384;
    const int qoff = h * HD, koff = DD + h * HD, voff = 2 * DD + h * HD;

    for (int i = tid; i < SS * 4; i += 256) {
        const int s = i >> 2, c4 = i & 3;
        float4 v = *(const float4*)(qkvb + (long)s * 384 + koff + (c4 << 2));
        float* kp = &sm[SM_K + (s << 4)];
        kp[c4]      = tf32f(v.x);
        kp[c4 + 4]  = tf32f(v.y);
        kp[c4 + 8]  = tf32f(v.z);
        kp[c4 + 12] = tf32f(v.w);
        float4 w = *(const float4*)(qkvb + (long)s * 384 + voff + (c4 << 2));
        const int colp = (s & ~7) + ((s & 3) << 1) + ((s & 7) >> 2);
        sm[SM_V + ((c4 << 2) + 0) * VSR + colp] = tf32f(w.x);
        sm[SM_V + ((c4 << 2) + 1) * VSR + colp] = tf32f(w.y);
        sm[SM_V + ((c4 << 2) + 2) * VSR + colp] = tf32f(w.z);
        sm[SM_V + ((c4 << 2) + 3) * VSR + colp] = tf32f(w.w);
    }
    __syncthreads();

    const int wq = wid << 4;
    float* Prow0 = &sm[SM_P + (wq + lr) * PSR];
    float* Prow1 = Prow0 + 8 * PSR;

    for (int j = 0; j < 4; j++) {
        const int qt = (blockIdx.y << 2) + j;

        const float* qp0 = qkvb + (long)(qt * 128 + wq + lr) * 384 + qoff;
        const float* qp1 = qp0 + 8 * 384;
        u32 qf[2][4];
        #pragma unroll
        for (int k8 = 0; k8 < 2; k8++) {
            const int c = (k8 << 3) + lc;
            qf[k8][0] = f2tf32(__ldg(&qp0[c])     * 0.25f);
            qf[k8][1] = f2tf32(__ldg(&qp1[c])     * 0.25f);
            qf[k8][2] = f2tf32(__ldg(&qp0[c + 4]) * 0.25f);
            qf[k8][3] = f2tf32(__ldg(&qp1[c + 4]) * 0.25f);
        }

        float oacc[2][4];
        #pragma unroll
        for (int t = 0; t < 2; t++)
            #pragma unroll
            for (int jj = 0; jj < 4; jj++) oacc[t][jj] = 0.f;
        float sl0 = 0.f, sl1 = 0.f;

        for (int kt = 0; kt < 8; kt++) {
            #pragma unroll
            for (int ni = 0; ni < 16; ni++) {
                const int krow = kt * 128 + ni * 8 + lr;
                float4 kv = *(const float4*)&sm[SM_K + (krow << 4) + (lc << 2)];
                float sacc[4] = {0.f, 0.f, 0.f, 0.f};
                MMA_TF32(sacc, qf[0][0], qf[0][1], qf[0][2], qf[0][3],
                         __float_as_uint(kv.x), __float_as_uint(kv.y));
                MMA_TF32(sacc, qf[1][0], qf[1][1], qf[1][2], qf[1][3],
                         __float_as_uint(kv.z), __float_as_uint(kv.w));
                const float p0 = __expf(sacc[0]), p1 = __expf(sacc[1]);
                const float p2 = __expf(sacc[2]), p3 = __expf(sacc[3]);
                sl0 += p0 + p1;
                sl1 += p2 + p3;
                const int col = ni * 8 + (lc << 1);
                *(float2*)&Prow0[col] = make_float2(p0, p1);
                *(float2*)&Prow1[col] = make_float2(p2, p3);
            }
            __syncwarp();
            #pragma unroll
            for (int k8 = 0; k8 < 16; k8++) {
                const int kc2 = (k8 << 3) + lc;
                u32 a0 = __float_as_uint(Prow0[kc2]);
                u32 a1 = __float_as_uint(Prow1[kc2]);
                u32 a2 = __float_as_uint(Prow0[kc2 + 4]);
                u32 a3 = __float_as_uint(Prow1[kc2 + 4]);
                const int kgb = kt * 128 + (k8 << 3) + (lc << 1);
                float2 va = *(const float2*)&sm[SM_V + (lr    ) * VSR + kgb];
                float2 vb = *(const float2*)&sm[SM_V + (lr + 8) * VSR + kgb];
                MMA_TF32(oacc[0], a0, a1, a2, a3,
                         __float_as_uint(va.x), __float_as_uint(va.y));
                MMA_TF32(oacc[1], a0, a1, a2, a3,
                         __float_as_uint(vb.x), __float_as_uint(vb.y));
            }
            __syncwarp();
        }

        float s0 = sl0, s1 = sl1;
        s0 += __shfl_xor_sync(0xffffffffu, s0, 1);
        s0 += __shfl_xor_sync(0xffffffffu, s0, 2);
        s1 += __shfl_xor_sync(0xffffffffu, s1, 1);
        s1 += __shfl_xor_sync(0xffffffffu, s1, 2);
        const float i0 = 1.f / s0, i1 = 1.f / s1;

        const long r0 = (long)(b * SS + qt * 128 + wq + lr);
        const long r1 = r0 + 8;
        #pragma unroll
        for (int t = 0; t < 2; t++) {
            const int col = h * HD + t * 8 + (lc << 1);
            float w0 = oacc[t][0] * i0, w1 = oacc[t][1] * i0;
            float w2 = oacc[t][2] * i1, w3 = oacc[t][3] * i1;
            float bb0 = tf32f(w0), bb1 = tf32f(w1), bb2 = tf32f(w2), bb3 = tf32f(w3);
            *(float2*)&oB[r0 * DD + col] = make_float2(bb0, bb1);
            *(float2*)&oB[r1 * DD + col] = make_float2(bb2, bb3);
            *(float2*)&oS[r0 * DD + col] = make_float2(tf32f(w0 - bb0), tf32f(w1 - bb1));
            *(float2*)&oS[r1 * DD + col] = make_float2(tf32f(w2 - bb2), tf32f(w3 - bb3));
        }
    }
}

// ============================================================================
// Norm-2 apply (unchanged)
// ============================================================================
__global__ void in_apply2(const float* __restrict__ in, const float* __restrict__ part,
                          const float* __restrict__ w, const float* __restrict__ bb,
                          float* __restrict__ out)
{
    const int b = blockIdx.y, chunk = blockIdx.x;
    __shared__ float sc[DD], sf[DD];
    if (threadIdx.x < DD) {
        const int d = threadIdx.x;
        float s = 0.f, q = 0.f;
        for (int c = 0; c < 16; c++) {
            const float* p = part + (long)((b * 16 + c) * 2) * DD;
            s += p[d]; q += p[DD + d];
        }
        float mean = s * (1.f / 1024.f);
        float var  = q * (1.f / 1024.f) - mean * mean;
        float inv  = rsqrtf(var + 1e-5f);
        float scale = w[d] * inv;
        sc[d] = scale;
        sf[d] = bb[d] - mean * scale;
    }
    __syncthreads();
    const float* base = in + ((long)b * SS + chunk * 64) * DD;
    float* ob = out + ((long)b * SS + chunk * 64) * DD;
    const int c4 = threadIdx.x & 31, rg = threadIdx.x >> 5;
    for (int r = rg; r < 64; r += 8) {
        float4 v = *(const float4*)(base + (long)r * DD + (c4 << 2));
        float4 o;
        o.x = v.x * sc[(c4 << 2) + 0] + sf[(c4 << 2) + 0];
        o.y = v.y * sc[(c4 << 2) + 1] + sf[(c4 << 2) + 1];
        o.z = v.z * sc[(c4 << 2) + 2] + sf[(c4 << 2) + 2];
        o.w = v.w * sc[(c4 << 2) + 3] + sf[(c4 << 2) + 3];
        *(float4*)(ob + (long)r * DD + (c4 << 2)) = o;
    }
}

// ============================================================================
// FUSED: pre2 = ypart[0] + ypart[1] + h + gate.b2, plus norm-2 stats (unchanged).
// ============================================================================
__global__ void add_stats(const float* __restrict__ yp, const float* __restrict__ h,
                          const float* __restrict__ gates, const float* __restrict__ b2,
                          float* __restrict__ pre2, float* __restrict__ part)
{
    const int b = blockIdx.y, chunk = blockIdx.x;
    __shared__ float b2s[NE * DD];
    b2s[threadIdx.x] = b2[threadIdx.x];
    b2s[threadIdx.x + 256] = b2[threadIdx.x + 256];
    __syncthreads();
    const long row0 = (long)b * SS + chunk * 64;
    const int c4 = threadIdx.x & 31, rg = threadIdx.x >> 5;
    const int c0 = c4 << 2;
    float4 s = make_float4(0.f, 0.f, 0.f, 0.f), q = s;
    for (int r = rg; r < 64; r += 8) {
        const long tok = row0 + r;
        const long idx = tok * DD + c0;
        const float* g = gates + tok * NE;
        const float g0 = g[0], g1 = g[1], g2 = g[2], g3 = g[3];
        float4 v = *(const float4*)(yp + idx);
        float4 v1 = *(const float4*)(yp + (long)NTOK * DD + idx);
        float4 hv = *(const float4*)(h + idx);
        float4 o;
        o.x = v.x + v1.x + hv.x
            + g0 * b2s[c0 + 0] + g1 * b2s[DD + c0 + 0] + g2 * b2s[2 * DD + c0 + 0] + g3 * b2s[3 * DD + c0 + 0];
        o.y = v.y + v1.y + hv.y
            + g0 * b2s[c0 + 1] + g1 * b2s[DD + c0 + 1] + g2 * b2s[2 * DD + c0 + 1] + g3 * b2s[3 * DD + c0 + 1];
        o.z = v.z + v1.z + hv.z
            + g0 * b2s[c0 + 2] + g1 * b2s[DD + c0 + 2] + g2 * b2s[2 * DD + c0 + 2] + g3 * b2s[3 * DD + c0 + 2];
        o.w = v.w + v1.w + hv.w
            + g0 * b2s[c0 + 3] + g1 * b2s[DD + c0 + 3] + g2 * b2s[2 * DD + c0 + 3] + g3 * b2s[3 * DD + c0 + 3];
        *(float4*)(pre2 + idx) = o;
        s.x += o.x; s.y += o.y; s.z += o.z; s.w += o.w;
        q.x += o.x * o.x; q.y += o.y * o.y; q.z += o.z * o.z; q.w += o.w * o.w;
    }
    __shared__ float4 sS[8][32], sQ[8][32];
    sS[rg][c4] = s; sQ[rg][c4] = q;
    __syncthreads();
    if (threadIdx.x < 32) {
        float4 ts = make_float4(0.f, 0.f, 0.f, 0.f), tq = ts;
        #pragma unroll
        for (int i = 0; i < 8; i++) {
            float4 a = sS[i][threadIdx.x], bq = sQ[i][threadIdx.x];
            ts.x += a.x; ts.y += a.y; ts.z += a.z; ts.w += a.w;
            tq.x += bq.x; tq.y += bq.y; tq.z += bq.z; tq.w += bq.w;
        }
        float* p = part + (long)((b * 16 + chunk) * 2) * DD;
        *(float4*)(p + (threadIdx.x << 2)) = ts;
        *(float4*)(p + DD + (threadIdx.x << 2)) = tq;
    }
}

// ============================================================================
// Launch (7 kernels)
// ============================================================================
extern "C" void kernel_launch(void* const* d_in, const int* in_sizes, int n_in,
                              void* d_out, int out_size)
{
    const float* x     = (const float*)d_in[0];
    const float* Wqkv  = (const float*)d_in[1];
    const float* bqkv  = (const float*)d_in[2];
    const float* Wo    = (const float*)d_in[3];
    const float* bo    = (const float*)d_in[4];
    const float* n1w   = (const float*)d_in[5];
    const float* n1b   = (const float*)d_in[6];
    const float* n2w   = (const float*)d_in[7];
    const float* n2b   = (const float*)d_in[8];
    const float* wg    = (const float*)d_in[9];
    const float* W1    = (const float*)d_in[10];
    const float* b1    = (const float*)d_in[11];
    const float* W2    = (const float*)d_in[12];
    const float* b2    = (const float*)d_in[13];

    float *qkv, *xB, *xS, *oB, *oS, *pre1, *h, *gates, *ypart, *pre2;
    float *wqkvB, *wqkvS, *woB, *woS, *part;
    __nv_bfloat16 *w1bf, *w2bf;
    cudaGetSymbolAddress((void**)&qkv,   g_qkv);
    cudaGetSymbolAddress((void**)&xB,    g_xB);
    cudaGetSymbolAddress((void**)&xS,    g_xS);
    cudaGetSymbolAddress((void**)&oB,    g_oB);
    cudaGetSymbolAddress((void**)&oS,    g_oS);
    cudaGetSymbolAddress((void**)&pre1,  g_pre1);
    cudaGetSymbolAddress((void**)&h,     g_h);
    cudaGetSymbolAddress((void**)&gates, g_gates);
    cudaGetSymbolAddress((void**)&ypart, g_ypart);
    cudaGetSymbolAddress((void**)&pre2,  g_pre2);
    cudaGetSymbolAddress((void**)&w1bf,  g_w1bf);
    cudaGetSymbolAddress((void**)&w2bf,  g_w2bf);
    cudaGetSymbolAddress((void**)&wqkvB, g_wqkvB);
    cudaGetSymbolAddress((void**)&wqkvS, g_wqkvS);
    cudaGetSymbolAddress((void**)&woB,   g_woB);
    cudaGetSymbolAddress((void**)&woS,   g_woS);
    cudaGetSymbolAddress((void**)&part,  g_part);

    cudaFuncSetAttribute(attn_mma, cudaFuncAttributeMaxDynamicSharedMemorySize, ATTN_SMEM);
    cudaFuncSetAttribute(gemm_mma3, cudaFuncAttributeMaxDynamicSharedMemorySize, 61440);
    cudaFuncSetAttribute(moe_fused, cudaFuncAttributeMaxDynamicSharedMemorySize, MOE_SMEM);

    // 0. Merged prep
    weight_prep<<<608, 256>>>(Wqkv, Wo, W1, W2, x,
                              wqkvB, wqkvS, woB, woS, w1bf, w2bf, xB, xS);

    // 1. QKV projection (3xTF32, BK=16)
    gemm_mma3<<<dim3(3, 128), 256, 61440>>>(xB, xS, wqkvB, wqkvS, bqkv, nullptr, qkv,
                                            128, 128, 384, 8, 0, nullptr);

    // 2. MMA flash attention
    attn_mma<<<dim3(64, 2), 256, ATTN_SMEM>>>(qkv, oB, oS);

    // 3. O-projection + bo + residual x ⊕ norm-1 stats
    gemm_mma3<<<dim3(1, 128), 256, 61440>>>(oB, oS, woB, woS, bo, x, pre1,
                                            128, 128, 128, 8, 128, part);

    // 4. FUSED MoE ⊕ norm-1 apply ⊕ gating (expert-split)
    moe_fused<<<dim3(128, 2), 256, MOE_SMEM>>>(pre1, part, n1w, n1b, wg,
                                               w1bf, w2bf, b1, h, gates, ypart);

    // 5. pre2 = ypart0 + ypart1 + h + gate·b2 ⊕ norm-2 stats
    add_stats<<<dim3(16, 8), 256>>>(ypart, h, gates, b2, pre2, part);

    // 6. Norm-2 apply -> output
    in_apply2<<<dim3(16, 8), 256>>>(pre2, part, n2w, n2b, (float*)d_out);
}

// round 13
// speedup vs baseline: 1.2883x; 1.0663x over previous
#include <cuda_runtime.h>
#include <cuda_bf16.h>

typedef unsigned long long ull;
typedef unsigned int u32;

// ===================== helpers =======================
__device__ __forceinline__ u32 f2tf32(float x) {
    u32 u; asm("cvt.rna.tf32.f32 %0, %1;" : "=r"(u) : "f"(x)); return u;
}
__device__ __forceinline__ float tf32f(float x) {
    return __uint_as_float(f2tf32(x));
}
#define MMA_TF32(acc, a0, a1, a2, a3, b0, b1) \
    asm volatile( \
        "mma.sync.aligned.m16n8k8.row.col.f32.tf32.tf32.f32 " \
        "{%0,%1,%2,%3}, {%4,%5,%6,%7}, {%8,%9}, {%0,%1,%2,%3};" \
        : "+f"((acc)[0]), "+f"((acc)[1]), "+f"((acc)[2]), "+f"((acc)[3]) \
        : "r"(a0), "r"(a1), "r"(a2), "r"(a3), "r"(b0), "r"(b1))

#define MMA_BF16(acc, a, b0, b1) \
    asm volatile( \
        "mma.sync.aligned.m16n8k16.row.col.f32.bf16.bf16.f32 " \
        "{%0,%1,%2,%3}, {%4,%5,%6,%7}, {%8,%9}, {%0,%1,%2,%3};" \
        : "+f"((acc)[0]), "+f"((acc)[1]), "+f"((acc)[2]), "+f"((acc)[3]) \
        : "r"((a)[0]), "r"((a)[1]), "r"((a)[2]), "r"((a)[3]), "r"(b0), "r"(b1))

__device__ __forceinline__ void ldsm4(u32* r, u32 addr) {
    asm volatile("ldmatrix.sync.aligned.m8n8.x4.shared.b16 {%0,%1,%2,%3}, [%4];"
        : "=r"(r[0]), "=r"(r[1]), "=r"(r[2]), "=r"(r[3]) : "r"(addr));
}
__device__ __forceinline__ void cpa16(u32 dst, const void* src) {
    asm volatile("cp.async.cg.shared.global [%0], [%1], 16;" :: "r"(dst), "l"(src));
}

// ===================== problem constants ====================================
#define BB    8
#define SS    1024
#define DD    128
#define NH    8
#define HD    16
#define NTOK  8192
#define HFF   512
#define NE    4

// ===================== scratch ==============================================
__device__ float         g_qkv  [NTOK * 384];
__device__ float         g_xB   [NTOK * DD];
__device__ float         g_oB   [NTOK * DD];
__device__ float         g_oS   [NTOK * DD];
__device__ float         g_pre1 [NTOK * DD];
__device__ float         g_h    [NTOK * DD];
__device__ float         g_gates[NTOK * NE];
__device__ float         g_ypart[2 * NTOK * DD];
__device__ float         g_pre2 [NTOK * DD];
__device__ __nv_bfloat16 g_w1bf [NE * HFF * DD];
__device__ __nv_bfloat16 g_w2bf [DD * NE * HFF];
__device__ float         g_wqkvB[384 * DD];
__device__ float         g_woB  [DD * DD];
__device__ float         g_woS  [DD * DD];
__device__ float         g_part [128 * 256];

// ============================================================================
// Merged prep: weight transposes + x tf32-round.
//  seg0 (48):  Wqkv -> wqkvB (tf32 big only; QKV gemm is 1xTF32)
//  seg1 (16):  Wo   -> woB/woS (tf32 big+small; O-proj stays 3xTF32)
//  seg2 (256): W1   -> w1bf
//  seg3 (256): W2   -> w2bf
//  seg4 (32):  x    -> xB (tf32 big only)
// ============================================================================
__global__ void __launch_bounds__(256) weight_prep(
    const float* __restrict__ Wqkv, const float* __restrict__ Wo,
    const float* __restrict__ W1,   const float* __restrict__ W2,
    const float* __restrict__ x,
    float* __restrict__ wqkvB,
    float* __restrict__ woB,   float* __restrict__ woS,
    __nv_bfloat16* __restrict__ w1bf, __nv_bfloat16* __restrict__ w2bf,
    float* __restrict__ xB)
{
    int bid = blockIdx.x;
    if (bid >= 576) {
        const long base = (long)(bid - 576) * 32768;
        for (int i = threadIdx.x * 4; i < 32768; i += 1024) {
            float4 v = *(const float4*)(x + base + i);
            *(float4*)(xB + base + i) = make_float4(tf32f(v.x), tf32f(v.y),
                                                    tf32f(v.z), tf32f(v.w));
        }
        return;
    }

    __shared__ float t[32][33];
    const float* src; int R, C, c0, r0, mode;   // 0: tf32 b+s, 1: bf16, 3: tf32 big
    float *dB = 0, *dS = 0; __nv_bfloat16* dH = 0;

    if (bid < 48) {
        src = Wqkv; R = 128; C = 384; mode = 3;
        c0 = (bid % 12) << 5; r0 = (bid / 12) << 5;
        dB = wqkvB;
    } else if (bid < 64) {
        bid -= 48; src = Wo; R = 128; C = 128; mode = 0;
        c0 = (bid & 3) << 5; r0 = (bid >> 2) << 5;
        dB = woB; dS = woS;
    } else if (bid < 320) {
        bid -= 64;
        const int e = bid >> 6, rem = bid & 63;
        src = W1 + (long)e * 128 * 512; R = 128; C = 512; mode = 1;
        c0 = (rem & 15) << 5; r0 = (rem >> 4) << 5;
        dH = w1bf + (long)e * 512 * 128;
    } else {
        bid -= 320; src = W2; R = 2048; C = 128; mode = 1;
        c0 = (bid & 3) << 5; r0 = (bid >> 2) << 5;
        dH = w2bf;
    }

    for (int i = threadIdx.x; i < 1024; i += 256) {
        const int r = i >> 5, c = i & 31;
        t[r][c] = src[(long)(r0 + r) * C + c0 + c];
    }
    __syncthreads();
    for (int i = threadIdx.x; i < 1024; i += 256) {
        const int c = i >> 5, r = i & 31;
        const float v = t[r][c];
        const long o = (long)(c0 + c) * R + r0 + r;
        if (mode == 0) {
            const u32 big = f2tf32(v);
            dB[o] = __uint_as_float(big);
            dS[o] = __uint_as_float(f2tf32(v - __uint_as_float(big)));
        } else if (mode == 3) {
            dB[o] = tf32f(v);
        } else {
            dH[o] = __float2bfloat16(v);
        }
    }
}

// ============================================================================
// TF32 mma GEMM, BM=64 x BN=128, BK=16, cp.async 2-stage. Templated:
//  X3=1: 3xTF32 big/small (stage 30720 B, smem 61440)
//  X3=0: 1xTF32 big only  (stage 15360 B, smem 30720) — multi-block co-res.
// part: optional fused column stats (gridDim.x==1); block owns 64 tokens.
// ============================================================================
template<int X3>
__global__ void __launch_bounds__(256) gemm_mma3(
    const float* __restrict__ Ab, const float* __restrict__ As,
    const float* __restrict__ Bb, const float* __restrict__ Bsm,
    const float* __restrict__ bias, const float* __restrict__ resid,
    float* __restrict__ C,
    int lda, int ldb, int ldc, int Kt, int ldres, float* __restrict__ part)
{
    extern __shared__ float dynsm[];
    const u32 smu = (u32)__cvta_generic_to_shared(dynsm);
    const u32 stageB = X3 ? 30720u : 15360u;
    const int stageF = X3 ? 7680 : 3840;
    const int bOffF  = X3 ? 2560 : 1280;     // Bb offset in floats within stage

    const int tid = threadIdx.x, wid = tid >> 5, lane = tid & 31;
    const int m0 = blockIdx.y << 6, n0 = blockIdx.x << 7;
    const int wm = wid >> 2, wn = wid & 3;
    const int lr = lane >> 2, lc = lane & 3;

    const float* Abase  = Ab  + (long)m0 * lda;
    const float* Asbase = X3 ? (As + (long)m0 * lda) : (const float*)0;
    const float* Bbase  = Bb  + (long)n0 * ldb;
    const float* Bsbase = X3 ? (Bsm + (long)n0 * ldb) : (const float*)0;

    float acc[2][4][4];
    #pragma unroll
    for (int mi = 0; mi < 2; mi++)
        #pragma unroll
        for (int ni = 0; ni < 4; ni++)
            #pragma unroll
            for (int j = 0; j < 4; j++) acc[mi][ni][j] = 0.f;

#define STAGE3(KT, S) do { \
    const int _k0 = (KT) << 4; \
    const u32 _sb = smu + (S) * stageB; \
    { \
        const int row = tid >> 2, ch = (tid & 3) << 2; \
        const u32 off = (u32)(row * 20 + ch) * 4; \
        cpa16(_sb + off, Abase + (long)row * lda + _k0 + ch); \
        if (X3) cpa16(_sb + 5120 + off, Asbase + (long)row * lda + _k0 + ch); \
    } \
    _Pragma("unroll") \
    for (int c = 0; c < 2; c++) { \
        const int idx = tid + (c << 8); \
        const int row = idx >> 2, ch = (idx & 3) << 2; \
        const u32 off = (u32)(row * 20 + ch) * 4; \
        cpa16(_sb + bOffF * 4 + off, Bbase + (long)row * ldb + _k0 + ch); \
        if (X3) cpa16(_sb + 20480 + off, Bsbase + (long)row * ldb + _k0 + ch); \
    } \
    asm volatile("cp.async.commit_group;" ::: "memory"); \
} while (0)

    STAGE3(0, 0);
    for (int kt = 0; kt < Kt; kt++) {
        const int s = kt & 1;
        if (kt + 1 < Kt) {
            STAGE3(kt + 1, (kt + 1) & 1);
            asm volatile("cp.async.wait_group 1;" ::: "memory");
        } else {
            asm volatile("cp.async.wait_group 0;" ::: "memory");
        }
        __syncthreads();
        float* AbP = dynsm + s * stageF;
        float* AmP = AbP + 1280;
        float* BsP = AbP + bOffF;
        float* BmP = AbP + 5120;
        #pragma unroll
        for (int k8 = 0; k8 < 2; k8++) {
            const int kc = (k8 << 3) + lc;
            u32 af[2][4], am[2][4];
            #pragma unroll
            for (int mi = 0; mi < 2; mi++) {
                const int r = wm * 32 + mi * 16 + lr;
                af[mi][0] = __float_as_uint(AbP[(r    ) * 20 + kc    ]);
                af[mi][1] = __float_as_uint(AbP[(r + 8) * 20 + kc    ]);
                af[mi][2] = __float_as_uint(AbP[(r    ) * 20 + kc + 4]);
                af[mi][3] = __float_as_uint(AbP[(r + 8) * 20 + kc + 4]);
                if (X3) {
                    am[mi][0] = __float_as_uint(AmP[(r    ) * 20 + kc    ]);
                    am[mi][1] = __float_as_uint(AmP[(r + 8) * 20 + kc    ]);
                    am[mi][2] = __float_as_uint(AmP[(r    ) * 20 + kc + 4]);
                    am[mi][3] = __float_as_uint(AmP[(r + 8) * 20 + kc + 4]);
                }
            }
            #pragma unroll
            for (int ni = 0; ni < 4; ni++) {
                const int nr = wn * 32 + ni * 8 + lr;
                u32 b0 = __float_as_uint(BsP[nr * 20 + kc    ]);
                u32 b1 = __float_as_uint(BsP[nr * 20 + kc + 4]);
                u32 s0 = 0, s1 = 0;
                if (X3) {
                    s0 = __float_as_uint(BmP[nr * 20 + kc    ]);
                    s1 = __float_as_uint(BmP[nr * 20 + kc + 4]);
                }
                #pragma unroll
                for (int mi = 0; mi < 2; mi++) {
                    if (X3) {
                        MMA_TF32(acc[mi][ni], am[mi][0], am[mi][1], am[mi][2], am[mi][3], b0, b1);
                        MMA_TF32(acc[mi][ni], af[mi][0], af[mi][1], af[mi][2], af[mi][3], s0, s1);
                    }
                    MMA_TF32(acc[mi][ni], af[mi][0], af[mi][1], af[mi][2], af[mi][3], b0, b1);
                }
            }
        }
        __syncthreads();
    }
#undef STAGE3

    float s8[8], q8[8];
    #pragma unroll
    for (int i = 0; i < 8; i++) { s8[i] = 0.f; q8[i] = 0.f; }

    #pragma unroll
    for (int mi = 0; mi < 2; mi++) {
        const int r0 = m0 + wm * 32 + mi * 16 + lr;
        const int r1 = r0 + 8;
        #pragma unroll
        for (int ni = 0; ni < 4; ni++) {
            const int col = wn * 32 + ni * 8 + (lc << 1);
            float v0 = acc[mi][ni][0], v1 = acc[mi][ni][1];
            float v2 = acc[mi][ni][2], v3 = acc[mi][ni][3];
            if (bias) {
                float2 bbv = *(const float2*)&bias[n0 + col];
                v0 += bbv.x; v1 += bbv.y; v2 += bbv.x; v3 += bbv.y;
            }
            if (resid) {
                float2 ra = *(const float2*)&resid[(long)r0 * ldres + n0 + col];
                float2 rb = *(const float2*)&resid[(long)r1 * ldres + n0 + col];
                v0 += ra.x; v1 += ra.y; v2 += rb.x; v3 += rb.y;
            }
            *(float2*)&C[(long)r0 * ldc + n0 + col] = make_float2(v0, v1);
            *(float2*)&C[(long)r1 * ldc + n0 + col] = make_float2(v2, v3);
            if (part) {
                s8[ni * 2 + 0] += v0 + v2;
                s8[ni * 2 + 1] += v1 + v3;
                q8[ni * 2 + 0] += v0 * v0 + v2 * v2;
                q8[ni * 2 + 1] += v1 * v1 + v3 * v3;
            }
        }
    }

    if (part) {
        #pragma unroll
        for (int i = 0; i < 8; i++) {
            s8[i] += __shfl_xor_sync(0xffffffffu, s8[i], 4);
            s8[i] += __shfl_xor_sync(0xffffffffu, s8[i], 8);
            s8[i] += __shfl_xor_sync(0xffffffffu, s8[i], 16);
            q8[i] += __shfl_xor_sync(0xffffffffu, q8[i], 4);
            q8[i] += __shfl_xor_sync(0xffffffffu, q8[i], 8);
            q8[i] += __shfl_xor_sync(0xffffffffu, q8[i], 16);
        }
        float* ssum = dynsm;
        float* ssq  = dynsm + 256;
        __syncthreads();
        if (lr == 0) {
            #pragma unroll
            for (int i = 0; i < 8; i++) {
                const int col = wn * 32 + (i >> 1) * 8 + (lc << 1) + (i & 1);
                ssum[wm * 128 + col] = s8[i];
                ssq [wm * 128 + col] = q8[i];
            }
        }
        __syncthreads();
        if (tid < 128) {
            part[blockIdx.y * 256 + tid]       = ssum[tid] + ssum[128 + tid];
            part[blockIdx.y * 256 + 128 + tid] = ssq[tid]  + ssq[128 + tid];
        }
    }
}

// ============================================================================
// FUSED MoE + norm-1 apply + gating (unchanged from round 12).
// ============================================================================
#define SA_OFF  0u
#define SW1_OFF 17408u
#define SW2_OFF 52224u
#define SH_OFF  89088u
#define MOE_SMEM 107520

__global__ void __launch_bounds__(256) moe_fused(
    const float* __restrict__ pre1, const float* __restrict__ part,
    const float* __restrict__ n1w, const float* __restrict__ n1b,
    const float* __restrict__ wg,
    const __nv_bfloat16* __restrict__ w1bf, const __nv_bfloat16* __restrict__ w2bf,
    const float* __restrict__ b1,
    float* __restrict__ hout, float* __restrict__ gatesOut,
    float* __restrict__ ypart)
{
    extern __shared__ char msm[];
    const u32 smu = (u32)__cvta_generic_to_shared(msm);

    const int tid = threadIdx.x, wid = tid >> 5, lane = tid & 31;
    const int lr = lane >> 2, lc = lane & 3, sel = lane >> 3;
    const int wm = wid >> 1, wn = wid & 1;
    const int m0 = blockIdx.x << 6;
    const int e0 = blockIdx.y << 1;
    const int b  = m0 >> 10;

#define MSTAGE(IT, S) do { \
    const int _e = e0 + ((IT) >> 3), _c = (IT) & 7; \
    const __nv_bfloat16* _w1 = w1bf + (long)((_e << 9) + (_c << 6)) * 128; \
    const __nv_bfloat16* _w2 = w2bf + (_e << 9) + (_c << 6); \
    _Pragma("unroll") \
    for (int j = 0; j < 4; j++) { \
        const int idx = tid + (j << 8); \
        const int r1 = idx >> 4, ch1 = (idx & 15) << 3; \
        cpa16(smu + SW1_OFF + (S) * 17408u + (u32)(r1 * 136 + ch1) * 2, \
              _w1 + (long)r1 * 128 + ch1); \
        const int r2 = idx >> 3, ch2 = (idx & 7) << 3; \
        cpa16(smu + SW2_OFF + (S) * 18432u + (u32)(r2 * 72 + ch2) * 2, \
              _w2 + (long)r2 * 2048 + ch2); \
    } \
    asm volatile("cp.async.commit_group;" ::: "memory"); \
} while (0)

    MSTAGE(0, 0);

    float* ovl    = (float*)(msm + SW1_OFF + 17408u);
    float* scA    = ovl;
    float* sfA    = ovl + 128;
    float* wgS    = ovl + 256;
    float* gatesS = ovl + 768;
    wgS[tid] = wg[tid];
    wgS[tid + 256] = wg[tid + 256];
    if (tid < DD) {
        const int d = tid;
        float s = 0.f, q = 0.f;
        for (int c = 0; c < 16; c++) {
            const float* p = part + (long)(b * 16 + c) * 256;
            s += p[d]; q += p[DD + d];
        }
        float mean = s * (1.f / 1024.f);
        float var  = q * (1.f / 1024.f) - mean * mean;
        float inv  = rsqrtf(var + 1e-5f);
        float scale = n1w[d] * inv;
        scA[d] = scale;
        sfA[d] = n1b[d] - mean * scale;
    }
    __syncthreads();

    {
        const int c4 = tid & 31, rg = tid >> 5;
        const int c0 = c4 << 2;
        for (int r = rg; r < 64; r += 8) {
            const long tok = m0 + r;
            float4 v = *(const float4*)(pre1 + tok * DD + c0);
            float4 o;
            o.x = v.x * scA[c0 + 0] + sfA[c0 + 0];
            o.y = v.y * scA[c0 + 1] + sfA[c0 + 1];
            o.z = v.z * scA[c0 + 2] + sfA[c0 + 2];
            o.w = v.w * scA[c0 + 3] + sfA[c0 + 3];
            if (e0 == 0) *(float4*)(hout + tok * DD + c0) = o;
            __nv_bfloat162 p0 = __floats2bfloat162_rn(o.x, o.y);
            __nv_bfloat162 p1 = __floats2bfloat162_rn(o.z, o.w);
            asm volatile("st.shared.v2.b32 [%0], {%1, %2};" ::
                "r"(smu + SA_OFF + (u32)(r * 136 + c0) * 2),
                "r"(*(u32*)&p0), "r"(*(u32*)&p1));
            float l0 = o.x * wgS[(c0 + 0) * NE + 0] + o.y * wgS[(c0 + 1) * NE + 0]
                     + o.z * wgS[(c0 + 2) * NE + 0] + o.w * wgS[(c0 + 3) * NE + 0];
            float l1 = o.x * wgS[(c0 + 0) * NE + 1] + o.y * wgS[(c0 + 1) * NE + 1]
                     + o.z * wgS[(c0 + 2) * NE + 1] + o.w * wgS[(c0 + 3) * NE + 1];
            float l2 = o.x * wgS[(c0 + 0) * NE + 2] + o.y * wgS[(c0 + 1) * NE + 2]
                     + o.z * wgS[(c0 + 2) * NE + 2] + o.w * wgS[(c0 + 3) * NE + 2];
            float l3 = o.x * wgS[(c0 + 0) * NE + 3] + o.y * wgS[(c0 + 1) * NE + 3]
                     + o.z * wgS[(c0 + 2) * NE + 3] + o.w * wgS[(c0 + 3) * NE + 3];
            #pragma unroll
            for (int off = 16; off; off >>= 1) {
                l0 += __shfl_xor_sync(0xffffffffu, l0, off);
                l1 += __shfl_xor_sync(0xffffffffu, l1, off);
                l2 += __shfl_xor_sync(0xffffffffu, l2, off);
                l3 += __shfl_xor_sync(0xffffffffu, l3, off);
            }
            if (c4 == 0) {
                float lg[4] = {l0, l1, l2, l3};
                int i1 = 0; float v1 = lg[0];
                #pragma unroll
                for (int e = 1; e < 4; e++) if (lg[e] > v1) { v1 = lg[e]; i1 = e; }
                int i2 = 0; float v2 = -3e38f;
                #pragma unroll
                for (int e = 0; e < 4; e++) if (e != i1 && lg[e] > v2) { v2 = lg[e]; i2 = e; }
                float e2  = expf(v2 - v1);
                float inv = 1.f / (1.f + e2);
                #pragma unroll
                for (int e = 0; e < 4; e++) {
                    const float gv = (e == i1) ? inv : ((e == i2) ? e2 * inv : 0.f);
                    gatesS[r * NE + e] = gv;
                    if (e0 == 0) gatesOut[tok * NE + e] = gv;
                }
            }
        }
    }
    __syncthreads();

    const int row0 = wm * 16 + lr;
    const float g00 = gatesS[(row0    ) * NE + e0];
    const float g01 = gatesS[(row0    ) * NE + e0 + 1];
    const float g10 = gatesS[(row0 + 8) * NE + e0];
    const float g11 = gatesS[(row0 + 8) * NE + e0 + 1];
    __syncthreads();

    const u32 aoff1 = (u32)((wm * 16 + (lane & 7) + ((sel & 1) << 3)) * 136
                            + ((sel >> 1) << 3)) * 2;
    u32 boff1[2];
    #pragma unroll
    for (int nb = 0; nb < 2; nb++)
        boff1[nb] = (u32)((wn * 32 + nb * 16 + ((sel >> 1) << 3) + (lane & 7)) * 136
                          + ((sel & 1) << 3)) * 2;
    const u32 aoff2 = (u32)((wm * 16 + (lane & 7) + ((sel & 1) << 3)) * 72
                            + ((sel >> 1) << 3)) * 2;
    u32 boff2[4];
    #pragma unroll
    for (int nb = 0; nb < 4; nb++)
        boff2[nb] = (u32)((wn * 64 + nb * 16 + ((sel >> 1) << 3) + (lane & 7)) * 72
                          + ((sel & 1) << 3)) * 2;

    float acc2[8][4];
    #pragma unroll
    for (int ni = 0; ni < 8; ni++)
        #pragma unroll
        for (int j = 0; j < 4; j++) acc2[ni][j] = 0.f;

    const int gtok0 = m0 + row0, gtok1 = gtok0 + 8;

    for (int it = 0; it < 16; it++) {
        const int s = it & 1;
        const int e = e0 + (it >> 3), c = it & 7;
        if (it + 1 < 16) {
            MSTAGE(it + 1, s ^ 1);
            asm volatile("cp.async.wait_group 1;" ::: "memory");
        } else {
            asm volatile("cp.async.wait_group 0;" ::: "memory");
        }
        __syncthreads();

        const u32 w1b = smu + SW1_OFF + s * 17408u;
        const u32 ab  = smu + SA_OFF;
        float acc1[4][4];
        #pragma unroll
        for (int ni = 0; ni < 4; ni++)
            #pragma unroll
            for (int j = 0; j < 4; j++) acc1[ni][j] = 0.f;
        #pragma unroll
        for (int k16 = 0; k16 < 8; k16++) {
            u32 a[4];
            ldsm4(a, ab + aoff1 + k16 * 32);
            #pragma unroll
            for (int nb = 0; nb < 2; nb++) {
                u32 bf[4];
                ldsm4(bf, w1b + boff1[nb] + k16 * 32);
                MMA_BF16(acc1[2 * nb    ], a, bf[0], bf[1]);
                MMA_BF16(acc1[2 * nb + 1], a, bf[2], bf[3]);
            }
        }
        const float g0 = (it >> 3) ? g01 : g00;
        const float g1 = (it >> 3) ? g11 : g10;
        const u32 hbse = smu + SH_OFF + s * 9216u;
        #pragma unroll
        for (int ni = 0; ni < 4; ni++) {
            const int col = wn * 32 + ni * 8 + (lc << 1);
            const float bb0 = __ldg(&b1[(e << 9) + (c << 6) + col]);
            const float bb1 = __ldg(&b1[(e << 9) + (c << 6) + col + 1]);
            float v0 = fmaxf(acc1[ni][0] + bb0, 0.f) * g0;
            float v1 = fmaxf(acc1[ni][1] + bb1, 0.f) * g0;
            float v2 = fmaxf(acc1[ni][2] + bb0, 0.f) * g1;
            float v3 = fmaxf(acc1[ni][3] + bb1, 0.f) * g1;
            __nv_bfloat162 p0 = __floats2bfloat162_rn(v0, v1);
            __nv_bfloat162 p1 = __floats2bfloat162_rn(v2, v3);
            asm volatile("st.shared.b32 [%0], %1;" ::
                "r"(hbse + (u32)(row0 * 72 + col) * 2), "r"(*(u32*)&p0));
            asm volatile("st.shared.b32 [%0], %1;" ::
                "r"(hbse + (u32)((row0 + 8) * 72 + col) * 2), "r"(*(u32*)&p1));
        }
        asm volatile("bar.sync %0, 64;" :: "r"(wm + 1) : "memory");

        const u32 w2b = smu + SW2_OFF + s * 18432u;
        #pragma unroll
        for (int k16 = 0; k16 < 4; k16++) {
            u32 a[4];
            ldsm4(a, hbse + aoff2 + k16 * 32);
            #pragma unroll
            for (int nb = 0; nb < 4; nb++) {
                u32 bf[4];
                ldsm4(bf, w2b + boff2[nb] + k16 * 32);
                MMA_BF16(acc2[2 * nb    ], a, bf[0], bf[1]);
                MMA_BF16(acc2[2 * nb + 1], a, bf[2], bf[3]);
            }
        }
        __syncthreads();
    }
#undef MSTAGE

    float* yz = ypart + (long)blockIdx.y * NTOK * DD;
    #pragma unroll
    for (int ni = 0; ni < 8; ni++) {
        const int col = wn * 64 + ni * 8 + (lc << 1);
        *(float2*)&yz[(long)gtok0 * DD + col] = make_float2(acc2[ni][0], acc2[ni][1]);
        *(float2*)&yz[(long)gtok1 * DD + col] = make_float2(acc2[ni][2], acc2[ni][3]);
    }
}

// ============================================================================
// MMA flash attention (unchanged from round 12).
// ============================================================================
#define VSR 1044
#define PSR 132
#define SM_K 0
#define SM_V (1024 * 16)
#define SM_P (SM_V + 16 * VSR)
#define ATTN_SMEM ((SM_P + 128 * PSR) * 4)

__global__ void __launch_bounds__(256) attn_mma(const float* __restrict__ qkv,
                                                float* __restrict__ oB,
                                                float* __restrict__ oS)
{
    extern __shared__ float sm[];
    const int bh = blockIdx.x, b = bh >> 3, h = bh & 7;
    const int tid = threadIdx.x, wid = tid >> 5, lane = tid & 31;
    const int lr = lane >> 2, lc = lane & 3;
    const float* qkvb = qkv + (long)b * SS * 384;
    const int qoff = h * HD, koff = DD + h * HD, voff = 2 * DD + h * HD;

    for (int i = tid; i < SS * 4; i += 256) {
        const int s = i >> 2, c4 = i & 3;
        float4 v = *(const float4*)(qkvb + (long)s * 384 + koff + (c4 << 2));
        float* kp = &sm[SM_K + (s << 4)];
        kp[c4]      = tf32f(v.x);
        kp[c4 + 4]  = tf32f(v.y);
        kp[c4 + 8]  = tf32f(v.z);
        kp[c4 + 12] = tf32f(v.w);
        float4 w = *(const float4*)(qkvb + (long)s * 384 + voff + (c4 << 2));
        const int colp = (s & ~7) + ((s & 3) << 1) + ((s & 7) >> 2);
        sm[SM_V + ((c4 << 2) + 0) * VSR + colp] = tf32f(w.x);
        sm[SM_V + ((c4 << 2) + 1) * VSR + colp] = tf32f(w.y);
        sm[SM_V + ((c4 << 2) + 2) * VSR + colp] = tf32f(w.z);
        sm[SM_V + ((c4 << 2) + 3) * VSR + colp] = tf32f(w.w);
    }
    __syncthreads();

    const int wq = wid << 4;
    float* Prow0 = &sm[SM_P + (wq + lr) * PSR];
    float* Prow1 = Prow0 + 8 * PSR;

    for (int j = 0; j < 4; j++) {
        const int qt = (blockIdx.y << 2) + j;

        const float* qp0 = qkvb + (long)(qt * 128 + wq + lr) * 384 + qoff;
        const float* qp1 = qp0 + 8 * 384;
        u32 qf[2][4];
        #pragma unroll
        for (int k8 = 0; k8 < 2; k8++) {
            const int c = (k8 << 3) + lc;
            qf[k8][0] = f2tf32(__ldg(&qp0[c])     * 0.25f);
            qf[k8][1] = f2tf32(__ldg(&qp1[c])     * 0.25f);
            qf[k8][2] = f2tf32(__ldg(&qp0[c + 4]) * 0.25f);
            qf[k8][3] = f2tf32(__ldg(&qp1[c + 4]) * 0.25f);
        }

        float oacc[2][4];
        #pragma unroll
        for (int t = 0; t < 2; t++)
            #pragma unroll
            for (int jj = 0; jj < 4; jj++) oacc[t][jj] = 0.f;
        float sl0 = 0.f, sl1 = 0.f;

        for (int kt = 0; kt < 8; kt++) {
            #pragma unroll
            for (int ni = 0; ni < 16; ni++) {
                const int krow = kt * 128 + ni * 8 + lr;
                float4 kv = *(const float4*)&sm[SM_K + (krow << 4) + (lc << 2)];
                float sacc[4] = {0.f, 0.f, 0.f, 0.f};
                MMA_TF32(sacc, qf[0][0], qf[0][1], qf[0][2], qf[0][3],
                         __float_as_uint(kv.x), __float_as_uint(kv.y));
                MMA_TF32(sacc, qf[1][0], qf[1][1], qf[1][2], qf[1][3],
                         __float_as_uint(kv.z), __float_as_uint(kv.w));
                const float p0 = __expf(sacc[0]), p1 = __expf(sacc[1]);
                const float p2 = __expf(sacc[2]), p3 = __expf(sacc[3]);
                sl0 += p0 + p1;
                sl1 += p2 + p3;
                const int col = ni * 8 + (lc << 1);
                *(float2*)&Prow0[col] = make_float2(p0, p1);
                *(float2*)&Prow1[col] = make_float2(p2, p3);
            }
            __syncwarp();
            #pragma unroll
            for (int k8 = 0; k8 < 16; k8++) {
                const int kc2 = (k8 << 3) + lc;
                u32 a0 = __float_as_uint(Prow0[kc2]);
                u32 a1 = __float_as_uint(Prow1[kc2]);
                u32 a2 = __float_as_uint(Prow0[kc2 + 4]);
                u32 a3 = __float_as_uint(Prow1[kc2 + 4]);
                const int kgb = kt * 128 + (k8 << 3) + (lc << 1);
                float2 va = *(const float2*)&sm[SM_V + (lr    ) * VSR + kgb];
                float2 vb = *(const float2*)&sm[SM_V + (lr + 8) * VSR + kgb];
                MMA_TF32(oacc[0], a0, a1, a2, a3,
                         __float_as_uint(va.x), __float_as_uint(va.y));
                MMA_TF32(oacc[1], a0, a1, a2, a3,
                         __float_as_uint(vb.x), __float_as_uint(vb.y));
            }
            __syncwarp();
        }

        float s0 = sl0, s1 = sl1;
        s0 += __shfl_xor_sync(0xffffffffu, s0, 1);
        s0 += __shfl_xor_sync(0xffffffffu, s0, 2);
        s1 += __shfl_xor_sync(0xffffffffu, s1, 1);
        s1 += __shfl_xor_sync(0xffffffffu, s1, 2);
        const float i0 = 1.f / s0, i1 = 1.f / s1;

        const long r0 = (long)(b * SS + qt * 128 + wq + lr);
        const long r1 = r0 + 8;
        #pragma unroll
        for (int t = 0; t < 2; t++) {
            const int col = h * HD + t * 8 + (lc << 1);
            float w0 = oacc[t][0] * i0, w1 = oacc[t][1] * i0;
            float w2 = oacc[t][2] * i1, w3 = oacc[t][3] * i1;
            float bb0 = tf32f(w0), bb1 = tf32f(w1), bb2 = tf32f(w2), bb3 = tf32f(w3);
            *(float2*)&oB[r0 * DD + col] = make_float2(bb0, bb1);
            *(float2*)&oB[r1 * DD + col] = make_float2(bb2, bb3);
            *(float2*)&oS[r0 * DD + col] = make_float2(tf32f(w0 - bb0), tf32f(w1 - bb1));
            *(float2*)&oS[r1 * DD + col] = make_float2(tf32f(w2 - bb2), tf32f(w3 - bb3));
        }
    }
}

// ============================================================================
// Norm-2 apply (unchanged)
// ============================================================================
__global__ void in_apply2(const float* __restrict__ in, const float* __restrict__ part,
                          const float* __restrict__ w, const float* __restrict__ bb,
                          float* __restrict__ out)
{
    const int b = blockIdx.y, chunk = blockIdx.x;
    __shared__ float sc[DD], sf[DD];
    if (threadIdx.x < DD) {
        const int d = threadIdx.x;
        float s = 0.f, q = 0.f;
        for (int c = 0; c < 16; c++) {
            const float* p = part + (long)((b * 16 + c) * 2) * DD;
            s += p[d]; q += p[DD + d];
        }
        float mean = s * (1.f / 1024.f);
        float var  = q * (1.f / 1024.f) - mean * mean;
        float inv  = rsqrtf(var + 1e-5f);
        float scale = w[d] * inv;
        sc[d] = scale;
        sf[d] = bb[d] - mean * scale;
    }
    __syncthreads();
    const float* base = in + ((long)b * SS + chunk * 64) * DD;
    float* ob = out + ((long)b * SS + chunk * 64) * DD;
    const int c4 = threadIdx.x & 31, rg = threadIdx.x >> 5;
    for (int r = rg; r < 64; r += 8) {
        float4 v = *(const float4*)(base + (long)r * DD + (c4 << 2));
        float4 o;
        o.x = v.x * sc[(c4 << 2) + 0] + sf[(c4 << 2) + 0];
        o.y = v.y * sc[(c4 << 2) + 1] + sf[(c4 << 2) + 1];
        o.z = v.z * sc[(c4 << 2) + 2] + sf[(c4 << 2) + 2];
        o.w = v.w * sc[(c4 << 2) + 3] + sf[(c4 << 2) + 3];
        *(float4*)(ob + (long)r * DD + (c4 << 2)) = o;
    }
}

// ============================================================================
// FUSED: pre2 = ypart[0] + ypart[1] + h + gate.b2, plus norm-2 stats (unchanged).
// ============================================================================
__global__ void add_stats(const float* __restrict__ yp, const float* __restrict__ h,
                          const float* __restrict__ gates, const float* __restrict__ b2,
                          float* __restrict__ pre2, float* __restrict__ part)
{
    const int b = blockIdx.y, chunk = blockIdx.x;
    __shared__ float b2s[NE * DD];
    b2s[threadIdx.x] = b2[threadIdx.x];
    b2s[threadIdx.x + 256] = b2[threadIdx.x + 256];
    __syncthreads();
    const long row0 = (long)b * SS + chunk * 64;
    const int c4 = threadIdx.x & 31, rg = threadIdx.x >> 5;
    const int c0 = c4 << 2;
    float4 s = make_float4(0.f, 0.f, 0.f, 0.f), q = s;
    for (int r = rg; r < 64; r += 8) {
        const long tok = row0 + r;
        const long idx = tok * DD + c0;
        const float* g = gates + tok * NE;
        const float g0 = g[0], g1 = g[1], g2 = g[2], g3 = g[3];
        float4 v = *(const float4*)(yp + idx);
        float4 v1 = *(const float4*)(yp + (long)NTOK * DD + idx);
        float4 hv = *(const float4*)(h + idx);
        float4 o;
        o.x = v.x + v1.x + hv.x
            + g0 * b2s[c0 + 0] + g1 * b2s[DD + c0 + 0] + g2 * b2s[2 * DD + c0 + 0] + g3 * b2s[3 * DD + c0 + 0];
        o.y = v.y + v1.y + hv.y
            + g0 * b2s[c0 + 1] + g1 * b2s[DD + c0 + 1] + g2 * b2s[2 * DD + c0 + 1] + g3 * b2s[3 * DD + c0 + 1];
        o.z = v.z + v1.z + hv.z
            + g0 * b2s[c0 + 2] + g1 * b2s[DD + c0 + 2] + g2 * b2s[2 * DD + c0 + 2] + g3 * b2s[3 * DD + c0 + 2];
        o.w = v.w + v1.w + hv.w
            + g0 * b2s[c0 + 3] + g1 * b2s[DD + c0 + 3] + g2 * b2s[2 * DD + c0 + 3] + g3 * b2s[3 * DD + c0 + 3];
        *(float4*)(pre2 + idx) = o;
        s.x += o.x; s.y += o.y; s.z += o.z; s.w += o.w;
        q.x += o.x * o.x; q.y += o.y * o.y; q.z += o.z * o.z; q.w += o.w * o.w;
    }
    __shared__ float4 sS[8][32], sQ[8][32];
    sS[rg][c4] = s; sQ[rg][c4] = q;
    __syncthreads();
    if (threadIdx.x < 32) {
        float4 ts = make_float4(0.f, 0.f, 0.f, 0.f), tq = ts;
        #pragma unroll
        for (int i = 0; i < 8; i++) {
            float4 a = sS[i][threadIdx.x], bq = sQ[i][threadIdx.x];
            ts.x += a.x; ts.y += a.y; ts.z += a.z; ts.w += a.w;
            tq.x += bq.x; tq.y += bq.y; tq.z += bq.z; tq.w += bq.w;
        }
        float* p = part + (long)((b * 16 + chunk) * 2) * DD;
        *(float4*)(p + (threadIdx.x << 2)) = ts;
        *(float4*)(p + DD + (threadIdx.x << 2)) = tq;
    }
}

// ============================================================================
// Launch (7 kernels)
// ============================================================================
extern "C" void kernel_launch(void* const* d_in, const int* in_sizes, int n_in,
                              void* d_out, int out_size)
{
    const float* x     = (const float*)d_in[0];
    const float* Wqkv  = (const float*)d_in[1];
    const float* bqkv  = (const float*)d_in[2];
    const float* Wo    = (const float*)d_in[3];
    const float* bo    = (const float*)d_in[4];
    const float* n1w   = (const float*)d_in[5];
    const float* n1b   = (const float*)d_in[6];
    const float* n2w   = (const float*)d_in[7];
    const float* n2b   = (const float*)d_in[8];
    const float* wg    = (const float*)d_in[9];
    const float* W1    = (const float*)d_in[10];
    const float* b1    = (const float*)d_in[11];
    const float* W2    = (const float*)d_in[12];
    const float* b2    = (const float*)d_in[13];

    float *qkv, *xB, *oB, *oS, *pre1, *h, *gates, *ypart, *pre2;
    float *wqkvB, *woB, *woS, *part;
    __nv_bfloat16 *w1bf, *w2bf;
    cudaGetSymbolAddress((void**)&qkv,   g_qkv);
    cudaGetSymbolAddress((void**)&xB,    g_xB);
    cudaGetSymbolAddress((void**)&oB,    g_oB);
    cudaGetSymbolAddress((void**)&oS,    g_oS);
    cudaGetSymbolAddress((void**)&pre1,  g_pre1);
    cudaGetSymbolAddress((void**)&h,     g_h);
    cudaGetSymbolAddress((void**)&gates, g_gates);
    cudaGetSymbolAddress((void**)&ypart, g_ypart);
    cudaGetSymbolAddress((void**)&pre2,  g_pre2);
    cudaGetSymbolAddress((void**)&w1bf,  g_w1bf);
    cudaGetSymbolAddress((void**)&w2bf,  g_w2bf);
    cudaGetSymbolAddress((void**)&wqkvB, g_wqkvB);
    cudaGetSymbolAddress((void**)&woB,   g_woB);
    cudaGetSymbolAddress((void**)&woS,   g_woS);
    cudaGetSymbolAddress((void**)&part,  g_part);

    cudaFuncSetAttribute(attn_mma, cudaFuncAttributeMaxDynamicSharedMemorySize, ATTN_SMEM);
    cudaFuncSetAttribute(gemm_mma3<0>, cudaFuncAttributeMaxDynamicSharedMemorySize, 30720);
    cudaFuncSetAttribute(gemm_mma3<1>, cudaFuncAttributeMaxDynamicSharedMemorySize, 61440);
    cudaFuncSetAttribute(moe_fused, cudaFuncAttributeMaxDynamicSharedMemorySize, MOE_SMEM);

    // 0. Merged prep
    weight_prep<<<608, 256>>>(Wqkv, Wo, W1, W2, x,
                              wqkvB, woB, woS, w1bf, w2bf, xB);

    // 1. QKV projection (1xTF32 — attention truncates to tf32 anyway)
    gemm_mma3<0><<<dim3(3, 128), 256, 30720>>>(xB, nullptr, wqkvB, nullptr,
                                               bqkv, nullptr, qkv,
                                               128, 128, 384, 8, 0, nullptr);

    // 2. MMA flash attention
    attn_mma<<<dim3(64, 2), 256, ATTN_SMEM>>>(qkv, oB, oS);

    // 3. O-projection + bo + residual x ⊕ norm-1 stats (3xTF32, routing-critical)
    gemm_mma3<1><<<dim3(1, 128), 256, 61440>>>(oB, oS, woB, woS, bo, x, pre1,
                                               128, 128, 128, 8, 128, part);

    // 4. FUSED MoE ⊕ norm-1 apply ⊕ gating
    moe_fused<<<dim3(128, 2), 256, MOE_SMEM>>>(pre1, part, n1w, n1b, wg,
                                               w1bf, w2bf, b1, h, gates, ypart);

    // 5. pre2 = ypart0 + ypart1 + h + gate·b2 ⊕ norm-2 stats
    add_stats<<<dim3(16, 8), 256>>>(ypart, h, gates, b2, pre2, part);

    // 6. Norm-2 apply -> output
    in_apply2<<<dim3(16, 8), 256>>>(pre2, part, n2w, n2b, (float*)d_out);
}

// round 14
// speedup vs baseline: 1.2885x; 1.0002x over previous
#include <cuda_runtime.h>
#include <cuda_bf16.h>

typedef unsigned long long ull;
typedef unsigned int u32;

// ===================== helpers =======================
__device__ __forceinline__ u32 f2tf32(float x) {
    u32 u; asm("cvt.rna.tf32.f32 %0, %1;" : "=r"(u) : "f"(x)); return u;
}
__device__ __forceinline__ float tf32f(float x) {
    return __uint_as_float(f2tf32(x));
}
__device__ __forceinline__ float ex2f(float x) {
    float r; asm("ex2.approx.f32 %0, %1;" : "=f"(r) : "f"(x)); return r;
}
#define MMA_TF32(acc, a0, a1, a2, a3, b0, b1) \
    asm volatile( \
        "mma.sync.aligned.m16n8k8.row.col.f32.tf32.tf32.f32 " \
        "{%0,%1,%2,%3}, {%4,%5,%6,%7}, {%8,%9}, {%0,%1,%2,%3};" \
        : "+f"((acc)[0]), "+f"((acc)[1]), "+f"((acc)[2]), "+f"((acc)[3]) \
        : "r"(a0), "r"(a1), "r"(a2), "r"(a3), "r"(b0), "r"(b1))

#define MMA_BF16(acc, a, b0, b1) \
    asm volatile( \
        "mma.sync.aligned.m16n8k16.row.col.f32.bf16.bf16.f32 " \
        "{%0,%1,%2,%3}, {%4,%5,%6,%7}, {%8,%9}, {%0,%1,%2,%3};" \
        : "+f"((acc)[0]), "+f"((acc)[1]), "+f"((acc)[2]), "+f"((acc)[3]) \
        : "r"((a)[0]), "r"((a)[1]), "r"((a)[2]), "r"((a)[3]), "r"(b0), "r"(b1))

__device__ __forceinline__ void ldsm4(u32* r, u32 addr) {
    asm volatile("ldmatrix.sync.aligned.m8n8.x4.shared.b16 {%0,%1,%2,%3}, [%4];"
        : "=r"(r[0]), "=r"(r[1]), "=r"(r[2]), "=r"(r[3]) : "r"(addr));
}
__device__ __forceinline__ void cpa16(u32 dst, const void* src) {
    asm volatile("cp.async.cg.shared.global [%0], [%1], 16;" :: "r"(dst), "l"(src));
}

// ===================== problem constants ====================================
#define BB    8
#define SS    1024
#define DD    128
#define NH    8
#define HD    16
#define NTOK  8192
#define HFF   512
#define NE    4

// ===================== scratch ==============================================
__device__ float         g_qkv  [NTOK * 384];
__device__ float         g_oB   [NTOK * DD];
__device__ float         g_oS   [NTOK * DD];
__device__ float         g_pre1 [NTOK * DD];
__device__ float         g_h    [NTOK * DD];
__device__ float         g_gates[NTOK * NE];
__device__ float         g_ypart[2 * NTOK * DD];
__device__ __nv_bfloat16 g_w1bf [NE * HFF * DD];
__device__ __nv_bfloat16 g_w2bf [DD * NE * HFF];
__device__ float         g_wqkvB[384 * DD];
__device__ float         g_woB  [DD * DD];
__device__ float         g_woS  [DD * DD];
__device__ float         g_part [128 * 256];
__device__ float         g_nrm  [BB * 256];
__device__ int           g_cnt1 = 0;
__device__ int           g_flag = 0;
__device__ int           g_cnt2 = 0;

// ============================================================================
// Merged prep: weight transposes (x is consumed raw by the 1xTF32 QKV gemm).
// ============================================================================
__global__ void __launch_bounds__(256) weight_prep(
    const float* __restrict__ Wqkv, const float* __restrict__ Wo,
    const float* __restrict__ W1,   const float* __restrict__ W2,
    float* __restrict__ wqkvB,
    float* __restrict__ woB,   float* __restrict__ woS,
    __nv_bfloat16* __restrict__ w1bf, __nv_bfloat16* __restrict__ w2bf)
{
    int bid = blockIdx.x;
    __shared__ float t[32][33];
    const float* src; int R, C, c0, r0, mode;   // 0: tf32 b+s, 1: bf16, 3: tf32 big
    float *dB = 0, *dS = 0; __nv_bfloat16* dH = 0;

    if (bid < 48) {
        src = Wqkv; R = 128; C = 384; mode = 3;
        c0 = (bid % 12) << 5; r0 = (bid / 12) << 5;
        dB = wqkvB;
    } else if (bid < 64) {
        bid -= 48; src = Wo; R = 128; C = 128; mode = 0;
        c0 = (bid & 3) << 5; r0 = (bid >> 2) << 5;
        dB = woB; dS = woS;
    } else if (bid < 320) {
        bid -= 64;
        const int e = bid >> 6, rem = bid & 63;
        src = W1 + (long)e * 128 * 512; R = 128; C = 512; mode = 1;
        c0 = (rem & 15) << 5; r0 = (rem >> 4) << 5;
        dH = w1bf + (long)e * 512 * 128;
    } else {
        bid -= 320; src = W2; R = 2048; C = 128; mode = 1;
        c0 = (bid & 3) << 5; r0 = (bid >> 2) << 5;
        dH = w2bf;
    }

    for (int i = threadIdx.x; i < 1024; i += 256) {
        const int r = i >> 5, c = i & 31;
        t[r][c] = src[(long)(r0 + r) * C + c0 + c];
    }
    __syncthreads();
    for (int i = threadIdx.x; i < 1024; i += 256) {
        const int c = i >> 5, r = i & 31;
        const float v = t[r][c];
        const long o = (long)(c0 + c) * R + r0 + r;
        if (mode == 0) {
            const u32 big = f2tf32(v);
            dB[o] = __uint_as_float(big);
            dS[o] = __uint_as_float(f2tf32(v - __uint_as_float(big)));
        } else if (mode == 3) {
            dB[o] = tf32f(v);
        } else {
            dH[o] = __float2bfloat16(v);
        }
    }
}

// ============================================================================
// TF32 mma GEMM, BM=64 x BN=128, BK=16, cp.async 2-stage (unchanged r13).
// ============================================================================
template<int X3>
__global__ void __launch_bounds__(256) gemm_mma3(
    const float* __restrict__ Ab, const float* __restrict__ As,
    const float* __restrict__ Bb, const float* __restrict__ Bsm,
    const float* __restrict__ bias, const float* __restrict__ resid,
    float* __restrict__ C,
    int lda, int ldb, int ldc, int Kt, int ldres, float* __restrict__ part)
{
    extern __shared__ float dynsm[];
    const u32 smu = (u32)__cvta_generic_to_shared(dynsm);
    const u32 stageB = X3 ? 30720u : 15360u;
    const int stageF = X3 ? 7680 : 3840;
    const int bOffF  = X3 ? 2560 : 1280;

    const int tid = threadIdx.x, wid = tid >> 5, lane = tid & 31;
    const int m0 = blockIdx.y << 6, n0 = blockIdx.x << 7;
    const int wm = wid >> 2, wn = wid & 3;
    const int lr = lane >> 2, lc = lane & 3;

    const float* Abase  = Ab  + (long)m0 * lda;
    const float* Asbase = X3 ? (As + (long)m0 * lda) : (const float*)0;
    const float* Bbase  = Bb  + (long)n0 * ldb;
    const float* Bsbase = X3 ? (Bsm + (long)n0 * ldb) : (const float*)0;

    float acc[2][4][4];
    #pragma unroll
    for (int mi = 0; mi < 2; mi++)
        #pragma unroll
        for (int ni = 0; ni < 4; ni++)
            #pragma unroll
            for (int j = 0; j < 4; j++) acc[mi][ni][j] = 0.f;

#define STAGE3(KT, S) do { \
    const int _k0 = (KT) << 4; \
    const u32 _sb = smu + (S) * stageB; \
    { \
        const int row = tid >> 2, ch = (tid & 3) << 2; \
        const u32 off = (u32)(row * 20 + ch) * 4; \
        cpa16(_sb + off, Abase + (long)row * lda + _k0 + ch); \
        if (X3) cpa16(_sb + 5120 + off, Asbase + (long)row * lda + _k0 + ch); \
    } \
    _Pragma("unroll") \
    for (int c = 0; c < 2; c++) { \
        const int idx = tid + (c << 8); \
        const int row = idx >> 2, ch = (idx & 3) << 2; \
        const u32 off = (u32)(row * 20 + ch) * 4; \
        cpa16(_sb + bOffF * 4 + off, Bbase + (long)row * ldb + _k0 + ch); \
        if (X3) cpa16(_sb + 20480 + off, Bsbase + (long)row * ldb + _k0 + ch); \
    } \
    asm volatile("cp.async.commit_group;" ::: "memory"); \
} while (0)

    STAGE3(0, 0);
    for (int kt = 0; kt < Kt; kt++) {
        const int s = kt & 1;
        if (kt + 1 < Kt) {
            STAGE3(kt + 1, (kt + 1) & 1);
            asm volatile("cp.async.wait_group 1;" ::: "memory");
        } else {
            asm volatile("cp.async.wait_group 0;" ::: "memory");
        }
        __syncthreads();
        float* AbP = dynsm + s * stageF;
        float* AmP = AbP + 1280;
        float* BsP = AbP + bOffF;
        float* BmP = AbP + 5120;
        #pragma unroll
        for (int k8 = 0; k8 < 2; k8++) {
            const int kc = (k8 << 3) + lc;
            u32 af[2][4], am[2][4];
            #pragma unroll
            for (int mi = 0; mi < 2; mi++) {
                const int r = wm * 32 + mi * 16 + lr;
                af[mi][0] = __float_as_uint(AbP[(r    ) * 20 + kc    ]);
                af[mi][1] = __float_as_uint(AbP[(r + 8) * 20 + kc    ]);
                af[mi][2] = __float_as_uint(AbP[(r    ) * 20 + kc + 4]);
                af[mi][3] = __float_as_uint(AbP[(r + 8) * 20 + kc + 4]);
                if (X3) {
                    am[mi][0] = __float_as_uint(AmP[(r    ) * 20 + kc    ]);
                    am[mi][1] = __float_as_uint(AmP[(r + 8) * 20 + kc    ]);
                    am[mi][2] = __float_as_uint(AmP[(r    ) * 20 + kc + 4]);
                    am[mi][3] = __float_as_uint(AmP[(r + 8) * 20 + kc + 4]);
                }
            }
            #pragma unroll
            for (int ni = 0; ni < 4; ni++) {
                const int nr = wn * 32 + ni * 8 + lr;
                u32 b0 = __float_as_uint(BsP[nr * 20 + kc    ]);
                u32 b1 = __float_as_uint(BsP[nr * 20 + kc + 4]);
                u32 s0 = 0, s1 = 0;
                if (X3) {
                    s0 = __float_as_uint(BmP[nr * 20 + kc    ]);
                    s1 = __float_as_uint(BmP[nr * 20 + kc + 4]);
                }
                #pragma unroll
                for (int mi = 0; mi < 2; mi++) {
                    if (X3) {
                        MMA_TF32(acc[mi][ni], am[mi][0], am[mi][1], am[mi][2], am[mi][3], b0, b1);
                        MMA_TF32(acc[mi][ni], af[mi][0], af[mi][1], af[mi][2], af[mi][3], s0, s1);
                    }
                    MMA_TF32(acc[mi][ni], af[mi][0], af[mi][1], af[mi][2], af[mi][3], b0, b1);
                }
            }
        }
        __syncthreads();
    }
#undef STAGE3

    float s8[8], q8[8];
    #pragma unroll
    for (int i = 0; i < 8; i++) { s8[i] = 0.f; q8[i] = 0.f; }

    #pragma unroll
    for (int mi = 0; mi < 2; mi++) {
        const int r0 = m0 + wm * 32 + mi * 16 + lr;
        const int r1 = r0 + 8;
        #pragma unroll
        for (int ni = 0; ni < 4; ni++) {
            const int col = wn * 32 + ni * 8 + (lc << 1);
            float v0 = acc[mi][ni][0], v1 = acc[mi][ni][1];
            float v2 = acc[mi][ni][2], v3 = acc[mi][ni][3];
            if (bias) {
                float2 bbv = *(const float2*)&bias[n0 + col];
                v0 += bbv.x; v1 += bbv.y; v2 += bbv.x; v3 += bbv.y;
            }
            if (resid) {
                float2 ra = *(const float2*)&resid[(long)r0 * ldres + n0 + col];
                float2 rb = *(const float2*)&resid[(long)r1 * ldres + n0 + col];
                v0 += ra.x; v1 += ra.y; v2 += rb.x; v3 += rb.y;
            }
            *(float2*)&C[(long)r0 * ldc + n0 + col] = make_float2(v0, v1);
            *(float2*)&C[(long)r1 * ldc + n0 + col] = make_float2(v2, v3);
            if (part) {
                s8[ni * 2 + 0] += v0 + v2;
                s8[ni * 2 + 1] += v1 + v3;
                q8[ni * 2 + 0] += v0 * v0 + v2 * v2;
                q8[ni * 2 + 1] += v1 * v1 + v3 * v3;
            }
        }
    }

    if (part) {
        #pragma unroll
        for (int i = 0; i < 8; i++) {
            s8[i] += __shfl_xor_sync(0xffffffffu, s8[i], 4);
            s8[i] += __shfl_xor_sync(0xffffffffu, s8[i], 8);
            s8[i] += __shfl_xor_sync(0xffffffffu, s8[i], 16);
            q8[i] += __shfl_xor_sync(0xffffffffu, q8[i], 4);
            q8[i] += __shfl_xor_sync(0xffffffffu, q8[i], 8);
            q8[i] += __shfl_xor_sync(0xffffffffu, q8[i], 16);
        }
        float* ssum = dynsm;
        float* ssq  = dynsm + 256;
        __syncthreads();
        if (lr == 0) {
            #pragma unroll
            for (int i = 0; i < 8; i++) {
                const int col = wn * 32 + (i >> 1) * 8 + (lc << 1) + (i & 1);
                ssum[wm * 128 + col] = s8[i];
                ssq [wm * 128 + col] = q8[i];
            }
        }
        __syncthreads();
        if (tid < 128) {
            part[blockIdx.y * 256 + tid]       = ssum[tid] + ssum[128 + tid];
            part[blockIdx.y * 256 + 128 + tid] = ssq[tid]  + ssq[128 + tid];
        }
    }
}

// ============================================================================
// FUSED MoE + norm-1 apply + gating (unchanged from round 13).
// ============================================================================
#define SA_OFF  0u
#define SW1_OFF 17408u
#define SW2_OFF 52224u
#define SH_OFF  89088u
#define MOE_SMEM 107520

__global__ void __launch_bounds__(256) moe_fused(
    const float* __restrict__ pre1, const float* __restrict__ part,
    const float* __restrict__ n1w, const float* __restrict__ n1b,
    const float* __restrict__ wg,
    const __nv_bfloat16* __restrict__ w1bf, const __nv_bfloat16* __restrict__ w2bf,
    const float* __restrict__ b1,
    float* __restrict__ hout, float* __restrict__ gatesOut,
    float* __restrict__ ypart)
{
    extern __shared__ char msm[];
    const u32 smu = (u32)__cvta_generic_to_shared(msm);

    const int tid = threadIdx.x, wid = tid >> 5, lane = tid & 31;
    const int lr = lane >> 2, lc = lane & 3, sel = lane >> 3;
    const int wm = wid >> 1, wn = wid & 1;
    const int m0 = blockIdx.x << 6;
    const int e0 = blockIdx.y << 1;
    const int b  = m0 >> 10;

#define MSTAGE(IT, S) do { \
    const int _e = e0 + ((IT) >> 3), _c = (IT) & 7; \
    const __nv_bfloat16* _w1 = w1bf + (long)((_e << 9) + (_c << 6)) * 128; \
    const __nv_bfloat16* _w2 = w2bf + (_e << 9) + (_c << 6); \
    _Pragma("unroll") \
    for (int j = 0; j < 4; j++) { \
        const int idx = tid + (j << 8); \
        const int r1 = idx >> 4, ch1 = (idx & 15) << 3; \
        cpa16(smu + SW1_OFF + (S) * 17408u + (u32)(r1 * 136 + ch1) * 2, \
              _w1 + (long)r1 * 128 + ch1); \
        const int r2 = idx >> 3, ch2 = (idx & 7) << 3; \
        cpa16(smu + SW2_OFF + (S) * 18432u + (u32)(r2 * 72 + ch2) * 2, \
              _w2 + (long)r2 * 2048 + ch2); \
    } \
    asm volatile("cp.async.commit_group;" ::: "memory"); \
} while (0)

    MSTAGE(0, 0);

    float* ovl    = (float*)(msm + SW1_OFF + 17408u);
    float* scA    = ovl;
    float* sfA    = ovl + 128;
    float* wgS    = ovl + 256;
    float* gatesS = ovl + 768;
    wgS[tid] = wg[tid];
    wgS[tid + 256] = wg[tid + 256];
    if (tid < DD) {
        const int d = tid;
        float s = 0.f, q = 0.f;
        for (int c = 0; c < 16; c++) {
            const float* p = part + (long)(b * 16 + c) * 256;
            s += p[d]; q += p[DD + d];
        }
        float mean = s * (1.f / 1024.f);
        float var  = q * (1.f / 1024.f) - mean * mean;
        float inv  = rsqrtf(var + 1e-5f);
        float scale = n1w[d] * inv;
        scA[d] = scale;
        sfA[d] = n1b[d] - mean * scale;
    }
    __syncthreads();

    {
        const int c4 = tid & 31, rg = tid >> 5;
        const int c0 = c4 << 2;
        for (int r = rg; r < 64; r += 8) {
            const long tok = m0 + r;
            float4 v = *(const float4*)(pre1 + tok * DD + c0);
            float4 o;
            o.x = v.x * scA[c0 + 0] + sfA[c0 + 0];
            o.y = v.y * scA[c0 + 1] + sfA[c0 + 1];
            o.z = v.z * scA[c0 + 2] + sfA[c0 + 2];
            o.w = v.w * scA[c0 + 3] + sfA[c0 + 3];
            if (e0 == 0) *(float4*)(hout + tok * DD + c0) = o;
            __nv_bfloat162 p0 = __floats2bfloat162_rn(o.x, o.y);
            __nv_bfloat162 p1 = __floats2bfloat162_rn(o.z, o.w);
            asm volatile("st.shared.v2.b32 [%0], {%1, %2};" ::
                "r"(smu + SA_OFF + (u32)(r * 136 + c0) * 2),
                "r"(*(u32*)&p0), "r"(*(u32*)&p1));
            float l0 = o.x * wgS[(c0 + 0) * NE + 0] + o.y * wgS[(c0 + 1) * NE + 0]
                     + o.z * wgS[(c0 + 2) * NE + 0] + o.w * wgS[(c0 + 3) * NE + 0];
            float l1 = o.x * wgS[(c0 + 0) * NE + 1] + o.y * wgS[(c0 + 1) * NE + 1]
                     + o.z * wgS[(c0 + 2) * NE + 1] + o.w * wgS[(c0 + 3) * NE + 1];
            float l2 = o.x * wgS[(c0 + 0) * NE + 2] + o.y * wgS[(c0 + 1) * NE + 2]
                     + o.z * wgS[(c0 + 2) * NE + 2] + o.w * wgS[(c0 + 3) * NE + 2];
            float l3 = o.x * wgS[(c0 + 0) * NE + 3] + o.y * wgS[(c0 + 1) * NE + 3]
                     + o.z * wgS[(c0 + 2) * NE + 3] + o.w * wgS[(c0 + 3) * NE + 3];
            #pragma unroll
            for (int off = 16; off; off >>= 1) {
                l0 += __shfl_xor_sync(0xffffffffu, l0, off);
                l1 += __shfl_xor_sync(0xffffffffu, l1, off);
                l2 += __shfl_xor_sync(0xffffffffu, l2, off);
                l3 += __shfl_xor_sync(0xffffffffu, l3, off);
            }
            if (c4 == 0) {
                float lg[4] = {l0, l1, l2, l3};
                int i1 = 0; float v1 = lg[0];
                #pragma unroll
                for (int e = 1; e < 4; e++) if (lg[e] > v1) { v1 = lg[e]; i1 = e; }
                int i2 = 0; float v2 = -3e38f;
                #pragma unroll
                for (int e = 0; e < 4; e++) if (e != i1 && lg[e] > v2) { v2 = lg[e]; i2 = e; }
                float e2  = expf(v2 - v1);
                float inv = 1.f / (1.f + e2);
                #pragma unroll
                for (int e = 0; e < 4; e++) {
                    const float gv = (e == i1) ? inv : ((e == i2) ? e2 * inv : 0.f);
                    gatesS[r * NE + e] = gv;
                    if (e0 == 0) gatesOut[tok * NE + e] = gv;
                }
            }
        }
    }
    __syncthreads();

    const int row0 = wm * 16 + lr;
    const float g00 = gatesS[(row0    ) * NE + e0];
    const float g01 = gatesS[(row0    ) * NE + e0 + 1];
    const float g10 = gatesS[(row0 + 8) * NE + e0];
    const float g11 = gatesS[(row0 + 8) * NE + e0 + 1];
    __syncthreads();

    const u32 aoff1 = (u32)((wm * 16 + (lane & 7) + ((sel & 1) << 3)) * 136
                            + ((sel >> 1) << 3)) * 2;
    u32 boff1[2];
    #pragma unroll
    for (int nb = 0; nb < 2; nb++)
        boff1[nb] = (u32)((wn * 32 + nb * 16 + ((sel >> 1) << 3) + (lane & 7)) * 136
                          + ((sel & 1) << 3)) * 2;
    const u32 aoff2 = (u32)((wm * 16 + (lane & 7) + ((sel & 1) << 3)) * 72
                            + ((sel >> 1) << 3)) * 2;
    u32 boff2[4];
    #pragma unroll
    for (int nb = 0; nb < 4; nb++)
        boff2[nb] = (u32)((wn * 64 + nb * 16 + ((sel >> 1) << 3) + (lane & 7)) * 72
                          + ((sel & 1) << 3)) * 2;

    float acc2[8][4];
    #pragma unroll
    for (int ni = 0; ni < 8; ni++)
        #pragma unroll
        for (int j = 0; j < 4; j++) acc2[ni][j] = 0.f;

    const int gtok0 = m0 + row0, gtok1 = gtok0 + 8;

    for (int it = 0; it < 16; it++) {
        const int s = it & 1;
        const int e = e0 + (it >> 3), c = it & 7;
        if (it + 1 < 16) {
            MSTAGE(it + 1, s ^ 1);
            asm volatile("cp.async.wait_group 1;" ::: "memory");
        } else {
            asm volatile("cp.async.wait_group 0;" ::: "memory");
        }
        __syncthreads();

        const u32 w1b = smu + SW1_OFF + s * 17408u;
        const u32 ab  = smu + SA_OFF;
        float acc1[4][4];
        #pragma unroll
        for (int ni = 0; ni < 4; ni++)
            #pragma unroll
            for (int j = 0; j < 4; j++) acc1[ni][j] = 0.f;
        #pragma unroll
        for (int k16 = 0; k16 < 8; k16++) {
            u32 a[4];
            ldsm4(a, ab + aoff1 + k16 * 32);
            #pragma unroll
            for (int nb = 0; nb < 2; nb++) {
                u32 bf[4];
                ldsm4(bf, w1b + boff1[nb] + k16 * 32);
                MMA_BF16(acc1[2 * nb    ], a, bf[0], bf[1]);
                MMA_BF16(acc1[2 * nb + 1], a, bf[2], bf[3]);
            }
        }
        const float g0 = (it >> 3) ? g01 : g00;
        const float g1 = (it >> 3) ? g11 : g10;
        const u32 hbse = smu + SH_OFF + s * 9216u;
        #pragma unroll
        for (int ni = 0; ni < 4; ni++) {
            const int col = wn * 32 + ni * 8 + (lc << 1);
            const float bb0 = __ldg(&b1[(e << 9) + (c << 6) + col]);
            const float bb1 = __ldg(&b1[(e << 9) + (c << 6) + col + 1]);
            float v0 = fmaxf(acc1[ni][0] + bb0, 0.f) * g0;
            float v1 = fmaxf(acc1[ni][1] + bb1, 0.f) * g0;
            float v2 = fmaxf(acc1[ni][2] + bb0, 0.f) * g1;
            float v3 = fmaxf(acc1[ni][3] + bb1, 0.f) * g1;
            __nv_bfloat162 p0 = __floats2bfloat162_rn(v0, v1);
            __nv_bfloat162 p1 = __floats2bfloat162_rn(v2, v3);
            asm volatile("st.shared.b32 [%0], %1;" ::
                "r"(hbse + (u32)(row0 * 72 + col) * 2), "r"(*(u32*)&p0));
            asm volatile("st.shared.b32 [%0], %1;" ::
                "r"(hbse + (u32)((row0 + 8) * 72 + col) * 2), "r"(*(u32*)&p1));
        }
        asm volatile("bar.sync %0, 64;" :: "r"(wm + 1) : "memory");

        const u32 w2b = smu + SW2_OFF + s * 18432u;
        #pragma unroll
        for (int k16 = 0; k16 < 4; k16++) {
            u32 a[4];
            ldsm4(a, hbse + aoff2 + k16 * 32);
            #pragma unroll
            for (int nb = 0; nb < 4; nb++) {
                u32 bf[4];
                ldsm4(bf, w2b + boff2[nb] + k16 * 32);
                MMA_BF16(acc2[2 * nb    ], a, bf[0], bf[1]);
                MMA_BF16(acc2[2 * nb + 1], a, bf[2], bf[3]);
            }
        }
        __syncthreads();
    }
#undef MSTAGE

    float* yz = ypart + (long)blockIdx.y * NTOK * DD;
    #pragma unroll
    for (int ni = 0; ni < 8; ni++) {
        const int col = wn * 64 + ni * 8 + (lc << 1);
        *(float2*)&yz[(long)gtok0 * DD + col] = make_float2(acc2[ni][0], acc2[ni][1]);
        *(float2*)&yz[(long)gtok1 * DD + col] = make_float2(acc2[ni][2], acc2[ni][3]);
    }
}

// ============================================================================
// MMA flash attention — exp2 with log2(e) folded into Q scale.
// ============================================================================
#define VSR 1044
#define PSR 132
#define SM_K 0
#define SM_V (1024 * 16)
#define SM_P (SM_V + 16 * VSR)
#define ATTN_SMEM ((SM_P + 128 * PSR) * 4)

__global__ void __launch_bounds__(256) attn_mma(const float* __restrict__ qkv,
                                                float* __restrict__ oB,
                                                float* __restrict__ oS)
{
    extern __shared__ float sm[];
    const int bh = blockIdx.x, b = bh >> 3, h = bh & 7;
    const int tid = threadIdx.x, wid = tid >> 5, lane = tid & 31;
    const int lr = lane >> 2, lc = lane & 3;
    const float* qkvb = qkv + (long)b * SS * 384;
    const int qoff = h * HD, koff = DD + h * HD, voff = 2 * DD + h * HD;
    const float QSCL = 0.25f * 1.4426950408889634f;

    for (int i = tid; i < SS * 4; i += 256) {
        const int s = i >> 2, c4 = i & 3;
        float4 v = *(const float4*)(qkvb + (long)s * 384 + koff + (c4 << 2));
        float* kp = &sm[SM_K + (s << 4)];
        kp[c4]      = tf32f(v.x);
        kp[c4 + 4]  = tf32f(v.y);
        kp[c4 + 8]  = tf32f(v.z);
        kp[c4 + 12] = tf32f(v.w);
        float4 w = *(const float4*)(qkvb + (long)s * 384 + voff + (c4 << 2));
        const int colp = (s & ~7) + ((s & 3) << 1) + ((s & 7) >> 2);
        sm[SM_V + ((c4 << 2) + 0) * VSR + colp] = tf32f(w.x);
        sm[SM_V + ((c4 << 2) + 1) * VSR + colp] = tf32f(w.y);
        sm[SM_V + ((c4 << 2) + 2) * VSR + colp] = tf32f(w.z);
        sm[SM_V + ((c4 << 2) + 3) * VSR + colp] = tf32f(w.w);
    }
    __syncthreads();

    const int wq = wid << 4;
    float* Prow0 = &sm[SM_P + (wq + lr) * PSR];
    float* Prow1 = Prow0 + 8 * PSR;

    for (int j = 0; j < 4; j++) {
        const int qt = (blockIdx.y << 2) + j;

        const float* qp0 = qkvb + (long)(qt * 128 + wq + lr) * 384 + qoff;
        const float* qp1 = qp0 + 8 * 384;
        u32 qf[2][4];
        #pragma unroll
        for (int k8 = 0; k8 < 2; k8++) {
            const int c = (k8 << 3) + lc;
            qf[k8][0] = f2tf32(__ldg(&qp0[c])     * QSCL);
            qf[k8][1] = f2tf32(__ldg(&qp1[c])     * QSCL);
            qf[k8][2] = f2tf32(__ldg(&qp0[c + 4]) * QSCL);
            qf[k8][3] = f2tf32(__ldg(&qp1[c + 4]) * QSCL);
        }

        float oacc[2][4];
        #pragma unroll
        for (int t = 0; t < 2; t++)
            #pragma unroll
            for (int jj = 0; jj < 4; jj++) oacc[t][jj] = 0.f;
        float sl0 = 0.f, sl1 = 0.f;

        for (int kt = 0; kt < 8; kt++) {
            #pragma unroll
            for (int ni = 0; ni < 16; ni++) {
                const int krow = kt * 128 + ni * 8 + lr;
                float4 kv = *(const float4*)&sm[SM_K + (krow << 4) + (lc << 2)];
                float sacc[4] = {0.f, 0.f, 0.f, 0.f};
                MMA_TF32(sacc, qf[0][0], qf[0][1], qf[0][2], qf[0][3],
                         __float_as_uint(kv.x), __float_as_uint(kv.y));
                MMA_TF32(sacc, qf[1][0], qf[1][1], qf[1][2], qf[1][3],
                         __float_as_uint(kv.z), __float_as_uint(kv.w));
                const float p0 = ex2f(sacc[0]), p1 = ex2f(sacc[1]);
                const float p2 = ex2f(sacc[2]), p3 = ex2f(sacc[3]);
                sl0 += p0 + p1;
                sl1 += p2 + p3;
                const int col = ni * 8 + (lc << 1);
                *(float2*)&Prow0[col] = make_float2(p0, p1);
                *(float2*)&Prow1[col] = make_float2(p2, p3);
            }
            __syncwarp();
            #pragma unroll
            for (int k8 = 0; k8 < 16; k8++) {
                const int kc2 = (k8 << 3) + lc;
                u32 a0 = __float_as_uint(Prow0[kc2]);
                u32 a1 = __float_as_uint(Prow1[kc2]);
                u32 a2 = __float_as_uint(Prow0[kc2 + 4]);
                u32 a3 = __float_as_uint(Prow1[kc2 + 4]);
                const int kgb = kt * 128 + (k8 << 3) + (lc << 1);
                float2 va = *(const float2*)&sm[SM_V + (lr    ) * VSR + kgb];
                float2 vb = *(const float2*)&sm[SM_V + (lr + 8) * VSR + kgb];
                MMA_TF32(oacc[0], a0, a1, a2, a3,
                         __float_as_uint(va.x), __float_as_uint(va.y));
                MMA_TF32(oacc[1], a0, a1, a2, a3,
                         __float_as_uint(vb.x), __float_as_uint(vb.y));
            }
            __syncwarp();
        }

        float s0 = sl0, s1 = sl1;
        s0 += __shfl_xor_sync(0xffffffffu, s0, 1);
        s0 += __shfl_xor_sync(0xffffffffu, s0, 2);
        s1 += __shfl_xor_sync(0xffffffffu, s1, 1);
        s1 += __shfl_xor_sync(0xffffffffu, s1, 2);
        const float i0 = 1.f / s0, i1 = 1.f / s1;

        const long r0 = (long)(b * SS + qt * 128 + wq + lr);
        const long r1 = r0 + 8;
        #pragma unroll
        for (int t = 0; t < 2; t++) {
            const int col = h * HD + t * 8 + (lc << 1);
            float w0 = oacc[t][0] * i0, w1 = oacc[t][1] * i0;
            float w2 = oacc[t][2] * i1, w3 = oacc[t][3] * i1;
            float bb0 = tf32f(w0), bb1 = tf32f(w1), bb2 = tf32f(w2), bb3 = tf32f(w3);
            *(float2*)&oB[r0 * DD + col] = make_float2(bb0, bb1);
            *(float2*)&oB[r1 * DD + col] = make_float2(bb2, bb3);
            *(float2*)&oS[r0 * DD + col] = make_float2(tf32f(w0 - bb0), tf32f(w1 - bb1));
            *(float2*)&oS[r1 * DD + col] = make_float2(tf32f(w2 - bb2), tf32f(w3 - bb3));
        }
    }
}

// ============================================================================
// FUSED final: pre2 (in registers) = ypart0+ypart1+h+gate·b2, norm-2 stats,
// software grid-sync (128 blocks, all co-resident), norm-2 apply -> out.
// Counters reset at end for graph-replay determinism.
// ============================================================================
__global__ void __launch_bounds__(256) add_norm2(
    const float* __restrict__ yp, const float* __restrict__ h,
    const float* __restrict__ gates, const float* __restrict__ b2,
    const float* __restrict__ n2w, const float* __restrict__ n2b,
    float* __restrict__ part, float* __restrict__ out)
{
    const int b = blockIdx.y, chunk = blockIdx.x;
    __shared__ float b2s[NE * DD];
    b2s[threadIdx.x] = b2[threadIdx.x];
    b2s[threadIdx.x + 256] = b2[threadIdx.x + 256];
    __syncthreads();
    const long row0 = (long)b * SS + chunk * 64;
    const int c4 = threadIdx.x & 31, rg = threadIdx.x >> 5;
    const int c0 = c4 << 2;

    float4 vals[8];
    float4 s = make_float4(0.f, 0.f, 0.f, 0.f), q = s;
    #pragma unroll
    for (int i = 0; i < 8; i++) {
        const int r = rg + i * 8;
        const long tok = row0 + r;
        const long idx = tok * DD + c0;
        const float* g = gates + tok * NE;
        const float g0 = g[0], g1 = g[1], g2 = g[2], g3 = g[3];
        float4 v  = *(const float4*)(yp + idx);
        float4 v1 = *(const float4*)(yp + (long)NTOK * DD + idx);
        float4 hv = *(const float4*)(h + idx);
        float4 o;
        o.x = v.x + v1.x + hv.x
            + g0 * b2s[c0 + 0] + g1 * b2s[DD + c0 + 0] + g2 * b2s[2 * DD + c0 + 0] + g3 * b2s[3 * DD + c0 + 0];
        o.y = v.y + v1.y + hv.y
            + g0 * b2s[c0 + 1] + g1 * b2s[DD + c0 + 1] + g2 * b2s[2 * DD + c0 + 1] + g3 * b2s[3 * DD + c0 + 1];
        o.z = v.z + v1.z + hv.z
            + g0 * b2s[c0 + 2] + g1 * b2s[DD + c0 + 2] + g2 * b2s[2 * DD + c0 + 2] + g3 * b2s[3 * DD + c0 + 2];
        o.w = v.w + v1.w + hv.w
            + g0 * b2s[c0 + 3] + g1 * b2s[DD + c0 + 3] + g2 * b2s[2 * DD + c0 + 3] + g3 * b2s[3 * DD + c0 + 3];
        vals[i] = o;
        s.x += o.x; s.y += o.y; s.z += o.z; s.w += o.w;
        q.x += o.x * o.x; q.y += o.y * o.y; q.z += o.z * o.z; q.w += o.w * o.w;
    }
    __shared__ float4 sS[8][32], sQ[8][32];
    sS[rg][c4] = s; sQ[rg][c4] = q;
    __syncthreads();
    if (threadIdx.x < 32) {
        float4 ts = make_float4(0.f, 0.f, 0.f, 0.f), tq = ts;
        #pragma unroll
        for (int i = 0; i < 8; i++) {
            float4 a = sS[i][threadIdx.x], bq = sQ[i][threadIdx.x];
            ts.x += a.x; ts.y += a.y; ts.z += a.z; ts.w += a.w;
            tq.x += bq.x; tq.y += bq.y; tq.z += bq.z; tq.w += bq.w;
        }
        float* p = part + (long)(b * 16 + chunk) * 256;
        *(float4*)(p + (threadIdx.x << 2)) = ts;
        *(float4*)(p + 128 + (threadIdx.x << 2)) = tq;
    }
    __syncthreads();
    __threadfence();

    __shared__ int lastS;
    if (threadIdx.x == 0)
        lastS = (atomicAdd(&g_cnt1, 1) == 127);
    __syncthreads();

    if (lastS) {
        // this block computes all batches' scale/shift
        if (threadIdx.x < DD) {
            const int d = threadIdx.x;
            for (int bb = 0; bb < BB; bb++) {
                float ss = 0.f, qq = 0.f;
                for (int c = 0; c < 16; c++) {
                    const float* p = part + (long)(bb * 16 + c) * 256;
                    ss += p[d]; qq += p[128 + d];
                }
                float mean = ss * (1.f / 1024.f);
                float var  = qq * (1.f / 1024.f) - mean * mean;
                float inv  = rsqrtf(var + 1e-5f);
                float sc = n2w[d] * inv;
                g_nrm[bb * 256 + d]       = sc;
                g_nrm[bb * 256 + 128 + d] = n2b[d] - mean * sc;
            }
        }
        __threadfence();
        __syncthreads();
        if (threadIdx.x == 0)
            atomicExch(&g_flag, 1);
    } else {
        if (threadIdx.x == 0)
            while (atomicAdd(&g_flag, 0) == 0) { }
        __syncthreads();
        __threadfence();
    }

    float sc[4], sf[4];
    #pragma unroll
    for (int jj = 0; jj < 4; jj++) {
        sc[jj] = g_nrm[b * 256 + c0 + jj];
        sf[jj] = g_nrm[b * 256 + 128 + c0 + jj];
    }
    #pragma unroll
    for (int i = 0; i < 8; i++) {
        const int r = rg + i * 8;
        float4 o = vals[i];
        o.x = o.x * sc[0] + sf[0];
        o.y = o.y * sc[1] + sf[1];
        o.z = o.z * sc[2] + sf[2];
        o.w = o.w * sc[3] + sf[3];
        *(float4*)(out + (row0 + r) * DD + c0) = o;
    }

    // reset counters for next invocation (graph replay)
    __threadfence();
    __syncthreads();
    if (threadIdx.x == 0) {
        if (atomicAdd(&g_cnt2, 1) == 127) {
            g_cnt1 = 0;
            g_cnt2 = 0;
            g_flag = 0;
        }
    }
}

// ============================================================================
// Launch (6 kernels)
// ============================================================================
extern "C" void kernel_launch(void* const* d_in, const int* in_sizes, int n_in,
                              void* d_out, int out_size)
{
    const float* x     = (const float*)d_in[0];
    const float* Wqkv  = (const float*)d_in[1];
    const float* bqkv  = (const float*)d_in[2];
    const float* Wo    = (const float*)d_in[3];
    const float* bo    = (const float*)d_in[4];
    const float* n1w   = (const float*)d_in[5];
    const float* n1b   = (const float*)d_in[6];
    const float* n2w   = (const float*)d_in[7];
    const float* n2b   = (const float*)d_in[8];
    const float* wg    = (const float*)d_in[9];
    const float* W1    = (const float*)d_in[10];
    const float* b1    = (const float*)d_in[11];
    const float* W2    = (const float*)d_in[12];
    const float* b2    = (const float*)d_in[13];

    float *qkv, *oB, *oS, *pre1, *h, *gates, *ypart;
    float *wqkvB, *woB, *woS, *part;
    __nv_bfloat16 *w1bf, *w2bf;
    cudaGetSymbolAddress((void**)&qkv,   g_qkv);
    cudaGetSymbolAddress((void**)&oB,    g_oB);
    cudaGetSymbolAddress((void**)&oS,    g_oS);
    cudaGetSymbolAddress((void**)&pre1,  g_pre1);
    cudaGetSymbolAddress((void**)&h,     g_h);
    cudaGetSymbolAddress((void**)&gates, g_gates);
    cudaGetSymbolAddress((void**)&ypart, g_ypart);
    cudaGetSymbolAddress((void**)&w1bf,  g_w1bf);
    cudaGetSymbolAddress((void**)&w2bf,  g_w2bf);
    cudaGetSymbolAddress((void**)&wqkvB, g_wqkvB);
    cudaGetSymbolAddress((void**)&woB,   g_woB);
    cudaGetSymbolAddress((void**)&woS,   g_woS);
    cudaGetSymbolAddress((void**)&part,  g_part);

    cudaFuncSetAttribute(attn_mma, cudaFuncAttributeMaxDynamicSharedMemorySize, ATTN_SMEM);
    cudaFuncSetAttribute(gemm_mma3<0>, cudaFuncAttributeMaxDynamicSharedMemorySize, 30720);
    cudaFuncSetAttribute(gemm_mma3<1>, cudaFuncAttributeMaxDynamicSharedMemorySize, 61440);
    cudaFuncSetAttribute(moe_fused, cudaFuncAttributeMaxDynamicSharedMemorySize, MOE_SMEM);

    // 0. Merged weight prep (x consumed raw by QKV)
    weight_prep<<<576, 256>>>(Wqkv, Wo, W1, W2, wqkvB, woB, woS, w1bf, w2bf);

    // 1. QKV projection (1xTF32; A = raw fp32 x, HW-truncated to tf32)
    gemm_mma3<0><<<dim3(3, 128), 256, 30720>>>(x, nullptr, wqkvB, nullptr,
                                               bqkv, nullptr, qkv,
                                               128, 128, 384, 8, 0, nullptr);

    // 2. MMA flash attention (exp2-folded)
    attn_mma<<<dim3(64, 2), 256, ATTN_SMEM>>>(qkv, oB, oS);

    // 3. O-projection + bo + residual x ⊕ norm-1 stats (3xTF32, routing-critical)
    gemm_mma3<1><<<dim3(1, 128), 256, 61440>>>(oB, oS, woB, woS, bo, x, pre1,
                                               128, 128, 128, 8, 128, part);

    // 4. FUSED MoE ⊕ norm-1 apply ⊕ gating
    moe_fused<<<dim3(128, 2), 256, MOE_SMEM>>>(pre1, part, n1w, n1b, wg,
                                               w1bf, w2bf, b1, h, gates, ypart);

    // 5. FUSED final: add + norm-2 stats + grid-sync + norm-2 apply -> output
    add_norm2<<<dim3(16, 8), 256>>>(ypart, h, gates, b2, n2w, n2b,
                                    part, (float*)d_out);
}

// round 15
// speedup vs baseline: 1.3324x; 1.0341x over previous
#include <cuda_runtime.h>
#include <cuda_bf16.h>

typedef unsigned long long ull;
typedef unsigned int u32;

// ===================== helpers =======================
__device__ __forceinline__ u32 f2tf32(float x) {
    u32 u; asm("cvt.rna.tf32.f32 %0, %1;" : "=r"(u) : "f"(x)); return u;
}
__device__ __forceinline__ float tf32f(float x) {
    return __uint_as_float(f2tf32(x));
}
__device__ __forceinline__ float ex2f(float x) {
    float r; asm("ex2.approx.f32 %0, %1;" : "=f"(r) : "f"(x)); return r;
}
#define MMA_TF32(acc, a0, a1, a2, a3, b0, b1) \
    asm volatile( \
        "mma.sync.aligned.m16n8k8.row.col.f32.tf32.tf32.f32 " \
        "{%0,%1,%2,%3}, {%4,%5,%6,%7}, {%8,%9}, {%0,%1,%2,%3};" \
        : "+f"((acc)[0]), "+f"((acc)[1]), "+f"((acc)[2]), "+f"((acc)[3]) \
        : "r"(a0), "r"(a1), "r"(a2), "r"(a3), "r"(b0), "r"(b1))

#define MMA_BF16(acc, a, b0, b1) \
    asm volatile( \
        "mma.sync.aligned.m16n8k16.row.col.f32.bf16.bf16.f32 " \
        "{%0,%1,%2,%3}, {%4,%5,%6,%7}, {%8,%9}, {%0,%1,%2,%3};" \
        : "+f"((acc)[0]), "+f"((acc)[1]), "+f"((acc)[2]), "+f"((acc)[3]) \
        : "r"((a)[0]), "r"((a)[1]), "r"((a)[2]), "r"((a)[3]), "r"(b0), "r"(b1))

__device__ __forceinline__ void ldsm4(u32* r, u32 addr) {
    asm volatile("ldmatrix.sync.aligned.m8n8.x4.shared.b16 {%0,%1,%2,%3}, [%4];"
        : "=r"(r[0]), "=r"(r[1]), "=r"(r[2]), "=r"(r[3]) : "r"(addr));
}
__device__ __forceinline__ void cpa16(u32 dst, const void* src) {
    asm volatile("cp.async.cg.shared.global [%0], [%1], 16;" :: "r"(dst), "l"(src));
}

// ===================== problem constants ====================================
#define BB    8
#define SS    1024
#define DD    128
#define NH    8
#define HD    16
#define NTOK  8192
#define HFF   512
#define NE    4

// ===================== scratch ==============================================
__device__ float         g_qkv  [NTOK * 384];
__device__ float         g_oB   [NTOK * DD];
__device__ float         g_oS   [NTOK * DD];
__device__ float         g_pre1 [NTOK * DD];
__device__ float         g_h    [NTOK * DD];
__device__ float         g_gates[NTOK * NE];
__device__ float         g_ypart[2 * NTOK * DD];
__device__ __nv_bfloat16 g_w1bf [NE * HFF * DD];
__device__ __nv_bfloat16 g_w2bf [DD * NE * HFF];
__device__ float         g_wqkvB[384 * DD];
__device__ float         g_woB  [DD * DD];
__device__ float         g_woS  [DD * DD];
__device__ float         g_part [128 * 256];
__device__ float         g_nrm  [BB * 256];
__device__ int           g_cntB [BB];
__device__ int           g_flagB[BB];
__device__ int           g_cnt2 = 0;

// ============================================================================
// Prep: Wqkv transpose only (needed by the QKV gemm that follows immediately).
// ============================================================================
__global__ void __launch_bounds__(256) weight_prep(
    const float* __restrict__ Wqkv, float* __restrict__ wqkvB)
{
    __shared__ float t[32][33];
    const int bid = blockIdx.x;
    const int c0 = (bid % 12) << 5, r0 = (bid / 12) << 5;
    for (int i = threadIdx.x; i < 1024; i += 256) {
        const int r = i >> 5, c = i & 31;
        t[r][c] = Wqkv[(long)(r0 + r) * 384 + c0 + c];
    }
    __syncthreads();
    for (int i = threadIdx.x; i < 1024; i += 256) {
        const int c = i >> 5, r = i & 31;
        wqkvB[(long)(c0 + c) * 128 + r0 + r] = tf32f(t[r][c]);
    }
}

// ============================================================================
// FUSED QKV gemm (1xTF32) + Wo/W1/W2 transposes on spare blocks.
// 1D grid of 912 blocks: [0,384) gemm tiles; [384,912) transposes (overlap).
// ============================================================================
__global__ void __launch_bounds__(256) qkv_fused(
    const float* __restrict__ A, const float* __restrict__ Bb,
    const float* __restrict__ bias, float* __restrict__ C,
    const float* __restrict__ Wo, const float* __restrict__ W1,
    const float* __restrict__ W2,
    float* __restrict__ woB, float* __restrict__ woS,
    __nv_bfloat16* __restrict__ w1bf, __nv_bfloat16* __restrict__ w2bf)
{
    extern __shared__ float dynsm[];
    const int tid = threadIdx.x;

    if (blockIdx.x >= 384) {
        // ---------------- transpose path ----------------
        int bid = blockIdx.x - 384;
        float (*t)[33] = (float(*)[33])dynsm;
        const float* src; int R, C2, c0, r0, mode;
        float *dB = 0, *dS = 0; __nv_bfloat16* dH = 0;
        if (bid < 16) {
            src = Wo; R = 128; C2 = 128; mode = 0;
            c0 = (bid & 3) << 5; r0 = (bid >> 2) << 5;
            dB = woB; dS = woS;
        } else if (bid < 272) {
            bid -= 16;
            const int e = bid >> 6, rem = bid & 63;
            src = W1 + (long)e * 128 * 512; R = 128; C2 = 512; mode = 1;
            c0 = (rem & 15) << 5; r0 = (rem >> 4) << 5;
            dH = w1bf + (long)e * 512 * 128;
        } else {
            bid -= 272; src = W2; R = 2048; C2 = 128; mode = 1;
            c0 = (bid & 3) << 5; r0 = (bid >> 2) << 5;
            dH = w2bf;
        }
        for (int i = tid; i < 1024; i += 256) {
            const int r = i >> 5, c = i & 31;
            t[r][c] = src[(long)(r0 + r) * C2 + c0 + c];
        }
        __syncthreads();
        for (int i = tid; i < 1024; i += 256) {
            const int c = i >> 5, r = i & 31;
            const float v = t[r][c];
            const long o = (long)(c0 + c) * R + r0 + r;
            if (mode == 0) {
                const u32 big = f2tf32(v);
                dB[o] = __uint_as_float(big);
                dS[o] = __uint_as_float(f2tf32(v - __uint_as_float(big)));
            } else {
                dH[o] = __float2bfloat16(v);
            }
        }
        return;
    }

    // ---------------- 1xTF32 gemm path (BM=64, BN=128, BK=16) ----------------
    const u32 smu = (u32)__cvta_generic_to_shared(dynsm);
    const int wid = tid >> 5, lane = tid & 31;
    const int n0 = (blockIdx.x % 3) << 7, m0 = (blockIdx.x / 3) << 6;
    const int wm = wid >> 2, wn = wid & 3;
    const int lr = lane >> 2, lc = lane & 3;
    const int lda = 128, ldb = 128, ldc = 384;

    const float* Abase = A  + (long)m0 * lda;
    const float* Bbase = Bb + (long)n0 * ldb;

    float acc[2][4][4];
    #pragma unroll
    for (int mi = 0; mi < 2; mi++)
        #pragma unroll
        for (int ni = 0; ni < 4; ni++)
            #pragma unroll
            for (int j = 0; j < 4; j++) acc[mi][ni][j] = 0.f;

#define QSTAGE(KT, S) do { \
    const int _k0 = (KT) << 4; \
    const u32 _sb = smu + (S) * 15360u; \
    { \
        const int row = tid >> 2, ch = (tid & 3) << 2; \
        cpa16(_sb + (u32)(row * 20 + ch) * 4, Abase + (long)row * lda + _k0 + ch); \
    } \
    _Pragma("unroll") \
    for (int c = 0; c < 2; c++) { \
        const int idx = tid + (c << 8); \
        const int row = idx >> 2, ch = (idx & 3) << 2; \
        cpa16(_sb + 5120u + (u32)(row * 20 + ch) * 4, Bbase + (long)row * ldb + _k0 + ch); \
    } \
    asm volatile("cp.async.commit_group;" ::: "memory"); \
} while (0)

    QSTAGE(0, 0);
    for (int kt = 0; kt < 8; kt++) {
        const int s = kt & 1;
        if (kt + 1 < 8) {
            QSTAGE(kt + 1, (kt + 1) & 1);
            asm volatile("cp.async.wait_group 1;" ::: "memory");
        } else {
            asm volatile("cp.async.wait_group 0;" ::: "memory");
        }
        __syncthreads();
        float* AbP = dynsm + s * 3840;
        float* BsP = AbP + 1280;
        #pragma unroll
        for (int k8 = 0; k8 < 2; k8++) {
            const int kc = (k8 << 3) + lc;
            u32 af[2][4];
            #pragma unroll
            for (int mi = 0; mi < 2; mi++) {
                const int r = wm * 32 + mi * 16 + lr;
                af[mi][0] = __float_as_uint(AbP[(r    ) * 20 + kc    ]);
                af[mi][1] = __float_as_uint(AbP[(r + 8) * 20 + kc    ]);
                af[mi][2] = __float_as_uint(AbP[(r    ) * 20 + kc + 4]);
                af[mi][3] = __float_as_uint(AbP[(r + 8) * 20 + kc + 4]);
            }
            #pragma unroll
            for (int ni = 0; ni < 4; ni++) {
                const int nr = wn * 32 + ni * 8 + lr;
                u32 b0 = __float_as_uint(BsP[nr * 20 + kc    ]);
                u32 b1 = __float_as_uint(BsP[nr * 20 + kc + 4]);
                #pragma unroll
                for (int mi = 0; mi < 2; mi++)
                    MMA_TF32(acc[mi][ni], af[mi][0], af[mi][1], af[mi][2], af[mi][3], b0, b1);
            }
        }
        __syncthreads();
    }
#undef QSTAGE

    #pragma unroll
    for (int mi = 0; mi < 2; mi++) {
        const int r0 = m0 + wm * 32 + mi * 16 + lr;
        const int r1 = r0 + 8;
        #pragma unroll
        for (int ni = 0; ni < 4; ni++) {
            const int col = wn * 32 + ni * 8 + (lc << 1);
            float2 bbv = *(const float2*)&bias[n0 + col];
            float v0 = acc[mi][ni][0] + bbv.x, v1 = acc[mi][ni][1] + bbv.y;
            float v2 = acc[mi][ni][2] + bbv.x, v3 = acc[mi][ni][3] + bbv.y;
            *(float2*)&C[(long)r0 * ldc + n0 + col] = make_float2(v0, v1);
            *(float2*)&C[(long)r1 * ldc + n0 + col] = make_float2(v2, v3);
        }
    }
}

// ============================================================================
// 3xTF32 mma GEMM for O-proj (unchanged from round 14, X3=1 only).
// ============================================================================
__global__ void __launch_bounds__(256) gemm_mma3(
    const float* __restrict__ Ab, const float* __restrict__ As,
    const float* __restrict__ Bb, const float* __restrict__ Bsm,
    const float* __restrict__ bias, const float* __restrict__ resid,
    float* __restrict__ C,
    int lda, int ldb, int ldc, int Kt, int ldres, float* __restrict__ part)
{
    extern __shared__ float dynsm[];
    const u32 smu = (u32)__cvta_generic_to_shared(dynsm);

    const int tid = threadIdx.x, wid = tid >> 5, lane = tid & 31;
    const int m0 = blockIdx.y << 6, n0 = blockIdx.x << 7;
    const int wm = wid >> 2, wn = wid & 3;
    const int lr = lane >> 2, lc = lane & 3;

    const float* Abase  = Ab  + (long)m0 * lda;
    const float* Asbase = As  + (long)m0 * lda;
    const float* Bbase  = Bb  + (long)n0 * ldb;
    const float* Bsbase = Bsm + (long)n0 * ldb;

    float acc[2][4][4];
    #pragma unroll
    for (int mi = 0; mi < 2; mi++)
        #pragma unroll
        for (int ni = 0; ni < 4; ni++)
            #pragma unroll
            for (int j = 0; j < 4; j++) acc[mi][ni][j] = 0.f;

#define STAGE3(KT, S) do { \
    const int _k0 = (KT) << 4; \
    const u32 _sb = smu + (S) * 30720u; \
    { \
        const int row = tid >> 2, ch = (tid & 3) << 2; \
        const u32 off = (u32)(row * 20 + ch) * 4; \
        cpa16(_sb + off,         Abase  + (long)row * lda + _k0 + ch); \
        cpa16(_sb + 5120 + off,  Asbase + (long)row * lda + _k0 + ch); \
    } \
    _Pragma("unroll") \
    for (int c = 0; c < 2; c++) { \
        const int idx = tid + (c << 8); \
        const int row = idx >> 2, ch = (idx & 3) << 2; \
        const u32 off = (u32)(row * 20 + ch) * 4; \
        cpa16(_sb + 10240 + off, Bbase  + (long)row * ldb + _k0 + ch); \
        cpa16(_sb + 20480 + off, Bsbase + (long)row * ldb + _k0 + ch); \
    } \
    asm volatile("cp.async.commit_group;" ::: "memory"); \
} while (0)

    STAGE3(0, 0);
    for (int kt = 0; kt < Kt; kt++) {
        const int s = kt & 1;
        if (kt + 1 < Kt) {
            STAGE3(kt + 1, (kt + 1) & 1);
            asm volatile("cp.async.wait_group 1;" ::: "memory");
        } else {
            asm volatile("cp.async.wait_group 0;" ::: "memory");
        }
        __syncthreads();
        float* AbP = dynsm + s * 7680;
        float* AmP = AbP + 1280;
        float* BsP = AbP + 2560;
        float* BmP = AbP + 5120;
        #pragma unroll
        for (int k8 = 0; k8 < 2; k8++) {
            const int kc = (k8 << 3) + lc;
            u32 af[2][4], am[2][4];
            #pragma unroll
            for (int mi = 0; mi < 2; mi++) {
                const int r = wm * 32 + mi * 16 + lr;
                af[mi][0] = __float_as_uint(AbP[(r    ) * 20 + kc    ]);
                af[mi][1] = __float_as_uint(AbP[(r + 8) * 20 + kc    ]);
                af[mi][2] = __float_as_uint(AbP[(r    ) * 20 + kc + 4]);
                af[mi][3] = __float_as_uint(AbP[(r + 8) * 20 + kc + 4]);
                am[mi][0] = __float_as_uint(AmP[(r    ) * 20 + kc    ]);
                am[mi][1] = __float_as_uint(AmP[(r + 8) * 20 + kc    ]);
                am[mi][2] = __float_as_uint(AmP[(r    ) * 20 + kc + 4]);
                am[mi][3] = __float_as_uint(AmP[(r + 8) * 20 + kc + 4]);
            }
            #pragma unroll
            for (int ni = 0; ni < 4; ni++) {
                const int nr = wn * 32 + ni * 8 + lr;
                u32 b0 = __float_as_uint(BsP[nr * 20 + kc    ]);
                u32 b1 = __float_as_uint(BsP[nr * 20 + kc + 4]);
                u32 s0 = __float_as_uint(BmP[nr * 20 + kc    ]);
                u32 s1 = __float_as_uint(BmP[nr * 20 + kc + 4]);
                #pragma unroll
                for (int mi = 0; mi < 2; mi++) {
                    MMA_TF32(acc[mi][ni], am[mi][0], am[mi][1], am[mi][2], am[mi][3], b0, b1);
                    MMA_TF32(acc[mi][ni], af[mi][0], af[mi][1], af[mi][2], af[mi][3], s0, s1);
                    MMA_TF32(acc[mi][ni], af[mi][0], af[mi][1], af[mi][2], af[mi][3], b0, b1);
                }
            }
        }
        __syncthreads();
    }
#undef STAGE3

    float s8[8], q8[8];
    #pragma unroll
    for (int i = 0; i < 8; i++) { s8[i] = 0.f; q8[i] = 0.f; }

    #pragma unroll
    for (int mi = 0; mi < 2; mi++) {
        const int r0 = m0 + wm * 32 + mi * 16 + lr;
        const int r1 = r0 + 8;
        #pragma unroll
        for (int ni = 0; ni < 4; ni++) {
            const int col = wn * 32 + ni * 8 + (lc << 1);
            float v0 = acc[mi][ni][0], v1 = acc[mi][ni][1];
            float v2 = acc[mi][ni][2], v3 = acc[mi][ni][3];
            if (bias) {
                float2 bbv = *(const float2*)&bias[n0 + col];
                v0 += bbv.x; v1 += bbv.y; v2 += bbv.x; v3 += bbv.y;
            }
            if (resid) {
                float2 ra = *(const float2*)&resid[(long)r0 * ldres + n0 + col];
                float2 rb = *(const float2*)&resid[(long)r1 * ldres + n0 + col];
                v0 += ra.x; v1 += ra.y; v2 += rb.x; v3 += rb.y;
            }
            *(float2*)&C[(long)r0 * ldc + n0 + col] = make_float2(v0, v1);
            *(float2*)&C[(long)r1 * ldc + n0 + col] = make_float2(v2, v3);
            if (part) {
                s8[ni * 2 + 0] += v0 + v2;
                s8[ni * 2 + 1] += v1 + v3;
                q8[ni * 2 + 0] += v0 * v0 + v2 * v2;
                q8[ni * 2 + 1] += v1 * v1 + v3 * v3;
            }
        }
    }

    if (part) {
        #pragma unroll
        for (int i = 0; i < 8; i++) {
            s8[i] += __shfl_xor_sync(0xffffffffu, s8[i], 4);
            s8[i] += __shfl_xor_sync(0xffffffffu, s8[i], 8);
            s8[i] += __shfl_xor_sync(0xffffffffu, s8[i], 16);
            q8[i] += __shfl_xor_sync(0xffffffffu, q8[i], 4);
            q8[i] += __shfl_xor_sync(0xffffffffu, q8[i], 8);
            q8[i] += __shfl_xor_sync(0xffffffffu, q8[i], 16);
        }
        float* ssum = dynsm;
        float* ssq  = dynsm + 256;
        __syncthreads();
        if (lr == 0) {
            #pragma unroll
            for (int i = 0; i < 8; i++) {
                const int col = wn * 32 + (i >> 1) * 8 + (lc << 1) + (i & 1);
                ssum[wm * 128 + col] = s8[i];
                ssq [wm * 128 + col] = q8[i];
            }
        }
        __syncthreads();
        if (tid < 128) {
            part[blockIdx.y * 256 + tid]       = ssum[tid] + ssum[128 + tid];
            part[blockIdx.y * 256 + 128 + tid] = ssq[tid]  + ssq[128 + tid];
        }
    }
}

// ============================================================================
// FUSED MoE + norm-1 apply + gating (unchanged from round 14).
// ============================================================================
#define SA_OFF  0u
#define SW1_OFF 17408u
#define SW2_OFF 52224u
#define SH_OFF  89088u
#define MOE_SMEM 107520

__global__ void __launch_bounds__(256) moe_fused(
    const float* __restrict__ pre1, const float* __restrict__ part,
    const float* __restrict__ n1w, const float* __restrict__ n1b,
    const float* __restrict__ wg,
    const __nv_bfloat16* __restrict__ w1bf, const __nv_bfloat16* __restrict__ w2bf,
    const float* __restrict__ b1,
    float* __restrict__ hout, float* __restrict__ gatesOut,
    float* __restrict__ ypart)
{
    extern __shared__ char msm[];
    const u32 smu = (u32)__cvta_generic_to_shared(msm);

    const int tid = threadIdx.x, wid = tid >> 5, lane = tid & 31;
    const int lr = lane >> 2, lc = lane & 3, sel = lane >> 3;
    const int wm = wid >> 1, wn = wid & 1;
    const int m0 = blockIdx.x << 6;
    const int e0 = blockIdx.y << 1;
    const int b  = m0 >> 10;

#define MSTAGE(IT, S) do { \
    const int _e = e0 + ((IT) >> 3), _c = (IT) & 7; \
    const __nv_bfloat16* _w1 = w1bf + (long)((_e << 9) + (_c << 6)) * 128; \
    const __nv_bfloat16* _w2 = w2bf + (_e << 9) + (_c << 6); \
    _Pragma("unroll") \
    for (int j = 0; j < 4; j++) { \
        const int idx = tid + (j << 8); \
        const int r1 = idx >> 4, ch1 = (idx & 15) << 3; \
        cpa16(smu + SW1_OFF + (S) * 17408u + (u32)(r1 * 136 + ch1) * 2, \
              _w1 + (long)r1 * 128 + ch1); \
        const int r2 = idx >> 3, ch2 = (idx & 7) << 3; \
        cpa16(smu + SW2_OFF + (S) * 18432u + (u32)(r2 * 72 + ch2) * 2, \
              _w2 + (long)r2 * 2048 + ch2); \
    } \
    asm volatile("cp.async.commit_group;" ::: "memory"); \
} while (0)

    MSTAGE(0, 0);

    float* ovl    = (float*)(msm + SW1_OFF + 17408u);
    float* scA    = ovl;
    float* sfA    = ovl + 128;
    float* wgS    = ovl + 256;
    float* gatesS = ovl + 768;
    wgS[tid] = wg[tid];
    wgS[tid + 256] = wg[tid + 256];
    if (tid < DD) {
        const int d = tid;
        float s = 0.f, q = 0.f;
        for (int c = 0; c < 16; c++) {
            const float* p = part + (long)(b * 16 + c) * 256;
            s += p[d]; q += p[DD + d];
        }
        float mean = s * (1.f / 1024.f);
        float var  = q * (1.f / 1024.f) - mean * mean;
        float inv  = rsqrtf(var + 1e-5f);
        float scale = n1w[d] * inv;
        scA[d] = scale;
        sfA[d] = n1b[d] - mean * scale;
    }
    __syncthreads();

    {
        const int c4 = tid & 31, rg = tid >> 5;
        const int c0 = c4 << 2;
        for (int r = rg; r < 64; r += 8) {
            const long tok = m0 + r;
            float4 v = *(const float4*)(pre1 + tok * DD + c0);
            float4 o;
            o.x = v.x * scA[c0 + 0] + sfA[c0 + 0];
            o.y = v.y * scA[c0 + 1] + sfA[c0 + 1];
            o.z = v.z * scA[c0 + 2] + sfA[c0 + 2];
            o.w = v.w * scA[c0 + 3] + sfA[c0 + 3];
            if (e0 == 0) *(float4*)(hout + tok * DD + c0) = o;
            __nv_bfloat162 p0 = __floats2bfloat162_rn(o.x, o.y);
            __nv_bfloat162 p1 = __floats2bfloat162_rn(o.z, o.w);
            asm volatile("st.shared.v2.b32 [%0], {%1, %2};" ::
                "r"(smu + SA_OFF + (u32)(r * 136 + c0) * 2),
                "r"(*(u32*)&p0), "r"(*(u32*)&p1));
            float l0 = o.x * wgS[(c0 + 0) * NE + 0] + o.y * wgS[(c0 + 1) * NE + 0]
                     + o.z * wgS[(c0 + 2) * NE + 0] + o.w * wgS[(c0 + 3) * NE + 0];
            float l1 = o.x * wgS[(c0 + 0) * NE + 1] + o.y * wgS[(c0 + 1) * NE + 1]
                     + o.z * wgS[(c0 + 2) * NE + 1] + o.w * wgS[(c0 + 3) * NE + 1];
            float l2 = o.x * wgS[(c0 + 0) * NE + 2] + o.y * wgS[(c0 + 1) * NE + 2]
                     + o.z * wgS[(c0 + 2) * NE + 2] + o.w * wgS[(c0 + 3) * NE + 2];
            float l3 = o.x * wgS[(c0 + 0) * NE + 3] + o.y * wgS[(c0 + 1) * NE + 3]
                     + o.z * wgS[(c0 + 2) * NE + 3] + o.w * wgS[(c0 + 3) * NE + 3];
            #pragma unroll
            for (int off = 16; off; off >>= 1) {
                l0 += __shfl_xor_sync(0xffffffffu, l0, off);
                l1 += __shfl_xor_sync(0xffffffffu, l1, off);
                l2 += __shfl_xor_sync(0xffffffffu, l2, off);
                l3 += __shfl_xor_sync(0xffffffffu, l3, off);
            }
            if (c4 == 0) {
                float lg[4] = {l0, l1, l2, l3};
                int i1 = 0; float v1 = lg[0];
                #pragma unroll
                for (int e = 1; e < 4; e++) if (lg[e] > v1) { v1 = lg[e]; i1 = e; }
                int i2 = 0; float v2 = -3e38f;
                #pragma unroll
                for (int e = 0; e < 4; e++) if (e != i1 && lg[e] > v2) { v2 = lg[e]; i2 = e; }
                float e2  = expf(v2 - v1);
                float inv = 1.f / (1.f + e2);
                #pragma unroll
                for (int e = 0; e < 4; e++) {
                    const float gv = (e == i1) ? inv : ((e == i2) ? e2 * inv : 0.f);
                    gatesS[r * NE + e] = gv;
                    if (e0 == 0) gatesOut[tok * NE + e] = gv;
                }
            }
        }
    }
    __syncthreads();

    const int row0 = wm * 16 + lr;
    const float g00 = gatesS[(row0    ) * NE + e0];
    const float g01 = gatesS[(row0    ) * NE + e0 + 1];
    const float g10 = gatesS[(row0 + 8) * NE + e0];
    const float g11 = gatesS[(row0 + 8) * NE + e0 + 1];
    __syncthreads();

    const u32 aoff1 = (u32)((wm * 16 + (lane & 7) + ((sel & 1) << 3)) * 136
                            + ((sel >> 1) << 3)) * 2;
    u32 boff1[2];
    #pragma unroll
    for (int nb = 0; nb < 2; nb++)
        boff1[nb] = (u32)((wn * 32 + nb * 16 + ((sel >> 1) << 3) + (lane & 7)) * 136
                          + ((sel & 1) << 3)) * 2;
    const u32 aoff2 = (u32)((wm * 16 + (lane & 7) + ((sel & 1) << 3)) * 72
                            + ((sel >> 1) << 3)) * 2;
    u32 boff2[4];
    #pragma unroll
    for (int nb = 0; nb < 4; nb++)
        boff2[nb] = (u32)((wn * 64 + nb * 16 + ((sel >> 1) << 3) + (lane & 7)) * 72
                          + ((sel & 1) << 3)) * 2;

    float acc2[8][4];
    #pragma unroll
    for (int ni = 0; ni < 8; ni++)
        #pragma unroll
        for (int j = 0; j < 4; j++) acc2[ni][j] = 0.f;

    const int gtok0 = m0 + row0, gtok1 = gtok0 + 8;

    for (int it = 0; it < 16; it++) {
        const int s = it & 1;
        const int e = e0 + (it >> 3), c = it & 7;
        if (it + 1 < 16) {
            MSTAGE(it + 1, s ^ 1);
            asm volatile("cp.async.wait_group 1;" ::: "memory");
        } else {
            asm volatile("cp.async.wait_group 0;" ::: "memory");
        }
        __syncthreads();

        const u32 w1b = smu + SW1_OFF + s * 17408u;
        const u32 ab  = smu + SA_OFF;
        float acc1[4][4];
        #pragma unroll
        for (int ni = 0; ni < 4; ni++)
            #pragma unroll
            for (int j = 0; j < 4; j++) acc1[ni][j] = 0.f;
        #pragma unroll
        for (int k16 = 0; k16 < 8; k16++) {
            u32 a[4];
            ldsm4(a, ab + aoff1 + k16 * 32);
            #pragma unroll
            for (int nb = 0; nb < 2; nb++) {
                u32 bf[4];
                ldsm4(bf, w1b + boff1[nb] + k16 * 32);
                MMA_BF16(acc1[2 * nb    ], a, bf[0], bf[1]);
                MMA_BF16(acc1[2 * nb + 1], a, bf[2], bf[3]);
            }
        }
        const float g0 = (it >> 3) ? g01 : g00;
        const float g1 = (it >> 3) ? g11 : g10;
        const u32 hbse = smu + SH_OFF + s * 9216u;
        #pragma unroll
        for (int ni = 0; ni < 4; ni++) {
            const int col = wn * 32 + ni * 8 + (lc << 1);
            const float bb0 = __ldg(&b1[(e << 9) + (c << 6) + col]);
            const float bb1 = __ldg(&b1[(e << 9) + (c << 6) + col + 1]);
            float v0 = fmaxf(acc1[ni][0] + bb0, 0.f) * g0;
            float v1 = fmaxf(acc1[ni][1] + bb1, 0.f) * g0;
            float v2 = fmaxf(acc1[ni][2] + bb0, 0.f) * g1;
            float v3 = fmaxf(acc1[ni][3] + bb1, 0.f) * g1;
            __nv_bfloat162 p0 = __floats2bfloat162_rn(v0, v1);
            __nv_bfloat162 p1 = __floats2bfloat162_rn(v2, v3);
            asm volatile("st.shared.b32 [%0], %1;" ::
                "r"(hbse + (u32)(row0 * 72 + col) * 2), "r"(*(u32*)&p0));
            asm volatile("st.shared.b32 [%0], %1;" ::
                "r"(hbse + (u32)((row0 + 8) * 72 + col) * 2), "r"(*(u32*)&p1));
        }
        asm volatile("bar.sync %0, 64;" :: "r"(wm + 1) : "memory");

        const u32 w2b = smu + SW2_OFF + s * 18432u;
        #pragma unroll
        for (int k16 = 0; k16 < 4; k16++) {
            u32 a[4];
            ldsm4(a, hbse + aoff2 + k16 * 32);
            #pragma unroll
            for (int nb = 0; nb < 4; nb++) {
                u32 bf[4];
                ldsm4(bf, w2b + boff2[nb] + k16 * 32);
                MMA_BF16(acc2[2 * nb    ], a, bf[0], bf[1]);
                MMA_BF16(acc2[2 * nb + 1], a, bf[2], bf[3]);
            }
        }
        __syncthreads();
    }
#undef MSTAGE

    float* yz = ypart + (long)blockIdx.y * NTOK * DD;
    #pragma unroll
    for (int ni = 0; ni < 8; ni++) {
        const int col = wn * 64 + ni * 8 + (lc << 1);
        *(float2*)&yz[(long)gtok0 * DD + col] = make_float2(acc2[ni][0], acc2[ni][1]);
        *(float2*)&yz[(long)gtok1 * DD + col] = make_float2(acc2[ni][2], acc2[ni][3]);
    }
}

// ============================================================================
// MMA flash attention (unchanged from round 14).
// ============================================================================
#define VSR 1044
#define PSR 132
#define SM_K 0
#define SM_V (1024 * 16)
#define SM_P (SM_V + 16 * VSR)
#define ATTN_SMEM ((SM_P + 128 * PSR) * 4)

__global__ void __launch_bounds__(256) attn_mma(const float* __restrict__ qkv,
                                                float* __restrict__ oB,
                                                float* __restrict__ oS)
{
    extern __shared__ float sm[];
    const int bh = blockIdx.x, b = bh >> 3, h = bh & 7;
    const int tid = threadIdx.x, wid = tid >> 5, lane = tid & 31;
    const int lr = lane >> 2, lc = lane & 3;
    const float* qkvb = qkv + (long)b * SS * 384;
    const int qoff = h * HD, koff = DD + h * HD, voff = 2 * DD + h * HD;
    const float QSCL = 0.25f * 1.4426950408889634f;

    for (int i = tid; i < SS * 4; i += 256) {
        const int s = i >> 2, c4 = i & 3;
        float4 v = *(const float4*)(qkvb + (long)s * 384 + koff + (c4 << 2));
        float* kp = &sm[SM_K + (s << 4)];
        kp[c4]      = tf32f(v.x);
        kp[c4 + 4]  = tf32f(v.y);
        kp[c4 + 8]  = tf32f(v.z);
        kp[c4 + 12] = tf32f(v.w);
        float4 w = *(const float4*)(qkvb + (long)s * 384 + voff + (c4 << 2));
        const int colp = (s & ~7) + ((s & 3) << 1) + ((s & 7) >> 2);
        sm[SM_V + ((c4 << 2) + 0) * VSR + colp] = tf32f(w.x);
        sm[SM_V + ((c4 << 2) + 1) * VSR + colp] = tf32f(w.y);
        sm[SM_V + ((c4 << 2) + 2) * VSR + colp] = tf32f(w.z);
        sm[SM_V + ((c4 << 2) + 3) * VSR + colp] = tf32f(w.w);
    }
    __syncthreads();

    const int wq = wid << 4;
    float* Prow0 = &sm[SM_P + (wq + lr) * PSR];
    float* Prow1 = Prow0 + 8 * PSR;

    for (int j = 0; j < 4; j++) {
        const int qt = (blockIdx.y << 2) + j;

        const float* qp0 = qkvb + (long)(qt * 128 + wq + lr) * 384 + qoff;
        const float* qp1 = qp0 + 8 * 384;
        u32 qf[2][4];
        #pragma unroll
        for (int k8 = 0; k8 < 2; k8++) {
            const int c = (k8 << 3) + lc;
            qf[k8][0] = f2tf32(__ldg(&qp0[c])     * QSCL);
            qf[k8][1] = f2tf32(__ldg(&qp1[c])     * QSCL);
            qf[k8][2] = f2tf32(__ldg(&qp0[c + 4]) * QSCL);
            qf[k8][3] = f2tf32(__ldg(&qp1[c + 4]) * QSCL);
        }

        float oacc[2][4];
        #pragma unroll
        for (int t = 0; t < 2; t++)
            #pragma unroll
            for (int jj = 0; jj < 4; jj++) oacc[t][jj] = 0.f;
        float sl0 = 0.f, sl1 = 0.f;

        for (int kt = 0; kt < 8; kt++) {
            #pragma unroll
            for (int ni = 0; ni < 16; ni++) {
                const int krow = kt * 128 + ni * 8 + lr;
                float4 kv = *(const float4*)&sm[SM_K + (krow << 4) + (lc << 2)];
                float sacc[4] = {0.f, 0.f, 0.f, 0.f};
                MMA_TF32(sacc, qf[0][0], qf[0][1], qf[0][2], qf[0][3],
                         __float_as_uint(kv.x), __float_as_uint(kv.y));
                MMA_TF32(sacc, qf[1][0], qf[1][1], qf[1][2], qf[1][3],
                         __float_as_uint(kv.z), __float_as_uint(kv.w));
                const float p0 = ex2f(sacc[0]), p1 = ex2f(sacc[1]);
                const float p2 = ex2f(sacc[2]), p3 = ex2f(sacc[3]);
                sl0 += p0 + p1;
                sl1 += p2 + p3;
                const int col = ni * 8 + (lc << 1);
                *(float2*)&Prow0[col] = make_float2(p0, p1);
                *(float2*)&Prow1[col] = make_float2(p2, p3);
            }
            __syncwarp();
            #pragma unroll
            for (int k8 = 0; k8 < 16; k8++) {
                const int kc2 = (k8 << 3) + lc;
                u32 a0 = __float_as_uint(Prow0[kc2]);
                u32 a1 = __float_as_uint(Prow1[kc2]);
                u32 a2 = __float_as_uint(Prow0[kc2 + 4]);
                u32 a3 = __float_as_uint(Prow1[kc2 + 4]);
                const int kgb = kt * 128 + (k8 << 3) + (lc << 1);
                float2 va = *(const float2*)&sm[SM_V + (lr    ) * VSR + kgb];
                float2 vb = *(const float2*)&sm[SM_V + (lr + 8) * VSR + kgb];
                MMA_TF32(oacc[0], a0, a1, a2, a3,
                         __float_as_uint(va.x), __float_as_uint(va.y));
                MMA_TF32(oacc[1], a0, a1, a2, a3,
                         __float_as_uint(vb.x), __float_as_uint(vb.y));
            }
            __syncwarp();
        }

        float s0 = sl0, s1 = sl1;
        s0 += __shfl_xor_sync(0xffffffffu, s0, 1);
        s0 += __shfl_xor_sync(0xffffffffu, s0, 2);
        s1 += __shfl_xor_sync(0xffffffffu, s1, 1);
        s1 += __shfl_xor_sync(0xffffffffu, s1, 2);
        const float i0 = 1.f / s0, i1 = 1.f / s1;

        const long r0 = (long)(b * SS + qt * 128 + wq + lr);
        const long r1 = r0 + 8;
        #pragma unroll
        for (int t = 0; t < 2; t++) {
            const int col = h * HD + t * 8 + (lc << 1);
            float w0 = oacc[t][0] * i0, w1 = oacc[t][1] * i0;
            float w2 = oacc[t][2] * i1, w3 = oacc[t][3] * i1;
            float bb0 = tf32f(w0), bb1 = tf32f(w1), bb2 = tf32f(w2), bb3 = tf32f(w3);
            *(float2*)&oB[r0 * DD + col] = make_float2(bb0, bb1);
            *(float2*)&oB[r1 * DD + col] = make_float2(bb2, bb3);
            *(float2*)&oS[r0 * DD + col] = make_float2(tf32f(w0 - bb0), tf32f(w1 - bb1));
            *(float2*)&oS[r1 * DD + col] = make_float2(tf32f(w2 - bb2), tf32f(w3 - bb3));
        }
    }
}

// ============================================================================
// FUSED final: add + norm-2 stats + PER-BATCH grid-sync + apply.
// Batch b's 16 blocks sync among themselves only (all 128 co-resident).
// ============================================================================
__global__ void __launch_bounds__(256) add_norm2(
    const float* __restrict__ yp, const float* __restrict__ h,
    const float* __restrict__ gates, const float* __restrict__ b2,
    const float* __restrict__ n2w, const float* __restrict__ n2b,
    float* __restrict__ part, float* __restrict__ out)
{
    const int b = blockIdx.y, chunk = blockIdx.x;
    __shared__ float b2s[NE * DD];
    b2s[threadIdx.x] = b2[threadIdx.x];
    b2s[threadIdx.x + 256] = b2[threadIdx.x + 256];
    __syncthreads();
    const long row0 = (long)b * SS + chunk * 64;
    const int c4 = threadIdx.x & 31, rg = threadIdx.x >> 5;
    const int c0 = c4 << 2;

    float4 vals[8];
    float4 s = make_float4(0.f, 0.f, 0.f, 0.f), q = s;
    #pragma unroll
    for (int i = 0; i < 8; i++) {
        const int r = rg + i * 8;
        const long tok = row0 + r;
        const long idx = tok * DD + c0;
        const float* g = gates + tok * NE;
        const float g0 = g[0], g1 = g[1], g2 = g[2], g3 = g[3];
        float4 v  = *(const float4*)(yp + idx);
        float4 v1 = *(const float4*)(yp + (long)NTOK * DD + idx);
        float4 hv = *(const float4*)(h + idx);
        float4 o;
        o.x = v.x + v1.x + hv.x
            + g0 * b2s[c0 + 0] + g1 * b2s[DD + c0 + 0] + g2 * b2s[2 * DD + c0 + 0] + g3 * b2s[3 * DD + c0 + 0];
        o.y = v.y + v1.y + hv.y
            + g0 * b2s[c0 + 1] + g1 * b2s[DD + c0 + 1] + g2 * b2s[2 * DD + c0 + 1] + g3 * b2s[3 * DD + c0 + 1];
        o.z = v.z + v1.z + hv.z
            + g0 * b2s[c0 + 2] + g1 * b2s[DD + c0 + 2] + g2 * b2s[2 * DD + c0 + 2] + g3 * b2s[3 * DD + c0 + 2];
        o.w = v.w + v1.w + hv.w
            + g0 * b2s[c0 + 3] + g1 * b2s[DD + c0 + 3] + g2 * b2s[2 * DD + c0 + 3] + g3 * b2s[3 * DD + c0 + 3];
        vals[i] = o;
        s.x += o.x; s.y += o.y; s.z += o.z; s.w += o.w;
        q.x += o.x * o.x; q.y += o.y * o.y; q.z += o.z * o.z; q.w += o.w * o.w;
    }
    __shared__ float4 sS[8][32], sQ[8][32];
    sS[rg][c4] = s; sQ[rg][c4] = q;
    __syncthreads();
    if (threadIdx.x < 32) {
        float4 ts = make_float4(0.f, 0.f, 0.f, 0.f), tq = ts;
        #pragma unroll
        for (int i = 0; i < 8; i++) {
            float4 a = sS[i][threadIdx.x], bq = sQ[i][threadIdx.x];
            ts.x += a.x; ts.y += a.y; ts.z += a.z; ts.w += a.w;
            tq.x += bq.x; tq.y += bq.y; tq.z += bq.z; tq.w += bq.w;
        }
        float* p = part + (long)(b * 16 + chunk) * 256;
        *(float4*)(p + (threadIdx.x << 2)) = ts;
        *(float4*)(p + 128 + (threadIdx.x << 2)) = tq;
    }
    __syncthreads();
    __threadfence();

    __shared__ int lastS;
    if (threadIdx.x == 0)
        lastS = (atomicAdd(&g_cntB[b], 1) == 15);
    __syncthreads();

    if (lastS) {
        if (threadIdx.x < DD) {
            const int d = threadIdx.x;
            float ss = 0.f, qq = 0.f;
            for (int c = 0; c < 16; c++) {
                const float* p = part + (long)(b * 16 + c) * 256;
                ss += p[d]; qq += p[128 + d];
            }
            float mean = ss * (1.f / 1024.f);
            float var  = qq * (1.f / 1024.f) - mean * mean;
            float inv  = rsqrtf(var + 1e-5f);
            float sc = n2w[d] * inv;
            g_nrm[b * 256 + d]       = sc;
            g_nrm[b * 256 + 128 + d] = n2b[d] - mean * sc;
        }
        __threadfence();
        __syncthreads();
        if (threadIdx.x == 0)
            atomicExch(&g_flagB[b], 1);
    } else {
        if (threadIdx.x == 0)
            while (atomicAdd(&g_flagB[b], 0) == 0) { }
        __syncthreads();
        __threadfence();
    }

    float sc[4], sf[4];
    #pragma unroll
    for (int jj = 0; jj < 4; jj++) {
        sc[jj] = g_nrm[b * 256 + c0 + jj];
        sf[jj] = g_nrm[b * 256 + 128 + c0 + jj];
    }
    #pragma unroll
    for (int i = 0; i < 8; i++) {
        const int r = rg + i * 8;
        float4 o = vals[i];
        o.x = o.x * sc[0] + sf[0];
        o.y = o.y * sc[1] + sf[1];
        o.z = o.z * sc[2] + sf[2];
        o.w = o.w * sc[3] + sf[3];
        *(float4*)(out + (row0 + r) * DD + c0) = o;
    }

    // reset counters for graph replay
    __threadfence();
    __syncthreads();
    if (threadIdx.x == 0) {
        if (atomicAdd(&g_cnt2, 1) == 127) {
            #pragma unroll
            for (int bb = 0; bb < BB; bb++) { g_cntB[bb] = 0; g_flagB[bb] = 0; }
            g_cnt2 = 0;
        }
    }
}

// ============================================================================
// Launch (5 kernels)
// ============================================================================
extern "C" void kernel_launch(void* const* d_in, const int* in_sizes, int n_in,
                              void* d_out, int out_size)
{
    const float* x     = (const float*)d_in[0];
    const float* Wqkv  = (const float*)d_in[1];
    const float* bqkv  = (const float*)d_in[2];
    const float* Wo    = (const float*)d_in[3];
    const float* bo    = (const float*)d_in[4];
    const float* n1w   = (const float*)d_in[5];
    const float* n1b   = (const float*)d_in[6];
    const float* n2w   = (const float*)d_in[7];
    const float* n2b   = (const float*)d_in[8];
    const float* wg    = (const float*)d_in[9];
    const float* W1    = (const float*)d_in[10];
    const float* b1    = (const float*)d_in[11];
    const float* W2    = (const float*)d_in[12];
    const float* b2    = (const float*)d_in[13];

    float *qkv, *oB, *oS, *pre1, *h, *gates, *ypart;
    float *wqkvB, *woB, *woS, *part;
    __nv_bfloat16 *w1bf, *w2bf;
    cudaGetSymbolAddress((void**)&qkv,   g_qkv);
    cudaGetSymbolAddress((void**)&oB,    g_oB);
    cudaGetSymbolAddress((void**)&oS,    g_oS);
    cudaGetSymbolAddress((void**)&pre1,  g_pre1);
    cudaGetSymbolAddress((void**)&h,     g_h);
    cudaGetSymbolAddress((void**)&gates, g_gates);
    cudaGetSymbolAddress((void**)&ypart, g_ypart);
    cudaGetSymbolAddress((void**)&w1bf,  g_w1bf);
    cudaGetSymbolAddress((void**)&w2bf,  g_w2bf);
    cudaGetSymbolAddress((void**)&wqkvB, g_wqkvB);
    cudaGetSymbolAddress((void**)&woB,   g_woB);
    cudaGetSymbolAddress((void**)&woS,   g_woS);
    cudaGetSymbolAddress((void**)&part,  g_part);

    cudaFuncSetAttribute(attn_mma, cudaFuncAttributeMaxDynamicSharedMemorySize, ATTN_SMEM);
    cudaFuncSetAttribute(qkv_fused, cudaFuncAttributeMaxDynamicSharedMemorySize, 30720);
    cudaFuncSetAttribute(gemm_mma3, cudaFuncAttributeMaxDynamicSharedMemorySize, 61440);
    cudaFuncSetAttribute(moe_fused, cudaFuncAttributeMaxDynamicSharedMemorySize, MOE_SMEM);

    // 0. Wqkv prep (small, feeds kernel 1)
    weight_prep<<<48, 256>>>(Wqkv, wqkvB);

    // 1. FUSED: QKV projection (1xTF32) + Wo/W1/W2 transposes on spare blocks
    qkv_fused<<<912, 256, 30720>>>(x, wqkvB, bqkv, qkv,
                                   Wo, W1, W2, woB, woS, w1bf, w2bf);

    // 2. MMA flash attention
    attn_mma<<<dim3(64, 2), 256, ATTN_SMEM>>>(qkv, oB, oS);

    // 3. O-projection + bo + residual x ⊕ norm-1 stats (3xTF32)
    gemm_mma3<<<dim3(1, 128), 256, 61440>>>(oB, oS, woB, woS, bo, x, pre1,
                                            128, 128, 128, 8, 128, part);

    // 4. FUSED MoE ⊕ norm-1 apply ⊕ gating
    moe_fused<<<dim3(128, 2), 256, MOE_SMEM>>>(pre1, part, n1w, n1b, wg,
                                               w1bf, w2bf, b1, h, gates, ypart);

    // 5. FUSED final: add + norm-2 stats + per-batch grid-sync + apply -> output
    add_norm2<<<dim3(16, 8), 256>>>(ypart, h, gates, b2, n2w, n2b,
                                    part, (float*)d_out);
}